// round 4
// baseline (speedup 1.0000x reference)
#include <cuda_runtime.h>
#include <math.h>

#define B_ 2
#define T_ 2048
#define C_ 1024
#define H_ 16
#define D_ 64
#define BT_ (B_*T_)
#define RW_ 64
#define RA_ 64
#define RG_ 160
#define EPS_ 6.4e-4f   // D * 1e-5

// ---------------- scratch (device globals: allocation-free) ----------------
__device__ float g_xr[BT_*C_];
__device__ float g_xw[BT_*C_];
__device__ float g_xk[BT_*C_];
__device__ float g_xv[BT_*C_];
__device__ float g_xa[BT_*C_];
__device__ float g_xg[BT_*C_];
__device__ float g_r [BT_*C_];
__device__ float g_k [BT_*C_];
__device__ float g_v [BT_*C_];
__device__ float g_w1[BT_*RW_];
__device__ float g_a1[BT_*RA_];
__device__ float g_g1[BT_*RG_];
__device__ float g_decay[BT_*C_];
__device__ float g_a [BT_*C_];
__device__ float g_g [BT_*C_];
__device__ float g_ain[BT_*C_];
__device__ float g_bin[BT_*C_];
__device__ float g_o [BT_*C_];
__device__ float g_pre[BT_*C_];
__device__ float g_w0[C_];

// ---------------- token-shift mixing: 6 mixed tensors ----------------
__global__ void mix_kernel(const float* __restrict__ x,
    const float* __restrict__ cr, const float* __restrict__ cw,
    const float* __restrict__ ck, const float* __restrict__ cv,
    const float* __restrict__ ca, const float* __restrict__ cg)
{
    int i = blockIdx.x * blockDim.x + threadIdx.x;
    if (i >= BT_*C_/4) return;
    int idx = i * 4;
    int c  = idx & (C_-1);
    int bt = idx >> 10;           // /C_
    int t  = bt & (T_-1);
    float4 xv = *(const float4*)(x + idx);
    float4 xs = make_float4(0.f,0.f,0.f,0.f);
    if (t) xs = *(const float4*)(x + idx - C_);
    float4 d = make_float4(xs.x-xv.x, xs.y-xv.y, xs.z-xv.z, xs.w-xv.w);
#define MIXOUT(arr, cf) { float4 cc = *(const float4*)((cf)+c); \
    float4 o = make_float4(xv.x + d.x*cc.x, xv.y + d.y*cc.y, \
                           xv.z + d.z*cc.z, xv.w + d.w*cc.w); \
    *(float4*)((arr)+idx) = o; }
    MIXOUT(g_xr, cr)
    MIXOUT(g_xw, cw)
    MIXOUT(g_xk, ck)
    MIXOUT(g_xv, cv)
    MIXOUT(g_xa, ca)
    MIXOUT(g_xg, cg)
#undef MIXOUT
}

// ---------------- w0 = base + cumsum(softplus(delta)) (inclusive scan) -----
__global__ void w0_kernel(const float* __restrict__ base,
                          const float* __restrict__ delta)
{
    __shared__ float s[C_];
    int tid = threadIdx.x;
    float v = 0.f;
    if (tid > 0) {
        float d = delta[tid-1];
        v = (d > 20.f) ? d : log1pf(expf(d));
    }
    s[tid] = v;
    __syncthreads();
    for (int off = 1; off < C_; off <<= 1) {
        float t = (tid >= off) ? s[tid-off] : 0.f;
        __syncthreads();
        s[tid] += t;
        __syncthreads();
    }
    g_w0[tid] = base[0] + s[tid];
}

// ---------------- SGEMM: C[M,N] = act(A[M,K] * B[N,K]^T + bias) ------------
// act: 0 = none, 1 = tanh, 2 = sigmoid(y + bias?), 3 = PoST decay transform
__global__ void __launch_bounds__(256)
sgemm_kernel(const float* __restrict__ A, const float* __restrict__ Bm,
             float* __restrict__ Cm, int M, int N, int K,
             const float* __restrict__ bias, const float* __restrict__ w0v,
             int act)
{
    __shared__ float As[8][132];
    __shared__ float Bs[8][132];
    int tid = threadIdx.x;
    int m0 = blockIdx.y * 128;
    int n0 = blockIdx.x * 128;

    int lr = tid >> 1;            // 0..127 : row within tile (A and B)
    int lq = (tid & 1) * 4;       // 0 or 4 : k offset

    int tx = tid & 15;            // 0..15  -> 8 cols
    int ty = tid >> 4;            // 0..15  -> 8 rows

    float acc[8][8];
#pragma unroll
    for (int i = 0; i < 8; i++)
#pragma unroll
        for (int j = 0; j < 8; j++) acc[i][j] = 0.f;

    for (int k0 = 0; k0 < K; k0 += 8) {
        float4 av = *(const float4*)(A + (size_t)(m0+lr)*K + k0 + lq);
        float4 bv = make_float4(0.f,0.f,0.f,0.f);
        if (n0 + lr < N)
            bv = *(const float4*)(Bm + (size_t)(n0+lr)*K + k0 + lq);
        __syncthreads();   // previous tile fully consumed
        As[lq+0][lr] = av.x; As[lq+1][lr] = av.y;
        As[lq+2][lr] = av.z; As[lq+3][lr] = av.w;
        Bs[lq+0][lr] = bv.x; Bs[lq+1][lr] = bv.y;
        Bs[lq+2][lr] = bv.z; Bs[lq+3][lr] = bv.w;
        __syncthreads();
#pragma unroll
        for (int kk = 0; kk < 8; kk++) {
            float a[8], b[8];
            *(float4*)&a[0] = *(const float4*)&As[kk][ty*8];
            *(float4*)&a[4] = *(const float4*)&As[kk][ty*8+4];
            *(float4*)&b[0] = *(const float4*)&Bs[kk][tx*8];
            *(float4*)&b[4] = *(const float4*)&Bs[kk][tx*8+4];
#pragma unroll
            for (int i = 0; i < 8; i++)
#pragma unroll
                for (int j = 0; j < 8; j++)
                    acc[i][j] = fmaf(a[i], b[j], acc[i][j]);
        }
    }

#pragma unroll
    for (int i = 0; i < 8; i++) {
        int m = m0 + ty*8 + i;
#pragma unroll
        for (int j = 0; j < 8; j++) {
            int n = n0 + tx*8 + j;
            if (n < N) {
                float y = acc[i][j];
                if (act == 1) {
                    y = tanhf(y);
                } else if (act == 2) {
                    float bb = bias ? bias[n] : 0.f;
                    y = 1.f / (1.f + expf(-(y + bb)));
                } else if (act == 3) {
                    float tt = w0v[n] + y + bias[n];
                    float nt = -tt;
                    float sp = (nt > 20.f) ? nt : log1pf(expf(nt));
                    float w  = -sp - 0.5f;
                    y = expf(-expf(w));
                }
                Cm[(size_t)m * N + n] = y;
            }
        }
    }
}

// ---------------- kk normalize / a_in / b_in / k update --------------------
__global__ void kk_kernel(const float* __restrict__ kkc,
                          const float* __restrict__ kac)
{
    int gid  = blockIdx.x * blockDim.x + threadIdx.x;
    int lane = gid & 31;
    int grp  = gid >> 5;                 // over BT_*H_
    if (grp >= BT_*H_) return;
    int bt = grp / H_, h = grp % H_;
    int base = bt * C_ + h * D_;
    int c0   = h * D_;

    float k0v = g_k[base + lane],      k1v = g_k[base + 32 + lane];
    float a0  = g_a[base + lane],      a1  = g_a[base + 32 + lane];
    float kk0 = k0v * kkc[c0 + lane],  kk1 = k1v * kkc[c0 + 32 + lane];

    float ss = kk0*kk0 + kk1*kk1;
#pragma unroll
    for (int o = 16; o; o >>= 1) ss += __shfl_xor_sync(0xffffffffu, ss, o);
    float inv = 1.f / fmaxf(sqrtf(ss), 1e-12f);
    kk0 *= inv; kk1 *= inv;

    g_ain[base + lane]      = -kk0;
    g_ain[base + 32 + lane] = -kk1;
    g_bin[base + lane]      = kk0 * a0;
    g_bin[base + 32 + lane] = kk1 * a1;
    g_k[base + lane]        = k0v * (1.f + (a0 - 1.f) * kac[c0 + lane]);
    g_k[base + 32 + lane]   = k1v * (1.f + (a1 - 1.f) * kac[c0 + 32 + lane]);
}

// ---------------- sequential RWKV-7 recurrence -----------------------------
// One block per (b,h). 256 threads: thread owns S[row, part*16 .. part*16+15].
__global__ void __launch_bounds__(256, 1) rec_kernel()
{
    int bh = blockIdx.x;
    int b = bh / H_, h = bh % H_;
    size_t base = (size_t)b * T_ * C_ + h * D_;

    __shared__ float sh[2][6][64];   // 0:r 1:w 2:k 3:v 4:a 5:b

    int tid  = threadIdx.x;
    int row  = tid >> 2;
    int part = tid & 3;
    int c0   = part * 16;

    const float* srcs[6] = { g_r, g_decay, g_k, g_v, g_ain, g_bin };
    int  vec = tid / 16, q = tid % 16;
    bool loader = tid < 96;

    float S[16];
#pragma unroll
    for (int i = 0; i < 16; i++) S[i] = 0.f;

    float4 ld = make_float4(0.f,0.f,0.f,0.f);
    if (loader) {
        ld = *(const float4*)(srcs[vec] + base + q*4);
        *(float4*)&sh[0][vec][q*4] = ld;
    }

    for (int t = 0; t < T_; t++) {
        int cur = t & 1, nxt = cur ^ 1;
        __syncthreads();   // sh[cur] ready

        if (loader && t + 1 < T_)
            ld = *(const float4*)(srcs[vec] + base + (size_t)(t+1)*C_ + q*4);

        // sa = sum_k S[row][k] * a[k]
        float sa = 0.f;
#pragma unroll
        for (int qq = 0; qq < 4; qq++) {
            float4 av = *(const float4*)&sh[cur][4][c0 + qq*4];
            sa += S[qq*4+0]*av.x + S[qq*4+1]*av.y
                + S[qq*4+2]*av.z + S[qq*4+3]*av.w;
        }
        sa += __shfl_xor_sync(0xffffffffu, sa, 1);
        sa += __shfl_xor_sync(0xffffffffu, sa, 2);

        float vj = sh[cur][3][row];
        float o = 0.f;
#pragma unroll
        for (int qq = 0; qq < 4; qq++) {
            float4 wv = *(const float4*)&sh[cur][1][c0 + qq*4];
            float4 bv = *(const float4*)&sh[cur][5][c0 + qq*4];
            float4 kv = *(const float4*)&sh[cur][2][c0 + qq*4];
            float4 rv = *(const float4*)&sh[cur][0][c0 + qq*4];
            S[qq*4+0] = S[qq*4+0]*wv.x + sa*bv.x + vj*kv.x;  o += S[qq*4+0]*rv.x;
            S[qq*4+1] = S[qq*4+1]*wv.y + sa*bv.y + vj*kv.y;  o += S[qq*4+1]*rv.y;
            S[qq*4+2] = S[qq*4+2]*wv.z + sa*bv.z + vj*kv.z;  o += S[qq*4+2]*rv.z;
            S[qq*4+3] = S[qq*4+3]*wv.w + sa*bv.w + vj*kv.w;  o += S[qq*4+3]*rv.w;
        }
        o += __shfl_xor_sync(0xffffffffu, o, 1);
        o += __shfl_xor_sync(0xffffffffu, o, 2);
        if (part == 0) g_o[base + (size_t)t*C_ + row] = o;

        if (loader && t + 1 < T_)
            *(float4*)&sh[nxt][vec][q*4] = ld;
    }
}

// ---------------- GroupNorm + bonus + gate ---------------------------------
__global__ void post_kernel(const float* __restrict__ rk,
                            const float* __restrict__ gnw,
                            const float* __restrict__ gnb)
{
    int gid  = blockIdx.x * blockDim.x + threadIdx.x;
    int lane = gid & 31;
    int grp  = gid >> 5;
    if (grp >= BT_*H_) return;
    int bt = grp / H_, h = grp % H_;
    int base = bt * C_ + h * D_;
    int c0   = h * D_;

    float o0 = g_o[base + lane], o1 = g_o[base + 32 + lane];
    float su = o0 + o1;
    float sq = o0*o0 + o1*o1;
    float r0 = g_r[base + lane], r1 = g_r[base + 32 + lane];
    float k0 = g_k[base + lane], k1 = g_k[base + 32 + lane];
    float bsum = r0*k0*rk[c0 + lane] + r1*k1*rk[c0 + 32 + lane];
#pragma unroll
    for (int o = 16; o; o >>= 1) {
        su   += __shfl_xor_sync(0xffffffffu, su,   o);
        sq   += __shfl_xor_sync(0xffffffffu, sq,   o);
        bsum += __shfl_xor_sync(0xffffffffu, bsum, o);
    }
    float mu  = su / 64.f;
    float var = sq / 64.f - mu * mu;
    float inv = rsqrtf(var + EPS_);

    float v0 = g_v[base + lane], v1 = g_v[base + 32 + lane];
    float on0 = (o0 - mu) * inv * gnw[c0 + lane]      + gnb[c0 + lane];
    float on1 = (o1 - mu) * inv * gnw[c0 + 32 + lane] + gnb[c0 + 32 + lane];
    g_pre[base + lane]      = (on0 + bsum * v0) * g_g[base + lane];
    g_pre[base + 32 + lane] = (on1 + bsum * v1) * g_g[base + 32 + lane];
}

// ---------------- host launcher ---------------------------------------------
extern "C" void kernel_launch(void* const* d_in, const int* in_sizes, int n_in,
                              void* d_out, int out_size)
{
    const float* x        = (const float*)d_in[0];
    const float* x_r      = (const float*)d_in[1];
    const float* x_w      = (const float*)d_in[2];
    const float* x_k      = (const float*)d_in[3];
    const float* x_v      = (const float*)d_in[4];
    const float* x_a      = (const float*)d_in[5];
    const float* x_g      = (const float*)d_in[6];
    const float* k_k      = (const float*)d_in[7];
    const float* k_a      = (const float*)d_in[8];
    const float* r_k      = (const float*)d_in[9];
    const float* Wr       = (const float*)d_in[10];
    const float* Wk       = (const float*)d_in[11];
    const float* Wv       = (const float*)d_in[12];
    const float* Wo       = (const float*)d_in[13];
    const float* wA       = (const float*)d_in[14];
    const float* wB       = (const float*)d_in[15];
    const float* wBias    = (const float*)d_in[16];
    const float* aA       = (const float*)d_in[17];
    const float* aB       = (const float*)d_in[18];
    const float* aBias    = (const float*)d_in[19];
    const float* gA       = (const float*)d_in[20];
    const float* gB       = (const float*)d_in[21];
    const float* gnw      = (const float*)d_in[22];
    const float* gnb      = (const float*)d_in[23];
    const float* w0_base  = (const float*)d_in[24];
    const float* w0_delta = (const float*)d_in[25];
    float* out = (float*)d_out;

    float *p_xr,*p_xw,*p_xk,*p_xv,*p_xa,*p_xg;
    float *p_r,*p_k,*p_v,*p_w1,*p_a1,*p_g1;
    float *p_dec,*p_a,*p_g,*p_pre,*p_w0;
    cudaGetSymbolAddress((void**)&p_xr, g_xr);
    cudaGetSymbolAddress((void**)&p_xw, g_xw);
    cudaGetSymbolAddress((void**)&p_xk, g_xk);
    cudaGetSymbolAddress((void**)&p_xv, g_xv);
    cudaGetSymbolAddress((void**)&p_xa, g_xa);
    cudaGetSymbolAddress((void**)&p_xg, g_xg);
    cudaGetSymbolAddress((void**)&p_r,  g_r);
    cudaGetSymbolAddress((void**)&p_k,  g_k);
    cudaGetSymbolAddress((void**)&p_v,  g_v);
    cudaGetSymbolAddress((void**)&p_w1, g_w1);
    cudaGetSymbolAddress((void**)&p_a1, g_a1);
    cudaGetSymbolAddress((void**)&p_g1, g_g1);
    cudaGetSymbolAddress((void**)&p_dec,g_decay);
    cudaGetSymbolAddress((void**)&p_a,  g_a);
    cudaGetSymbolAddress((void**)&p_g,  g_g);
    cudaGetSymbolAddress((void**)&p_pre,g_pre);
    cudaGetSymbolAddress((void**)&p_w0, g_w0);

    // 1) token-shift mixes
    mix_kernel<<<(BT_*C_/4 + 255)/256, 256>>>(x, x_r, x_w, x_k, x_v, x_a, x_g);

    // 2) w0 scan
    w0_kernel<<<1, C_>>>(w0_base, w0_delta);

    auto gemm = [&](const float* A, const float* Bm, float* Cm,
                    int M, int N, int K,
                    const float* bias, const float* w0v, int act) {
        dim3 grid((N + 127) / 128, M / 128);
        sgemm_kernel<<<grid, 256>>>(A, Bm, Cm, M, N, K, bias, w0v, act);
    };

    // 3) big projections
    gemm(p_xr, Wr, p_r, BT_, C_, C_, nullptr, nullptr, 0);
    gemm(p_xk, Wk, p_k, BT_, C_, C_, nullptr, nullptr, 0);
    gemm(p_xv, Wv, p_v, BT_, C_, C_, nullptr, nullptr, 0);

    // 4) LoRA stage 1
    gemm(p_xw, wA, p_w1, BT_, RW_, C_, nullptr, nullptr, 1);   // tanh
    gemm(p_xa, aA, p_a1, BT_, RA_, C_, nullptr, nullptr, 0);
    gemm(p_xg, gA, p_g1, BT_, RG_, C_, nullptr, nullptr, 2);   // sigmoid, no bias

    // 5) LoRA stage 2 (+ fused epilogues)
    gemm(p_w1, wB, p_dec, BT_, C_, RW_, wBias, p_w0, 3);       // decay transform
    gemm(p_a1, aB, p_a,   BT_, C_, RA_, aBias, nullptr, 2);    // sigmoid(+bias)
    gemm(p_g1, gB, p_g,   BT_, C_, RG_, nullptr, nullptr, 0);

    // 6) kk normalize / a_in / b_in / k update
    kk_kernel<<<(BT_*H_*32 + 255)/256, 256>>>(k_k, k_a);

    // 7) sequential recurrence
    rec_kernel<<<B_*H_, 256>>>();

    // 8) GroupNorm + bonus + gate
    post_kernel<<<(BT_*H_*32 + 255)/256, 256>>>(r_k, gnw, gnb);

    // 9) output projection
    gemm(p_pre, Wo, out, BT_, C_, C_, nullptr, nullptr, 0);
}

// round 5
// speedup vs baseline: 1.2138x; 1.2138x over previous
#include <cuda_runtime.h>
#include <math.h>

#define B_ 2
#define T_ 2048
#define C_ 1024
#define H_ 16
#define D_ 64
#define BT_ (B_*T_)
#define RW_ 64
#define RA_ 64
#define RG_ 160
#define EPS_ 6.4e-4f   // D * 1e-5

// ---------------- packed f32x2 helpers (Blackwell FFMA2) -------------------
__device__ __forceinline__ unsigned long long f32x2_fma(
    unsigned long long a, unsigned long long b, unsigned long long c) {
    unsigned long long d;
    asm("fma.rn.f32x2 %0, %1, %2, %3;" : "=l"(d) : "l"(a), "l"(b), "l"(c));
    return d;
}
__device__ __forceinline__ unsigned long long f32x2_mul(
    unsigned long long a, unsigned long long b) {
    unsigned long long d;
    asm("mul.rn.f32x2 %0, %1, %2;" : "=l"(d) : "l"(a), "l"(b));
    return d;
}
__device__ __forceinline__ unsigned long long f32x2_pack(float lo, float hi) {
    unsigned long long d;
    asm("mov.b64 %0, {%1, %2};" : "=l"(d) : "f"(lo), "f"(hi));
    return d;
}
__device__ __forceinline__ float2 f32x2_unpack(unsigned long long v) {
    float lo, hi;
    asm("mov.b64 {%0, %1}, %2;" : "=f"(lo), "=f"(hi) : "l"(v));
    return make_float2(lo, hi);
}

// ---------------- scratch (device globals: allocation-free) ----------------
__device__ float g_xr[BT_*C_];
__device__ float g_xw[BT_*C_];
__device__ float g_xk[BT_*C_];
__device__ float g_xv[BT_*C_];
__device__ float g_xa[BT_*C_];
__device__ float g_xg[BT_*C_];
__device__ float g_r [BT_*C_];
__device__ float g_k [BT_*C_];
__device__ float g_v [BT_*C_];
__device__ float g_w1[BT_*RW_];
__device__ float g_a1[BT_*RA_];
__device__ float g_g1[BT_*RG_];
__device__ float g_decay[BT_*C_];
__device__ float g_a [BT_*C_];
__device__ float g_g [BT_*C_];
__device__ float g_ain[BT_*C_];
__device__ float g_bin[BT_*C_];
__device__ float g_o [BT_*C_];
__device__ float g_pre[BT_*C_];
__device__ float g_w0[C_];

// ---------------- token-shift mixing: 6 mixed tensors ----------------------
__global__ void mix_kernel(const float* __restrict__ x,
    const float* __restrict__ cr, const float* __restrict__ cw,
    const float* __restrict__ ck, const float* __restrict__ cv,
    const float* __restrict__ ca, const float* __restrict__ cg)
{
    int i = blockIdx.x * blockDim.x + threadIdx.x;
    if (i >= BT_*C_/4) return;
    int idx = i * 4;
    int c  = idx & (C_-1);
    int bt = idx >> 10;           // /C_
    int t  = bt & (T_-1);
    float4 xv = *(const float4*)(x + idx);
    float4 xs = make_float4(0.f,0.f,0.f,0.f);
    if (t) xs = *(const float4*)(x + idx - C_);
    float4 d = make_float4(xs.x-xv.x, xs.y-xv.y, xs.z-xv.z, xs.w-xv.w);
#define MIXOUT(arr, cf) { float4 cc = *(const float4*)((cf)+c); \
    float4 o = make_float4(xv.x + d.x*cc.x, xv.y + d.y*cc.y, \
                           xv.z + d.z*cc.z, xv.w + d.w*cc.w); \
    *(float4*)((arr)+idx) = o; }
    MIXOUT(g_xr, cr)
    MIXOUT(g_xw, cw)
    MIXOUT(g_xk, ck)
    MIXOUT(g_xv, cv)
    MIXOUT(g_xa, ca)
    MIXOUT(g_xg, cg)
#undef MIXOUT
}

// ---------------- w0 = base + cumsum(softplus(delta)) ----------------------
__global__ void w0_kernel(const float* __restrict__ base,
                          const float* __restrict__ delta)
{
    __shared__ float s[C_];
    int tid = threadIdx.x;
    float v = 0.f;
    if (tid > 0) {
        float d = delta[tid-1];
        v = (d > 20.f) ? d : log1pf(expf(d));
    }
    s[tid] = v;
    __syncthreads();
    for (int off = 1; off < C_; off <<= 1) {
        float t = (tid >= off) ? s[tid-off] : 0.f;
        __syncthreads();
        s[tid] += t;
        __syncthreads();
    }
    g_w0[tid] = base[0] + s[tid];
}

// ---------------- fused f32x2 SGEMM: up to 3 jobs via blockIdx.z ------------
// C[M,N] = act(A[M,K] * B[N,K]^T [+bias]); act: 0 none, 1 tanh,
// 2 sigmoid(y+bias?), 3 PoST decay transform (uses g_w0 + bias)
struct GemmJob { const float* A; const float* Bm; float* C;
                 const float* bias; int N; int K; int act; };
struct Jobs3 { GemmJob j[3]; };

__global__ void __launch_bounds__(256)
fgemm_kernel(Jobs3 jobs)
{
    GemmJob jb = jobs.j[blockIdx.z];
    const int N = jb.N, K = jb.K;
    const int m0 = blockIdx.y * 128;
    const int n0 = blockIdx.x * 128;
    if (n0 >= N) return;

    __shared__ alignas(16) float As[8][132];
    __shared__ alignas(16) float Bs[8][132];

    int tid = threadIdx.x;
    int lr = tid >> 1;            // 0..127 row within tile
    int lq = (tid & 1) * 4;       // 0 or 4 k offset
    int tx = tid & 15;
    int ty = tid >> 4;

    const float* Ap = jb.A  + (size_t)(m0 + lr) * K + lq;
    const float* Bp = jb.Bm + (size_t)(n0 + lr) * K + lq;
    bool bok = (n0 + lr) < N;

    unsigned long long acc[8][4];
#pragma unroll
    for (int i = 0; i < 8; i++)
#pragma unroll
        for (int j = 0; j < 4; j++) acc[i][j] = 0ull;

    float4 av = *(const float4*)Ap;
    float4 bv = make_float4(0.f,0.f,0.f,0.f);
    if (bok) bv = *(const float4*)Bp;

    for (int k0 = 0; k0 < K; k0 += 8) {
        __syncthreads();   // previous tile fully consumed
        As[lq+0][lr] = av.x; As[lq+1][lr] = av.y;
        As[lq+2][lr] = av.z; As[lq+3][lr] = av.w;
        Bs[lq+0][lr] = bv.x; Bs[lq+1][lr] = bv.y;
        Bs[lq+2][lr] = bv.z; Bs[lq+3][lr] = bv.w;
        __syncthreads();
        if (k0 + 8 < K) {      // prefetch next tile (latency hidden by compute)
            av = *(const float4*)(Ap + k0 + 8);
            if (bok) bv = *(const float4*)(Bp + k0 + 8);
        }
#pragma unroll
        for (int kk = 0; kk < 8; kk++) {
            float a_[8];
            *(float4*)&a_[0] = *(const float4*)&As[kk][ty*8];
            *(float4*)&a_[4] = *(const float4*)&As[kk][ty*8+4];
            ulonglong2 b0 = *(const ulonglong2*)&Bs[kk][tx*8];
            ulonglong2 b1 = *(const ulonglong2*)&Bs[kk][tx*8+4];
#pragma unroll
            for (int i = 0; i < 8; i++) {
                unsigned long long a2 = f32x2_pack(a_[i], a_[i]);
                acc[i][0] = f32x2_fma(a2, b0.x, acc[i][0]);
                acc[i][1] = f32x2_fma(a2, b0.y, acc[i][1]);
                acc[i][2] = f32x2_fma(a2, b1.x, acc[i][2]);
                acc[i][3] = f32x2_fma(a2, b1.y, acc[i][3]);
            }
        }
    }

    const int act = jb.act;
#pragma unroll
    for (int i = 0; i < 8; i++) {
        int m = m0 + ty*8 + i;
#pragma unroll
        for (int jq = 0; jq < 4; jq++) {
            float2 y = f32x2_unpack(acc[i][jq]);
            float ys[2] = { y.x, y.y };
            int nb = n0 + tx*8 + jq*2;
#pragma unroll
            for (int s = 0; s < 2; s++) {
                int nn = nb + s;
                if (nn < N) {
                    float yy = ys[s];
                    if (act == 1) {
                        yy = tanhf(yy);
                    } else if (act == 2) {
                        float bb = jb.bias ? jb.bias[nn] : 0.f;
                        yy = 1.f / (1.f + expf(-(yy + bb)));
                    } else if (act == 3) {
                        float tt = g_w0[nn] + yy + jb.bias[nn];
                        float nt = -tt;
                        float sp = (nt > 20.f) ? nt : log1pf(expf(nt));
                        yy = expf(-expf(-sp - 0.5f));
                    }
                    jb.C[(size_t)m * N + nn] = yy;
                }
            }
        }
    }
}

// ---------------- kk normalize / a_in / b_in / k update --------------------
__global__ void kk_kernel(const float* __restrict__ kkc,
                          const float* __restrict__ kac)
{
    int gid  = blockIdx.x * blockDim.x + threadIdx.x;
    int lane = gid & 31;
    int grp  = gid >> 5;                 // over BT_*H_
    if (grp >= BT_*H_) return;
    int bt = grp / H_, h = grp % H_;
    int base = bt * C_ + h * D_;
    int c0   = h * D_;

    float k0v = g_k[base + lane],      k1v = g_k[base + 32 + lane];
    float a0  = g_a[base + lane],      a1  = g_a[base + 32 + lane];
    float kk0 = k0v * kkc[c0 + lane],  kk1 = k1v * kkc[c0 + 32 + lane];

    float ss = kk0*kk0 + kk1*kk1;
#pragma unroll
    for (int o = 16; o; o >>= 1) ss += __shfl_xor_sync(0xffffffffu, ss, o);
    float inv = 1.f / fmaxf(sqrtf(ss), 1e-12f);
    kk0 *= inv; kk1 *= inv;

    g_ain[base + lane]      = -kk0;
    g_ain[base + 32 + lane] = -kk1;
    g_bin[base + lane]      = kk0 * a0;
    g_bin[base + 32 + lane] = kk1 * a1;
    g_k[base + lane]        = k0v * (1.f + (a0 - 1.f) * kac[c0 + lane]);
    g_k[base + 32 + lane]   = k1v * (1.f + (a1 - 1.f) * kac[c0 + 32 + lane]);
}

// ---------------- sequential RWKV-7 recurrence (v2: 512 thr, f32x2) --------
// One block per (b,h). Thread owns S[row, cp*8 .. cp*8+7] as 4 f32x2 pairs.
__global__ void __launch_bounds__(512, 1) rec_kernel()
{
    int bh = blockIdx.x;
    int b = bh >> 4, h = bh & 15;
    size_t base = (size_t)b * T_ * C_ + h * D_;

    __shared__ alignas(16) float sh[2][6][64];   // 0:r 1:w 2:k 3:v 4:a 5:b

    int tid = threadIdx.x;
    int row = tid >> 3;          // 0..63
    int cp  = tid & 7;           // 0..7
    int c0  = cp * 8;

    // loader threads: 6 vectors x 16 float4 = 96 slots
    int  vec = tid >> 4, q = tid & 15;
    bool loader = tid < 96;
    const float* srcp = nullptr;
    if (loader) {
        const float* srcs[6] = { g_r, g_decay, g_k, g_v, g_ain, g_bin };
        srcp = srcs[vec] + base + q*4;
    }

    unsigned long long S[4] = {0ull, 0ull, 0ull, 0ull};

    float4 ld = make_float4(0.f,0.f,0.f,0.f);
    if (loader) {
        ld = *(const float4*)srcp;
        *(float4*)&sh[0][vec][q*4] = ld;
    }

    for (int t = 0; t < T_; t++) {
        int cur = t & 1, nxt = cur ^ 1;
        __syncthreads();   // sh[cur] ready, prior buffer reads done

        if (loader && t + 1 < T_)
            ld = *(const float4*)(srcp + (size_t)(t+1)*C_);

        // sa = sum_c S[row][c] * a[c]
        ulonglong2 aA = *(const ulonglong2*)&sh[cur][4][c0];
        ulonglong2 aB = *(const ulonglong2*)&sh[cur][4][c0+4];
        unsigned long long sacc = f32x2_mul(S[0], aA.x);
        sacc = f32x2_fma(S[1], aA.y, sacc);
        sacc = f32x2_fma(S[2], aB.x, sacc);
        sacc = f32x2_fma(S[3], aB.y, sacc);
        float2 sp = f32x2_unpack(sacc);
        float sa = sp.x + sp.y;
        sa += __shfl_xor_sync(0xffffffffu, sa, 1);
        sa += __shfl_xor_sync(0xffffffffu, sa, 2);
        sa += __shfl_xor_sync(0xffffffffu, sa, 4);

        float vj = sh[cur][3][row];
        ulonglong2 wA = *(const ulonglong2*)&sh[cur][1][c0];
        ulonglong2 wB = *(const ulonglong2*)&sh[cur][1][c0+4];
        ulonglong2 bA = *(const ulonglong2*)&sh[cur][5][c0];
        ulonglong2 bB = *(const ulonglong2*)&sh[cur][5][c0+4];
        ulonglong2 kA = *(const ulonglong2*)&sh[cur][2][c0];
        ulonglong2 kB = *(const ulonglong2*)&sh[cur][2][c0+4];
        ulonglong2 rA = *(const ulonglong2*)&sh[cur][0][c0];
        ulonglong2 rB = *(const ulonglong2*)&sh[cur][0][c0+4];

        unsigned long long sa2 = f32x2_pack(sa, sa);
        unsigned long long v2  = f32x2_pack(vj, vj);

        // S = S*w + sa*b + v*k ; o += S*r
        S[0] = f32x2_fma(v2, kA.x, f32x2_fma(sa2, bA.x, f32x2_mul(S[0], wA.x)));
        S[1] = f32x2_fma(v2, kA.y, f32x2_fma(sa2, bA.y, f32x2_mul(S[1], wA.y)));
        S[2] = f32x2_fma(v2, kB.x, f32x2_fma(sa2, bB.x, f32x2_mul(S[2], wB.x)));
        S[3] = f32x2_fma(v2, kB.y, f32x2_fma(sa2, bB.y, f32x2_mul(S[3], wB.y)));

        unsigned long long oacc = f32x2_mul(S[0], rA.x);
        oacc = f32x2_fma(S[1], rA.y, oacc);
        oacc = f32x2_fma(S[2], rB.x, oacc);
        oacc = f32x2_fma(S[3], rB.y, oacc);
        float2 op = f32x2_unpack(oacc);
        float o = op.x + op.y;
        o += __shfl_xor_sync(0xffffffffu, o, 1);
        o += __shfl_xor_sync(0xffffffffu, o, 2);
        o += __shfl_xor_sync(0xffffffffu, o, 4);
        if (cp == 0) g_o[base + (size_t)t*C_ + row] = o;

        if (loader && t + 1 < T_)
            *(float4*)&sh[nxt][vec][q*4] = ld;
    }
}

// ---------------- GroupNorm + bonus + gate ---------------------------------
__global__ void post_kernel(const float* __restrict__ rk,
                            const float* __restrict__ gnw,
                            const float* __restrict__ gnb)
{
    int gid  = blockIdx.x * blockDim.x + threadIdx.x;
    int lane = gid & 31;
    int grp  = gid >> 5;
    if (grp >= BT_*H_) return;
    int bt = grp / H_, h = grp % H_;
    int base = bt * C_ + h * D_;
    int c0   = h * D_;

    float o0 = g_o[base + lane], o1 = g_o[base + 32 + lane];
    float su = o0 + o1;
    float sq = o0*o0 + o1*o1;
    float r0 = g_r[base + lane], r1 = g_r[base + 32 + lane];
    float k0 = g_k[base + lane], k1 = g_k[base + 32 + lane];
    float bsum = r0*k0*rk[c0 + lane] + r1*k1*rk[c0 + 32 + lane];
#pragma unroll
    for (int o = 16; o; o >>= 1) {
        su   += __shfl_xor_sync(0xffffffffu, su,   o);
        sq   += __shfl_xor_sync(0xffffffffu, sq,   o);
        bsum += __shfl_xor_sync(0xffffffffu, bsum, o);
    }
    float mu  = su / 64.f;
    float var = sq / 64.f - mu * mu;
    float inv = rsqrtf(var + EPS_);

    float v0 = g_v[base + lane], v1 = g_v[base + 32 + lane];
    float on0 = (o0 - mu) * inv * gnw[c0 + lane]      + gnb[c0 + lane];
    float on1 = (o1 - mu) * inv * gnw[c0 + 32 + lane] + gnb[c0 + 32 + lane];
    g_pre[base + lane]      = (on0 + bsum * v0) * g_g[base + lane];
    g_pre[base + 32 + lane] = (on1 + bsum * v1) * g_g[base + 32 + lane];
}

// ---------------- host launcher ---------------------------------------------
extern "C" void kernel_launch(void* const* d_in, const int* in_sizes, int n_in,
                              void* d_out, int out_size)
{
    const float* x        = (const float*)d_in[0];
    const float* x_r      = (const float*)d_in[1];
    const float* x_w      = (const float*)d_in[2];
    const float* x_k      = (const float*)d_in[3];
    const float* x_v      = (const float*)d_in[4];
    const float* x_a      = (const float*)d_in[5];
    const float* x_g      = (const float*)d_in[6];
    const float* k_k      = (const float*)d_in[7];
    const float* k_a      = (const float*)d_in[8];
    const float* r_k      = (const float*)d_in[9];
    const float* Wr       = (const float*)d_in[10];
    const float* Wk       = (const float*)d_in[11];
    const float* Wv       = (const float*)d_in[12];
    const float* Wo       = (const float*)d_in[13];
    const float* wA       = (const float*)d_in[14];
    const float* wB       = (const float*)d_in[15];
    const float* wBias    = (const float*)d_in[16];
    const float* aA       = (const float*)d_in[17];
    const float* aB       = (const float*)d_in[18];
    const float* aBias    = (const float*)d_in[19];
    const float* gA       = (const float*)d_in[20];
    const float* gB       = (const float*)d_in[21];
    const float* gnw      = (const float*)d_in[22];
    const float* gnb      = (const float*)d_in[23];
    const float* w0_base  = (const float*)d_in[24];
    const float* w0_delta = (const float*)d_in[25];
    float* out = (float*)d_out;

    float *p_xr,*p_xw,*p_xk,*p_xv,*p_xa,*p_xg;
    float *p_r,*p_k,*p_v,*p_w1,*p_a1,*p_g1;
    float *p_dec,*p_a,*p_g,*p_pre;
    cudaGetSymbolAddress((void**)&p_xr, g_xr);
    cudaGetSymbolAddress((void**)&p_xw, g_xw);
    cudaGetSymbolAddress((void**)&p_xk, g_xk);
    cudaGetSymbolAddress((void**)&p_xv, g_xv);
    cudaGetSymbolAddress((void**)&p_xa, g_xa);
    cudaGetSymbolAddress((void**)&p_xg, g_xg);
    cudaGetSymbolAddress((void**)&p_r,  g_r);
    cudaGetSymbolAddress((void**)&p_k,  g_k);
    cudaGetSymbolAddress((void**)&p_v,  g_v);
    cudaGetSymbolAddress((void**)&p_w1, g_w1);
    cudaGetSymbolAddress((void**)&p_a1, g_a1);
    cudaGetSymbolAddress((void**)&p_g1, g_g1);
    cudaGetSymbolAddress((void**)&p_dec,g_decay);
    cudaGetSymbolAddress((void**)&p_a,  g_a);
    cudaGetSymbolAddress((void**)&p_g,  g_g);
    cudaGetSymbolAddress((void**)&p_pre,g_pre);

    // 1) token-shift mixes
    mix_kernel<<<(BT_*C_/4 + 255)/256, 256>>>(x, x_r, x_w, x_k, x_v, x_a, x_g);

    // 2) w0 scan
    w0_kernel<<<1, C_>>>(w0_base, w0_delta);

    // 3) big r/k/v projections fused via grid.z (768 blocks)
    {
        Jobs3 jb;
        jb.j[0] = { p_xr, Wr, p_r, nullptr, C_, C_, 0 };
        jb.j[1] = { p_xk, Wk, p_k, nullptr, C_, C_, 0 };
        jb.j[2] = { p_xv, Wv, p_v, nullptr, C_, C_, 0 };
        fgemm_kernel<<<dim3(C_/128, BT_/128, 3), 256>>>(jb);
    }

    // 4) LoRA stage 1 fused (one wave instead of three)
    {
        Jobs3 jb;
        jb.j[0] = { p_xw, wA, p_w1, nullptr, RW_, C_, 1 };   // tanh
        jb.j[1] = { p_xa, aA, p_a1, nullptr, RA_, C_, 0 };
        jb.j[2] = { p_xg, gA, p_g1, nullptr, RG_, C_, 2 };   // sigmoid, no bias
        fgemm_kernel<<<dim3((RG_+127)/128, BT_/128, 3), 256>>>(jb);
    }

    // 5) LoRA stage 2 fused (+ fused epilogues)
    {
        Jobs3 jb;
        jb.j[0] = { p_w1, wB, p_dec, wBias,   C_, RW_, 3 };  // decay transform
        jb.j[1] = { p_a1, aB, p_a,   aBias,   C_, RA_, 2 };  // sigmoid(+bias)
        jb.j[2] = { p_g1, gB, p_g,   nullptr, C_, RG_, 0 };
        fgemm_kernel<<<dim3(C_/128, BT_/128, 3), 256>>>(jb);
    }

    // 6) kk normalize / a_in / b_in / k update
    kk_kernel<<<(BT_*H_*32 + 255)/256, 256>>>(k_k, k_a);

    // 7) sequential recurrence
    rec_kernel<<<B_*H_, 512>>>();

    // 8) GroupNorm + bonus + gate
    post_kernel<<<(BT_*H_*32 + 255)/256, 256>>>(r_k, gnw, gnb);

    // 9) output projection
    {
        Jobs3 jb;
        jb.j[0] = { p_pre, Wo, out, nullptr, C_, C_, 0 };
        jb.j[1] = jb.j[0];
        jb.j[2] = jb.j[0];
        fgemm_kernel<<<dim3(C_/128, BT_/128, 1), 256>>>(jb);
    }
}

// round 7
// speedup vs baseline: 1.4984x; 1.2344x over previous
#include <cuda_runtime.h>
#include <cuda_bf16.h>
#include <math.h>
#include <stdint.h>

#define B_ 2
#define T_ 2048
#define C_ 1024
#define H_ 16
#define D_ 64
#define BT_ (B_*T_)
#define RW_ 64
#define RA_ 64
#define RG_ 160
#define EPS_ 6.4e-4f   // D * 1e-5

// ---------------- packed f32x2 helpers --------------------------------------
__device__ __forceinline__ unsigned long long f32x2_fma(
    unsigned long long a, unsigned long long b, unsigned long long c) {
    unsigned long long d;
    asm("fma.rn.f32x2 %0, %1, %2, %3;" : "=l"(d) : "l"(a), "l"(b), "l"(c));
    return d;
}
__device__ __forceinline__ unsigned long long f32x2_pack(float lo, float hi) {
    unsigned long long d;
    asm("mov.b64 %0, {%1, %2};" : "=l"(d) : "f"(lo), "f"(hi));
    return d;
}
__device__ __forceinline__ float2 f32x2_unpack(unsigned long long v) {
    float lo, hi;
    asm("mov.b64 {%0, %1}, %2;" : "=f"(lo), "=f"(hi) : "l"(v));
    return make_float2(lo, hi);
}
__device__ __forceinline__ uint32_t smem_u32(const void* p) {
    uint32_t a;
    asm("{ .reg .u64 t; cvta.to.shared.u64 t, %1; cvt.u32.u64 %0, t; }"
        : "=r"(a) : "l"(p));
    return a;
}

// ---------------- scratch (device globals: allocation-free) ----------------
__device__ float g_xw[BT_*C_];
__device__ float g_xa[BT_*C_];
__device__ float g_xg[BT_*C_];
__device__ __nv_bfloat16 g_xrh[BT_*C_], g_xrl[BT_*C_];
__device__ __nv_bfloat16 g_xkh[BT_*C_], g_xkl[BT_*C_];
__device__ __nv_bfloat16 g_xvh[BT_*C_], g_xvl[BT_*C_];
__device__ __nv_bfloat16 g_preh[BT_*C_], g_prel[BT_*C_];
__device__ __nv_bfloat16 g_wh[4][C_*C_], g_wl[4][C_*C_];   // Wr,Wk,Wv,Wo hi/lo
__device__ float g_r [BT_*C_];
__device__ float g_k [BT_*C_];
__device__ float g_v [BT_*C_];
__device__ float g_w1[BT_*RW_];
__device__ float g_a1[BT_*RA_];
__device__ float g_g1[BT_*RG_];
__device__ float g_decay[BT_*C_];
__device__ float g_a [BT_*C_];
__device__ float g_g [BT_*C_];
__device__ float g_ain[BT_*C_];
__device__ float g_bin[BT_*C_];
__device__ float g_o [BT_*C_];
__device__ float g_w0[C_];

// ---------------- fp32 -> bf16 hi/lo split helper ---------------------------
__device__ __forceinline__ void split4(float4 m, uint2& hi, uint2& lo) {
    __nv_bfloat16 h0 = __float2bfloat16_rn(m.x);
    __nv_bfloat16 h1 = __float2bfloat16_rn(m.y);
    __nv_bfloat16 h2 = __float2bfloat16_rn(m.z);
    __nv_bfloat16 h3 = __float2bfloat16_rn(m.w);
    __nv_bfloat16 l0 = __float2bfloat16_rn(m.x - __bfloat162float(h0));
    __nv_bfloat16 l1 = __float2bfloat16_rn(m.y - __bfloat162float(h1));
    __nv_bfloat16 l2 = __float2bfloat16_rn(m.z - __bfloat162float(h2));
    __nv_bfloat16 l3 = __float2bfloat16_rn(m.w - __bfloat162float(h3));
    __nv_bfloat162 ph0 = __halves2bfloat162(h0, h1);
    __nv_bfloat162 ph1 = __halves2bfloat162(h2, h3);
    __nv_bfloat162 pl0 = __halves2bfloat162(l0, l1);
    __nv_bfloat162 pl1 = __halves2bfloat162(l2, l3);
    hi.x = *reinterpret_cast<uint32_t*>(&ph0);
    hi.y = *reinterpret_cast<uint32_t*>(&ph1);
    lo.x = *reinterpret_cast<uint32_t*>(&pl0);
    lo.y = *reinterpret_cast<uint32_t*>(&pl1);
}

// ---------------- weight conversion: fp32 -> bf16 hi/lo --------------------
struct WConvJobs { const float* src[4]; };
__global__ void wconv_kernel(WConvJobs jobs)
{
    int w = blockIdx.y;
    int i = (blockIdx.x * blockDim.x + threadIdx.x) * 4;
    if (i >= C_*C_) return;
    float4 v = *(const float4*)(jobs.src[w] + i);
    uint2 hi, lo;
    split4(v, hi, lo);
    *(uint2*)(&g_wh[w][i]) = hi;
    *(uint2*)(&g_wl[w][i]) = lo;
}

// ---------------- token-shift mixing ----------------------------------------
__global__ void mix_kernel(const float* __restrict__ x,
    const float* __restrict__ cr, const float* __restrict__ cw,
    const float* __restrict__ ck, const float* __restrict__ cv,
    const float* __restrict__ ca, const float* __restrict__ cg)
{
    int i = blockIdx.x * blockDim.x + threadIdx.x;
    if (i >= BT_*C_/4) return;
    int idx = i * 4;
    int c  = idx & (C_-1);
    int bt = idx >> 10;
    int t  = bt & (T_-1);
    float4 xv = *(const float4*)(x + idx);
    float4 xs = make_float4(0.f,0.f,0.f,0.f);
    if (t) xs = *(const float4*)(x + idx - C_);
    float4 d = make_float4(xs.x-xv.x, xs.y-xv.y, xs.z-xv.z, xs.w-xv.w);
#define MIXV(cf, o) { float4 cc = *(const float4*)((cf)+c); \
    o = make_float4(xv.x + d.x*cc.x, xv.y + d.y*cc.y, \
                    xv.z + d.z*cc.z, xv.w + d.w*cc.w); }
    float4 m;
    uint2 hi, lo;
    MIXV(cr, m) split4(m, hi, lo);
    *(uint2*)(g_xrh + idx) = hi; *(uint2*)(g_xrl + idx) = lo;
    MIXV(ck, m) split4(m, hi, lo);
    *(uint2*)(g_xkh + idx) = hi; *(uint2*)(g_xkl + idx) = lo;
    MIXV(cv, m) split4(m, hi, lo);
    *(uint2*)(g_xvh + idx) = hi; *(uint2*)(g_xvl + idx) = lo;
    MIXV(cw, m) *(float4*)(g_xw + idx) = m;
    MIXV(ca, m) *(float4*)(g_xa + idx) = m;
    MIXV(cg, m) *(float4*)(g_xg + idx) = m;
#undef MIXV
}

// ---------------- w0 = base + cumsum(softplus(delta)) ----------------------
__global__ void w0_kernel(const float* __restrict__ base,
                          const float* __restrict__ delta)
{
    __shared__ float s[C_];
    int tid = threadIdx.x;
    float v = 0.f;
    if (tid > 0) {
        float d = delta[tid-1];
        v = (d > 20.f) ? d : log1pf(expf(d));
    }
    s[tid] = v;
    __syncthreads();
    for (int off = 1; off < C_; off <<= 1) {
        float t = (tid >= off) ? s[tid-off] : 0.f;
        __syncthreads();
        s[tid] += t;
        __syncthreads();
    }
    g_w0[tid] = base[0] + s[tid];
}

// ================ HMMA bf16-split GEMM (base-PTX mma.sync) ==================
// C[4096,1024] = (Ah+Al)[4096,1024] * (Bh+Bl)[1024,1024]^T, fp32 out.
// CTA tile 128x128, 8 warps (2m x 4n), warp tile 64x32.
// K staged 32 wide, double-buffered smem, ldmatrix fragments.
struct HJob { const __nv_bfloat16 *Ah, *Al, *Bh, *Bl; float* C; };
struct HJobs { HJob j[3]; };

#define LDK 40                         // 32 + 8 pad (80B row stride)
#define HTILE (128*LDK)                // elems per tile
#define HSMEM_BYTES (2*4*HTILE*2)      // 2 stages * 4 tiles * bf16 = 81920

__device__ __forceinline__ void ldm_x4(uint32_t addr, uint32_t r[4]) {
    asm volatile("ldmatrix.sync.aligned.m8n8.x4.shared.b16 {%0,%1,%2,%3}, [%4];"
        : "=r"(r[0]), "=r"(r[1]), "=r"(r[2]), "=r"(r[3]) : "r"(addr));
}
__device__ __forceinline__ void ldm_x2(uint32_t addr, uint32_t r[2]) {
    asm volatile("ldmatrix.sync.aligned.m8n8.x2.shared.b16 {%0,%1}, [%2];"
        : "=r"(r[0]), "=r"(r[1]) : "r"(addr));
}
__device__ __forceinline__ void mma_bf16(float* d, const uint32_t* a,
                                         const uint32_t* b) {
    asm volatile("mma.sync.aligned.m16n8k16.row.col.f32.bf16.bf16.f32 "
        "{%0,%1,%2,%3}, {%4,%5,%6,%7}, {%8,%9}, {%0,%1,%2,%3};"
        : "+f"(d[0]), "+f"(d[1]), "+f"(d[2]), "+f"(d[3])
        : "r"(a[0]), "r"(a[1]), "r"(a[2]), "r"(a[3]), "r"(b[0]), "r"(b[1]));
}

__global__ void __launch_bounds__(256, 1) hgemm_kernel(HJobs jobs)
{
    HJob jb = jobs.j[blockIdx.z];
    const int m0 = blockIdx.y * 128;
    const int n0 = blockIdx.x * 128;

    extern __shared__ __nv_bfloat16 sm[];   // [stage][tile 0:Ah 1:Al 2:Bh 3:Bl]

    int tid  = threadIdx.x;
    int wid  = tid >> 5;
    int lane = tid & 31;
    int wm = (wid & 1) * 64;
    int wn = (wid >> 1) * 32;

    // ---- loaders: row = tid>>1, seg = tid&1 (16 bf16 = 2x uint4) ----
    int lrow = tid >> 1, lseg = tid & 1;
    const __nv_bfloat16* gsrc[4] = {
        jb.Ah + (size_t)(m0 + lrow) * C_ + lseg * 16,
        jb.Al + (size_t)(m0 + lrow) * C_ + lseg * 16,
        jb.Bh + (size_t)(n0 + lrow) * C_ + lseg * 16,
        jb.Bl + (size_t)(n0 + lrow) * C_ + lseg * 16 };
    uint32_t sdst = lrow * LDK + lseg * 16;   // elem offset within tile

    float acc[4][4][4];
#pragma unroll
    for (int i = 0; i < 4; i++)
#pragma unroll
        for (int j = 0; j < 4; j++)
#pragma unroll
            for (int q = 0; q < 4; q++) acc[i][j][q] = 0.f;

    // per-lane ldmatrix address pieces (bytes)
    uint32_t rowA = (lane & 15) * (LDK*2);
    uint32_t colA = (lane >> 4) * 16;
    uint32_t rowB = (lane & 7)  * (LDK*2);
    uint32_t colB = ((lane >> 3) & 1) * 16;

    uint4 pf[4][2];
#pragma unroll
    for (int tl = 0; tl < 4; tl++) {
        pf[tl][0] = *(const uint4*)(gsrc[tl]);
        pf[tl][1] = *(const uint4*)(gsrc[tl] + 8);
    }

    for (int c = 0; c < 32; c++) {
        __nv_bfloat16* buf = sm + (size_t)(c & 1) * 4 * HTILE;
#pragma unroll
        for (int tl = 0; tl < 4; tl++) {
            *(uint4*)(buf + tl*HTILE + sdst)     = pf[tl][0];
            *(uint4*)(buf + tl*HTILE + sdst + 8) = pf[tl][1];
        }
        __syncthreads();
        if (c + 1 < 32) {
#pragma unroll
            for (int tl = 0; tl < 4; tl++) {
                pf[tl][0] = *(const uint4*)(gsrc[tl] + (c+1)*32);
                pf[tl][1] = *(const uint4*)(gsrc[tl] + (c+1)*32 + 8);
            }
        }
        uint32_t sb = smem_u32(buf);
        // products: (Ah,Bh), (Ah,Bl), (Al,Bh)
#pragma unroll
        for (int p = 0; p < 3; p++) {
            uint32_t abase = sb + ((p == 2) ? 1 : 0) * (HTILE*2);
            uint32_t bbase = sb + ((p == 1) ? 3 : 2) * (HTILE*2);
#pragma unroll
            for (int ks = 0; ks < 2; ks++) {
                uint32_t af[4][4], bf[4][2];
#pragma unroll
                for (int mt = 0; mt < 4; mt++)
                    ldm_x4(abase + (wm + mt*16) * (LDK*2) + rowA + ks*32 + colA,
                           af[mt]);
#pragma unroll
                for (int nt = 0; nt < 4; nt++)
                    ldm_x2(bbase + (wn + nt*8) * (LDK*2) + rowB + ks*32 + colB,
                           bf[nt]);
#pragma unroll
                for (int mt = 0; mt < 4; mt++)
#pragma unroll
                    for (int nt = 0; nt < 4; nt++)
                        mma_bf16(acc[mt][nt], af[mt], bf[nt]);
            }
        }
    }

    // epilogue: thread (g=lane>>2, tg=lane&3) holds rows g,g+8 cols 2tg,2tg+1
    int g = lane >> 2, tg = lane & 3;
#pragma unroll
    for (int mt = 0; mt < 4; mt++) {
#pragma unroll
        for (int nt = 0; nt < 4; nt++) {
            float* p0 = jb.C + (size_t)(m0 + wm + mt*16 + g) * C_
                             + n0 + wn + nt*8 + 2*tg;
            *(float2*)p0            = make_float2(acc[mt][nt][0], acc[mt][nt][1]);
            *(float2*)(p0 + 8*C_)   = make_float2(acc[mt][nt][2], acc[mt][nt][3]);
        }
    }
}

// ---------------- fused f32x2 SGEMM (LoRA path) -----------------------------
struct GemmJob { const float* A; const float* Bm; float* C;
                 const float* bias; int N; int K; int act; };
struct Jobs3 { GemmJob j[3]; };

__global__ void __launch_bounds__(256)
fgemm_kernel(Jobs3 jobs)
{
    GemmJob jb = jobs.j[blockIdx.z];
    const int N = jb.N, K = jb.K;
    const int m0 = blockIdx.y * 128;
    const int n0 = blockIdx.x * 128;
    if (n0 >= N) return;

    __shared__ alignas(16) float As[8][132];
    __shared__ alignas(16) float Bs[8][132];

    int tid = threadIdx.x;
    int lr = tid >> 1;
    int lq = (tid & 1) * 4;
    int tx = tid & 15;
    int ty = tid >> 4;

    const float* Ap = jb.A  + (size_t)(m0 + lr) * K + lq;
    const float* Bp = jb.Bm + (size_t)(n0 + lr) * K + lq;
    bool bok = (n0 + lr) < N;

    unsigned long long acc[8][4];
#pragma unroll
    for (int i = 0; i < 8; i++)
#pragma unroll
        for (int j = 0; j < 4; j++) acc[i][j] = 0ull;

    float4 av = *(const float4*)Ap;
    float4 bv = make_float4(0.f,0.f,0.f,0.f);
    if (bok) bv = *(const float4*)Bp;

    for (int k0 = 0; k0 < K; k0 += 8) {
        __syncthreads();
        As[lq+0][lr] = av.x; As[lq+1][lr] = av.y;
        As[lq+2][lr] = av.z; As[lq+3][lr] = av.w;
        Bs[lq+0][lr] = bv.x; Bs[lq+1][lr] = bv.y;
        Bs[lq+2][lr] = bv.z; Bs[lq+3][lr] = bv.w;
        __syncthreads();
        if (k0 + 8 < K) {
            av = *(const float4*)(Ap + k0 + 8);
            if (bok) bv = *(const float4*)(Bp + k0 + 8);
        }
#pragma unroll
        for (int kk = 0; kk < 8; kk++) {
            float a_[8];
            *(float4*)&a_[0] = *(const float4*)&As[kk][ty*8];
            *(float4*)&a_[4] = *(const float4*)&As[kk][ty*8+4];
            ulonglong2 b0 = *(const ulonglong2*)&Bs[kk][tx*8];
            ulonglong2 b1 = *(const ulonglong2*)&Bs[kk][tx*8+4];
#pragma unroll
            for (int i = 0; i < 8; i++) {
                unsigned long long a2 = f32x2_pack(a_[i], a_[i]);
                acc[i][0] = f32x2_fma(a2, b0.x, acc[i][0]);
                acc[i][1] = f32x2_fma(a2, b0.y, acc[i][1]);
                acc[i][2] = f32x2_fma(a2, b1.x, acc[i][2]);
                acc[i][3] = f32x2_fma(a2, b1.y, acc[i][3]);
            }
        }
    }

    const int act = jb.act;
#pragma unroll
    for (int i = 0; i < 8; i++) {
        int m = m0 + ty*8 + i;
#pragma unroll
        for (int jq = 0; jq < 4; jq++) {
            float2 y = f32x2_unpack(acc[i][jq]);
            float ys[2] = { y.x, y.y };
            int nb = n0 + tx*8 + jq*2;
#pragma unroll
            for (int s = 0; s < 2; s++) {
                int nn = nb + s;
                if (nn < N) {
                    float yy = ys[s];
                    if (act == 1) {
                        yy = tanhf(yy);
                    } else if (act == 2) {
                        float bb = jb.bias ? jb.bias[nn] : 0.f;
                        yy = 1.f / (1.f + expf(-(yy + bb)));
                    } else if (act == 3) {
                        float tt = g_w0[nn] + yy + jb.bias[nn];
                        float nt = -tt;
                        float sp = (nt > 20.f) ? nt : log1pf(expf(nt));
                        yy = expf(-expf(-sp - 0.5f));
                    }
                    jb.C[(size_t)m * N + nn] = yy;
                }
            }
        }
    }
}

// ---------------- kk normalize / a_in / b_in / k update --------------------
__global__ void kk_kernel(const float* __restrict__ kkc,
                          const float* __restrict__ kac)
{
    int gid  = blockIdx.x * blockDim.x + threadIdx.x;
    int lane = gid & 31;
    int grp  = gid >> 5;
    if (grp >= BT_*H_) return;
    int bt = grp / H_, h = grp % H_;
    int base = bt * C_ + h * D_;
    int c0   = h * D_;

    float k0v = g_k[base + lane],      k1v = g_k[base + 32 + lane];
    float a0  = g_a[base + lane],      a1  = g_a[base + 32 + lane];
    float kk0 = k0v * kkc[c0 + lane],  kk1 = k1v * kkc[c0 + 32 + lane];

    float ss = kk0*kk0 + kk1*kk1;
#pragma unroll
    for (int o = 16; o; o >>= 1) ss += __shfl_xor_sync(0xffffffffu, ss, o);
    float inv = 1.f / fmaxf(sqrtf(ss), 1e-12f);
    kk0 *= inv; kk1 *= inv;

    g_ain[base + lane]      = -kk0;
    g_ain[base + 32 + lane] = -kk1;
    g_bin[base + lane]      = kk0 * a0;
    g_bin[base + 32 + lane] = kk1 * a1;
    g_k[base + lane]        = k0v * (1.f + (a0 - 1.f) * kac[c0 + lane]);
    g_k[base + 32 + lane]   = k1v * (1.f + (a1 - 1.f) * kac[c0 + 32 + lane]);
}

// ---------------- sequential RWKV-7 recurrence ------------------------------
__global__ void __launch_bounds__(512, 1) rec_kernel()
{
    int bh = blockIdx.x;
    int b = bh >> 4, h = bh & 15;
    size_t base = (size_t)b * T_ * C_ + h * D_;

    __shared__ alignas(16) float sh[2][6][64];

    int tid = threadIdx.x;
    int row = tid >> 3;
    int cp  = tid & 7;
    int c0  = cp * 8;

    int  vec = tid >> 4, q = tid & 15;
    bool loader = tid < 96;
    const float* srcp = nullptr;
    if (loader) {
        const float* srcs[6] = { g_r, g_decay, g_k, g_v, g_ain, g_bin };
        srcp = srcs[vec] + base + q*4;
    }

    unsigned long long S[4] = {0ull, 0ull, 0ull, 0ull};

    float4 ld = make_float4(0.f,0.f,0.f,0.f);
    if (loader) {
        ld = *(const float4*)srcp;
        *(float4*)&sh[0][vec][q*4] = ld;
    }

    for (int t = 0; t < T_; t++) {
        int cur = t & 1, nxt = cur ^ 1;
        __syncthreads();

        if (loader && t + 1 < T_)
            ld = *(const float4*)(srcp + (size_t)(t+1)*C_);

        ulonglong2 aA = *(const ulonglong2*)&sh[cur][4][c0];
        ulonglong2 aB = *(const ulonglong2*)&sh[cur][4][c0+4];
        unsigned long long sacc = f32x2_fma(S[0], aA.x, 0ull);
        sacc = f32x2_fma(S[1], aA.y, sacc);
        sacc = f32x2_fma(S[2], aB.x, sacc);
        sacc = f32x2_fma(S[3], aB.y, sacc);
        float2 sp = f32x2_unpack(sacc);
        float sa = sp.x + sp.y;
        sa += __shfl_xor_sync(0xffffffffu, sa, 1);
        sa += __shfl_xor_sync(0xffffffffu, sa, 2);
        sa += __shfl_xor_sync(0xffffffffu, sa, 4);

        float vj = sh[cur][3][row];
        ulonglong2 wA = *(const ulonglong2*)&sh[cur][1][c0];
        ulonglong2 wB = *(const ulonglong2*)&sh[cur][1][c0+4];
        ulonglong2 bA = *(const ulonglong2*)&sh[cur][5][c0];
        ulonglong2 bB = *(const ulonglong2*)&sh[cur][5][c0+4];
        ulonglong2 kA = *(const ulonglong2*)&sh[cur][2][c0];
        ulonglong2 kB = *(const ulonglong2*)&sh[cur][2][c0+4];
        ulonglong2 rA = *(const ulonglong2*)&sh[cur][0][c0];
        ulonglong2 rB = *(const ulonglong2*)&sh[cur][0][c0+4];

        unsigned long long sa2 = f32x2_pack(sa, sa);
        unsigned long long v2  = f32x2_pack(vj, vj);

        S[0] = f32x2_fma(v2, kA.x, f32x2_fma(sa2, bA.x, f32x2_fma(S[0], wA.x, 0ull)));
        S[1] = f32x2_fma(v2, kA.y, f32x2_fma(sa2, bA.y, f32x2_fma(S[1], wA.y, 0ull)));
        S[2] = f32x2_fma(v2, kB.x, f32x2_fma(sa2, bB.x, f32x2_fma(S[2], wB.x, 0ull)));
        S[3] = f32x2_fma(v2, kB.y, f32x2_fma(sa2, bB.y, f32x2_fma(S[3], wB.y, 0ull)));

        unsigned long long oacc = f32x2_fma(S[0], rA.x, 0ull);
        oacc = f32x2_fma(S[1], rA.y, oacc);
        oacc = f32x2_fma(S[2], rB.x, oacc);
        oacc = f32x2_fma(S[3], rB.y, oacc);
        float2 op = f32x2_unpack(oacc);
        float o = op.x + op.y;
        o += __shfl_xor_sync(0xffffffffu, o, 1);
        o += __shfl_xor_sync(0xffffffffu, o, 2);
        o += __shfl_xor_sync(0xffffffffu, o, 4);
        if (cp == 0) g_o[base + (size_t)t*C_ + row] = o;

        if (loader && t + 1 < T_)
            *(float4*)&sh[nxt][vec][q*4] = ld;
    }
}

// ---------------- GroupNorm + bonus + gate (emits bf16 hi/lo) --------------
__global__ void post_kernel(const float* __restrict__ rk,
                            const float* __restrict__ gnw,
                            const float* __restrict__ gnb)
{
    int gid  = blockIdx.x * blockDim.x + threadIdx.x;
    int lane = gid & 31;
    int grp  = gid >> 5;
    if (grp >= BT_*H_) return;
    int bt = grp / H_, h = grp % H_;
    int base = bt * C_ + h * D_;
    int c0   = h * D_;

    float o0 = g_o[base + lane], o1 = g_o[base + 32 + lane];
    float su = o0 + o1;
    float sq = o0*o0 + o1*o1;
    float r0 = g_r[base + lane], r1 = g_r[base + 32 + lane];
    float k0 = g_k[base + lane], k1 = g_k[base + 32 + lane];
    float bsum = r0*k0*rk[c0 + lane] + r1*k1*rk[c0 + 32 + lane];
#pragma unroll
    for (int o = 16; o; o >>= 1) {
        su   += __shfl_xor_sync(0xffffffffu, su,   o);
        sq   += __shfl_xor_sync(0xffffffffu, sq,   o);
        bsum += __shfl_xor_sync(0xffffffffu, bsum, o);
    }
    float mu  = su / 64.f;
    float var = sq / 64.f - mu * mu;
    float inv = rsqrtf(var + EPS_);

    float v0 = g_v[base + lane], v1 = g_v[base + 32 + lane];
    float on0 = (o0 - mu) * inv * gnw[c0 + lane]      + gnb[c0 + lane];
    float on1 = (o1 - mu) * inv * gnw[c0 + 32 + lane] + gnb[c0 + 32 + lane];
    float p0 = (on0 + bsum * v0) * g_g[base + lane];
    float p1 = (on1 + bsum * v1) * g_g[base + 32 + lane];

    __nv_bfloat16 h0 = __float2bfloat16_rn(p0);
    __nv_bfloat16 h1 = __float2bfloat16_rn(p1);
    g_preh[base + lane]      = h0;
    g_preh[base + 32 + lane] = h1;
    g_prel[base + lane]      = __float2bfloat16_rn(p0 - __bfloat162float(h0));
    g_prel[base + 32 + lane] = __float2bfloat16_rn(p1 - __bfloat162float(h1));
}

// ---------------- host launcher ---------------------------------------------
extern "C" void kernel_launch(void* const* d_in, const int* in_sizes, int n_in,
                              void* d_out, int out_size)
{
    const float* x        = (const float*)d_in[0];
    const float* x_r      = (const float*)d_in[1];
    const float* x_w      = (const float*)d_in[2];
    const float* x_k      = (const float*)d_in[3];
    const float* x_v      = (const float*)d_in[4];
    const float* x_a      = (const float*)d_in[5];
    const float* x_g      = (const float*)d_in[6];
    const float* k_k      = (const float*)d_in[7];
    const float* k_a      = (const float*)d_in[8];
    const float* r_k      = (const float*)d_in[9];
    const float* Wr       = (const float*)d_in[10];
    const float* Wk       = (const float*)d_in[11];
    const float* Wv       = (const float*)d_in[12];
    const float* Wo       = (const float*)d_in[13];
    const float* wA       = (const float*)d_in[14];
    const float* wB       = (const float*)d_in[15];
    const float* wBias    = (const float*)d_in[16];
    const float* aA       = (const float*)d_in[17];
    const float* aB       = (const float*)d_in[18];
    const float* aBias    = (const float*)d_in[19];
    const float* gA       = (const float*)d_in[20];
    const float* gB       = (const float*)d_in[21];
    const float* gnw      = (const float*)d_in[22];
    const float* gnb      = (const float*)d_in[23];
    const float* w0_base  = (const float*)d_in[24];
    const float* w0_delta = (const float*)d_in[25];
    float* out = (float*)d_out;

    float *p_xw,*p_xa,*p_xg;
    float *p_r,*p_k,*p_v,*p_w1,*p_a1,*p_g1;
    float *p_dec,*p_a,*p_g;
    __nv_bfloat16 *p_xrh,*p_xrl,*p_xkh,*p_xkl,*p_xvh,*p_xvl,*p_preh,*p_prel;
    __nv_bfloat16 *p_wh,*p_wl;
    cudaGetSymbolAddress((void**)&p_xw, g_xw);
    cudaGetSymbolAddress((void**)&p_xa, g_xa);
    cudaGetSymbolAddress((void**)&p_xg, g_xg);
    cudaGetSymbolAddress((void**)&p_r,  g_r);
    cudaGetSymbolAddress((void**)&p_k,  g_k);
    cudaGetSymbolAddress((void**)&p_v,  g_v);
    cudaGetSymbolAddress((void**)&p_w1, g_w1);
    cudaGetSymbolAddress((void**)&p_a1, g_a1);
    cudaGetSymbolAddress((void**)&p_g1, g_g1);
    cudaGetSymbolAddress((void**)&p_dec,g_decay);
    cudaGetSymbolAddress((void**)&p_a,  g_a);
    cudaGetSymbolAddress((void**)&p_g,  g_g);
    cudaGetSymbolAddress((void**)&p_xrh, g_xrh);
    cudaGetSymbolAddress((void**)&p_xrl, g_xrl);
    cudaGetSymbolAddress((void**)&p_xkh, g_xkh);
    cudaGetSymbolAddress((void**)&p_xkl, g_xkl);
    cudaGetSymbolAddress((void**)&p_xvh, g_xvh);
    cudaGetSymbolAddress((void**)&p_xvl, g_xvl);
    cudaGetSymbolAddress((void**)&p_preh, g_preh);
    cudaGetSymbolAddress((void**)&p_prel, g_prel);
    cudaGetSymbolAddress((void**)&p_wh, g_wh);
    cudaGetSymbolAddress((void**)&p_wl, g_wl);

    cudaFuncSetAttribute(hgemm_kernel, cudaFuncAttributeMaxDynamicSharedMemorySize,
                         HSMEM_BYTES);

    // 0) weight fp32 -> bf16 hi/lo
    {
        WConvJobs wj;
        wj.src[0] = Wr; wj.src[1] = Wk; wj.src[2] = Wv; wj.src[3] = Wo;
        wconv_kernel<<<dim3(C_*C_/4/256, 4), 256>>>(wj);
    }

    // 1) token-shift mixes (+ bf16 hi/lo for xr/xk/xv)
    mix_kernel<<<(BT_*C_/4 + 255)/256, 256>>>(x, x_r, x_w, x_k, x_v, x_a, x_g);

    // 2) w0 scan
    w0_kernel<<<1, C_>>>(w0_base, w0_delta);

    // 3) big r/k/v projections on tensor cores (bf16-split HMMA)
    {
        HJobs hj;
        hj.j[0] = { p_xrh, p_xrl, p_wh + 0*C_*C_, p_wl + 0*C_*C_, p_r };
        hj.j[1] = { p_xkh, p_xkl, p_wh + 1*C_*C_, p_wl + 1*C_*C_, p_k };
        hj.j[2] = { p_xvh, p_xvl, p_wh + 2*C_*C_, p_wl + 2*C_*C_, p_v };
        hgemm_kernel<<<dim3(C_/128, BT_/128, 3), 256, HSMEM_BYTES>>>(hj);
    }

    // 4) LoRA stage 1 fused
    {
        Jobs3 jb;
        jb.j[0] = { p_xw, wA, p_w1, nullptr, RW_, C_, 1 };
        jb.j[1] = { p_xa, aA, p_a1, nullptr, RA_, C_, 0 };
        jb.j[2] = { p_xg, gA, p_g1, nullptr, RG_, C_, 2 };
        fgemm_kernel<<<dim3((RG_+127)/128, BT_/128, 3), 256>>>(jb);
    }

    // 5) LoRA stage 2 fused
    {
        Jobs3 jb;
        jb.j[0] = { p_w1, wB, p_dec, wBias,   C_, RW_, 3 };
        jb.j[1] = { p_a1, aB, p_a,   aBias,   C_, RA_, 2 };
        jb.j[2] = { p_g1, gB, p_g,   nullptr, C_, RG_, 0 };
        fgemm_kernel<<<dim3(C_/128, BT_/128, 3), 256>>>(jb);
    }

    // 6) kk normalize / a_in / b_in / k update
    kk_kernel<<<(BT_*H_*32 + 255)/256, 256>>>(k_k, k_a);

    // 7) sequential recurrence
    rec_kernel<<<B_*H_, 512>>>();

    // 8) GroupNorm + bonus + gate (-> bf16 hi/lo)
    post_kernel<<<(BT_*H_*32 + 255)/256, 256>>>(r_k, gnw, gnb);

    // 9) output projection on tensor cores
    {
        HJobs hj;
        hj.j[0] = { p_preh, p_prel, p_wh + 3*C_*C_, p_wl + 3*C_*C_, out };
        hj.j[1] = hj.j[0];
        hj.j[2] = hj.j[0];
        hgemm_kernel<<<dim3(C_/128, BT_/128, 1), 256, HSMEM_BYTES>>>(hj);
    }
}

// round 8
// speedup vs baseline: 1.5270x; 1.0191x over previous
#include <cuda_runtime.h>
#include <cuda_bf16.h>
#include <math.h>
#include <stdint.h>

#define B_ 2
#define T_ 2048
#define C_ 1024
#define H_ 16
#define D_ 64
#define BT_ (B_*T_)
#define RW_ 64
#define RA_ 64
#define RG_ 160
#define EPS_ 6.4e-4f   // D * 1e-5
#define RCHUNK 16      // recurrence timesteps per smem chunk

// ---------------- packed f32x2 helpers --------------------------------------
__device__ __forceinline__ unsigned long long f32x2_fma(
    unsigned long long a, unsigned long long b, unsigned long long c) {
    unsigned long long d;
    asm("fma.rn.f32x2 %0, %1, %2, %3;" : "=l"(d) : "l"(a), "l"(b), "l"(c));
    return d;
}
__device__ __forceinline__ unsigned long long f32x2_pack(float lo, float hi) {
    unsigned long long d;
    asm("mov.b64 %0, {%1, %2};" : "=l"(d) : "f"(lo), "f"(hi));
    return d;
}
__device__ __forceinline__ float2 f32x2_unpack(unsigned long long v) {
    float lo, hi;
    asm("mov.b64 {%0, %1}, %2;" : "=f"(lo), "=f"(hi) : "l"(v));
    return make_float2(lo, hi);
}
__device__ __forceinline__ uint32_t smem_u32(const void* p) {
    uint32_t a;
    asm("{ .reg .u64 t; cvta.to.shared.u64 t, %1; cvt.u32.u64 %0, t; }"
        : "=r"(a) : "l"(p));
    return a;
}

// ---------------- scratch (device globals: allocation-free) ----------------
__device__ float g_xw[BT_*C_];
__device__ float g_xa[BT_*C_];
__device__ float g_xg[BT_*C_];
__device__ __nv_bfloat16 g_xrh[BT_*C_], g_xrl[BT_*C_];
__device__ __nv_bfloat16 g_xkh[BT_*C_], g_xkl[BT_*C_];
__device__ __nv_bfloat16 g_xvh[BT_*C_], g_xvl[BT_*C_];
__device__ __nv_bfloat16 g_preh[BT_*C_], g_prel[BT_*C_];
__device__ __nv_bfloat16 g_wh[4][C_*C_], g_wl[4][C_*C_];   // Wr,Wk,Wv,Wo hi/lo
__device__ float g_r [BT_*C_];
__device__ float g_k [BT_*C_];
__device__ float g_v [BT_*C_];
__device__ float g_w1[BT_*RW_];
__device__ float g_a1[BT_*RA_];
__device__ float g_g1[BT_*RG_];
__device__ float g_decay[BT_*C_];
__device__ float g_a [BT_*C_];
__device__ float g_g [BT_*C_];
__device__ float g_ain[BT_*C_];
__device__ float g_bin[BT_*C_];
__device__ float g_o [BT_*C_];
__device__ float g_w0[C_];

// ---------------- fp32 -> bf16 hi/lo split helper ---------------------------
__device__ __forceinline__ void split4(float4 m, uint2& hi, uint2& lo) {
    __nv_bfloat16 h0 = __float2bfloat16_rn(m.x);
    __nv_bfloat16 h1 = __float2bfloat16_rn(m.y);
    __nv_bfloat16 h2 = __float2bfloat16_rn(m.z);
    __nv_bfloat16 h3 = __float2bfloat16_rn(m.w);
    __nv_bfloat16 l0 = __float2bfloat16_rn(m.x - __bfloat162float(h0));
    __nv_bfloat16 l1 = __float2bfloat16_rn(m.y - __bfloat162float(h1));
    __nv_bfloat16 l2 = __float2bfloat16_rn(m.z - __bfloat162float(h2));
    __nv_bfloat16 l3 = __float2bfloat16_rn(m.w - __bfloat162float(h3));
    __nv_bfloat162 ph0 = __halves2bfloat162(h0, h1);
    __nv_bfloat162 ph1 = __halves2bfloat162(h2, h3);
    __nv_bfloat162 pl0 = __halves2bfloat162(l0, l1);
    __nv_bfloat162 pl1 = __halves2bfloat162(l2, l3);
    hi.x = *reinterpret_cast<uint32_t*>(&ph0);
    hi.y = *reinterpret_cast<uint32_t*>(&ph1);
    lo.x = *reinterpret_cast<uint32_t*>(&pl0);
    lo.y = *reinterpret_cast<uint32_t*>(&pl1);
}

// ---------------- weight conversion: fp32 -> bf16 hi/lo --------------------
struct WConvJobs { const float* src[4]; };
__global__ void wconv_kernel(WConvJobs jobs)
{
    int w = blockIdx.y;
    int i = (blockIdx.x * blockDim.x + threadIdx.x) * 4;
    if (i >= C_*C_) return;
    float4 v = *(const float4*)(jobs.src[w] + i);
    uint2 hi, lo;
    split4(v, hi, lo);
    *(uint2*)(&g_wh[w][i]) = hi;
    *(uint2*)(&g_wl[w][i]) = lo;
}

// ---------------- token-shift mixing ----------------------------------------
__global__ void mix_kernel(const float* __restrict__ x,
    const float* __restrict__ cr, const float* __restrict__ cw,
    const float* __restrict__ ck, const float* __restrict__ cv,
    const float* __restrict__ ca, const float* __restrict__ cg)
{
    int i = blockIdx.x * blockDim.x + threadIdx.x;
    if (i >= BT_*C_/4) return;
    int idx = i * 4;
    int c  = idx & (C_-1);
    int bt = idx >> 10;
    int t  = bt & (T_-1);
    float4 xv = *(const float4*)(x + idx);
    float4 xs = make_float4(0.f,0.f,0.f,0.f);
    if (t) xs = *(const float4*)(x + idx - C_);
    float4 d = make_float4(xs.x-xv.x, xs.y-xv.y, xs.z-xv.z, xs.w-xv.w);
#define MIXV(cf, o) { float4 cc = *(const float4*)((cf)+c); \
    o = make_float4(xv.x + d.x*cc.x, xv.y + d.y*cc.y, \
                    xv.z + d.z*cc.z, xv.w + d.w*cc.w); }
    float4 m;
    uint2 hi, lo;
    MIXV(cr, m) split4(m, hi, lo);
    *(uint2*)(g_xrh + idx) = hi; *(uint2*)(g_xrl + idx) = lo;
    MIXV(ck, m) split4(m, hi, lo);
    *(uint2*)(g_xkh + idx) = hi; *(uint2*)(g_xkl + idx) = lo;
    MIXV(cv, m) split4(m, hi, lo);
    *(uint2*)(g_xvh + idx) = hi; *(uint2*)(g_xvl + idx) = lo;
    MIXV(cw, m) *(float4*)(g_xw + idx) = m;
    MIXV(ca, m) *(float4*)(g_xa + idx) = m;
    MIXV(cg, m) *(float4*)(g_xg + idx) = m;
#undef MIXV
}

// ---------------- w0 = base + cumsum(softplus(delta)) ----------------------
__global__ void w0_kernel(const float* __restrict__ base,
                          const float* __restrict__ delta)
{
    __shared__ float s[C_];
    int tid = threadIdx.x;
    float v = 0.f;
    if (tid > 0) {
        float d = delta[tid-1];
        v = (d > 20.f) ? d : log1pf(expf(d));
    }
    s[tid] = v;
    __syncthreads();
    for (int off = 1; off < C_; off <<= 1) {
        float t = (tid >= off) ? s[tid-off] : 0.f;
        __syncthreads();
        s[tid] += t;
        __syncthreads();
    }
    g_w0[tid] = base[0] + s[tid];
}

// ================ HMMA bf16-split GEMM (base-PTX mma.sync) ==================
struct HJob { const __nv_bfloat16 *Ah, *Al, *Bh, *Bl; float* C; };
struct HJobs { HJob j[3]; };

#define LDK 40                         // 32 + 8 pad (80B row stride)
#define HTILE (128*LDK)
#define HSMEM_BYTES (2*4*HTILE*2)      // 81920

__device__ __forceinline__ void ldm_x4(uint32_t addr, uint32_t r[4]) {
    asm volatile("ldmatrix.sync.aligned.m8n8.x4.shared.b16 {%0,%1,%2,%3}, [%4];"
        : "=r"(r[0]), "=r"(r[1]), "=r"(r[2]), "=r"(r[3]) : "r"(addr));
}
__device__ __forceinline__ void ldm_x2(uint32_t addr, uint32_t r[2]) {
    asm volatile("ldmatrix.sync.aligned.m8n8.x2.shared.b16 {%0,%1}, [%2];"
        : "=r"(r[0]), "=r"(r[1]) : "r"(addr));
}
__device__ __forceinline__ void mma_bf16(float* d, const uint32_t* a,
                                         const uint32_t* b) {
    asm volatile("mma.sync.aligned.m16n8k16.row.col.f32.bf16.bf16.f32 "
        "{%0,%1,%2,%3}, {%4,%5,%6,%7}, {%8,%9}, {%0,%1,%2,%3};"
        : "+f"(d[0]), "+f"(d[1]), "+f"(d[2]), "+f"(d[3])
        : "r"(a[0]), "r"(a[1]), "r"(a[2]), "r"(a[3]), "r"(b[0]), "r"(b[1]));
}

__global__ void __launch_bounds__(256, 1) hgemm_kernel(HJobs jobs)
{
    HJob jb = jobs.j[blockIdx.z];
    const int m0 = blockIdx.y * 128;
    const int n0 = blockIdx.x * 128;

    extern __shared__ __nv_bfloat16 sm[];

    int tid  = threadIdx.x;
    int wid  = tid >> 5;
    int lane = tid & 31;
    int wm = (wid & 1) * 64;
    int wn = (wid >> 1) * 32;

    int lrow = tid >> 1, lseg = tid & 1;
    const __nv_bfloat16* gsrc[4] = {
        jb.Ah + (size_t)(m0 + lrow) * C_ + lseg * 16,
        jb.Al + (size_t)(m0 + lrow) * C_ + lseg * 16,
        jb.Bh + (size_t)(n0 + lrow) * C_ + lseg * 16,
        jb.Bl + (size_t)(n0 + lrow) * C_ + lseg * 16 };
    uint32_t sdst = lrow * LDK + lseg * 16;

    float acc[4][4][4];
#pragma unroll
    for (int i = 0; i < 4; i++)
#pragma unroll
        for (int j = 0; j < 4; j++)
#pragma unroll
            for (int q = 0; q < 4; q++) acc[i][j][q] = 0.f;

    uint32_t rowA = (lane & 15) * (LDK*2);
    uint32_t colA = (lane >> 4) * 16;
    uint32_t rowB = (lane & 7)  * (LDK*2);
    uint32_t colB = ((lane >> 3) & 1) * 16;

    uint4 pf[4][2];
#pragma unroll
    for (int tl = 0; tl < 4; tl++) {
        pf[tl][0] = *(const uint4*)(gsrc[tl]);
        pf[tl][1] = *(const uint4*)(gsrc[tl] + 8);
    }

    for (int c = 0; c < 32; c++) {
        __nv_bfloat16* buf = sm + (size_t)(c & 1) * 4 * HTILE;
#pragma unroll
        for (int tl = 0; tl < 4; tl++) {
            *(uint4*)(buf + tl*HTILE + sdst)     = pf[tl][0];
            *(uint4*)(buf + tl*HTILE + sdst + 8) = pf[tl][1];
        }
        __syncthreads();
        if (c + 1 < 32) {
#pragma unroll
            for (int tl = 0; tl < 4; tl++) {
                pf[tl][0] = *(const uint4*)(gsrc[tl] + (c+1)*32);
                pf[tl][1] = *(const uint4*)(gsrc[tl] + (c+1)*32 + 8);
            }
        }
        uint32_t sb = smem_u32(buf);
#pragma unroll
        for (int p = 0; p < 3; p++) {
            uint32_t abase = sb + ((p == 2) ? 1 : 0) * (HTILE*2);
            uint32_t bbase = sb + ((p == 1) ? 3 : 2) * (HTILE*2);
#pragma unroll
            for (int ks = 0; ks < 2; ks++) {
                uint32_t af[4][4], bfr[4][2];
#pragma unroll
                for (int mt = 0; mt < 4; mt++)
                    ldm_x4(abase + (wm + mt*16) * (LDK*2) + rowA + ks*32 + colA,
                           af[mt]);
#pragma unroll
                for (int nt = 0; nt < 4; nt++)
                    ldm_x2(bbase + (wn + nt*8) * (LDK*2) + rowB + ks*32 + colB,
                           bfr[nt]);
#pragma unroll
                for (int mt = 0; mt < 4; mt++)
#pragma unroll
                    for (int nt = 0; nt < 4; nt++)
                        mma_bf16(acc[mt][nt], af[mt], bfr[nt]);
            }
        }
    }

    int g = lane >> 2, tg = lane & 3;
#pragma unroll
    for (int mt = 0; mt < 4; mt++) {
#pragma unroll
        for (int nt = 0; nt < 4; nt++) {
            float* p0 = jb.C + (size_t)(m0 + wm + mt*16 + g) * C_
                             + n0 + wn + nt*8 + 2*tg;
            *(float2*)p0            = make_float2(acc[mt][nt][0], acc[mt][nt][1]);
            *(float2*)(p0 + 8*C_)   = make_float2(acc[mt][nt][2], acc[mt][nt][3]);
        }
    }
}

// ---------------- fused f32x2 SGEMM (LoRA path), templated M-tile -----------
struct GemmJob { const float* A; const float* Bm; float* C;
                 const float* bias; int N; int K; int act; };
struct Jobs3 { GemmJob j[3]; };

template<int MT>
__global__ void __launch_bounds__(256)
fgemm_kernel(Jobs3 jobs)
{
    GemmJob jb = jobs.j[blockIdx.z];
    const int N = jb.N, K = jb.K;
    const int m0 = blockIdx.y * MT;
    const int n0 = blockIdx.x * 128;
    if (n0 >= N) return;

    constexpr int MROWS = MT/16;      // rows per thread-row-group: 8 or 4
    __shared__ alignas(16) float As[8][MT+4];
    __shared__ alignas(16) float Bs[8][132];

    int tid = threadIdx.x;
    int tx = tid & 15;
    int ty = tid >> 4;

    // loaders
    int blr = tid >> 1, blq = (tid & 1) * 4;                 // B: 128 rows
    int alr, alq;
    if (MT == 128) { alr = tid >> 1; alq = (tid & 1) * 4; }  // A: 128 rows
    else           { alr = tid & 63; alq = ((tid >> 6) & 1) * 4; } // 64 rows

    const float* Ap = jb.A  + (size_t)(m0 + alr) * K + alq;
    const float* Bp = jb.Bm + (size_t)(n0 + blr) * K + blq;
    bool bok = (n0 + blr) < N;

    unsigned long long acc[MROWS][4];
#pragma unroll
    for (int i = 0; i < MROWS; i++)
#pragma unroll
        for (int j = 0; j < 4; j++) acc[i][j] = 0ull;

    float4 av = *(const float4*)Ap;
    float4 bv = make_float4(0.f,0.f,0.f,0.f);
    if (bok) bv = *(const float4*)Bp;

    for (int k0 = 0; k0 < K; k0 += 8) {
        __syncthreads();
        As[alq+0][alr] = av.x; As[alq+1][alr] = av.y;
        As[alq+2][alr] = av.z; As[alq+3][alr] = av.w;
        Bs[blq+0][blr] = bv.x; Bs[blq+1][blr] = bv.y;
        Bs[blq+2][blr] = bv.z; Bs[blq+3][blr] = bv.w;
        __syncthreads();
        if (k0 + 8 < K) {
            av = *(const float4*)(Ap + k0 + 8);
            if (bok) bv = *(const float4*)(Bp + k0 + 8);
        }
#pragma unroll
        for (int kk = 0; kk < 8; kk++) {
            float a_[MROWS];
#pragma unroll
            for (int i = 0; i < MROWS; i += 4)
                *(float4*)&a_[i] = *(const float4*)&As[kk][ty*MROWS + i];
            ulonglong2 b0 = *(const ulonglong2*)&Bs[kk][tx*8];
            ulonglong2 b1 = *(const ulonglong2*)&Bs[kk][tx*8+4];
#pragma unroll
            for (int i = 0; i < MROWS; i++) {
                unsigned long long a2 = f32x2_pack(a_[i], a_[i]);
                acc[i][0] = f32x2_fma(a2, b0.x, acc[i][0]);
                acc[i][1] = f32x2_fma(a2, b0.y, acc[i][1]);
                acc[i][2] = f32x2_fma(a2, b1.x, acc[i][2]);
                acc[i][3] = f32x2_fma(a2, b1.y, acc[i][3]);
            }
        }
    }

    const int act = jb.act;
#pragma unroll
    for (int i = 0; i < MROWS; i++) {
        int m = m0 + ty*MROWS + i;
#pragma unroll
        for (int jq = 0; jq < 4; jq++) {
            float2 y = f32x2_unpack(acc[i][jq]);
            float ys[2] = { y.x, y.y };
            int nb = n0 + tx*8 + jq*2;
#pragma unroll
            for (int s = 0; s < 2; s++) {
                int nn = nb + s;
                if (nn < N) {
                    float yy = ys[s];
                    if (act == 1) {
                        yy = tanhf(yy);
                    } else if (act == 2) {
                        float bb = jb.bias ? jb.bias[nn] : 0.f;
                        yy = 1.f / (1.f + expf(-(yy + bb)));
                    } else if (act == 3) {
                        float tt = g_w0[nn] + yy + jb.bias[nn];
                        float nt = -tt;
                        float sp = (nt > 20.f) ? nt : log1pf(expf(nt));
                        yy = expf(-expf(-sp - 0.5f));
                    }
                    jb.C[(size_t)m * N + nn] = yy;
                }
            }
        }
    }
}

// ---------------- kk normalize / a_in / b_in / k update --------------------
__global__ void kk_kernel(const float* __restrict__ kkc,
                          const float* __restrict__ kac)
{
    int gid  = blockIdx.x * blockDim.x + threadIdx.x;
    int lane = gid & 31;
    int grp  = gid >> 5;
    if (grp >= BT_*H_) return;
    int bt = grp / H_, h = grp % H_;
    int base = bt * C_ + h * D_;
    int c0   = h * D_;

    float k0v = g_k[base + lane],      k1v = g_k[base + 32 + lane];
    float a0  = g_a[base + lane],      a1  = g_a[base + 32 + lane];
    float kk0 = k0v * kkc[c0 + lane],  kk1 = k1v * kkc[c0 + 32 + lane];

    float ss = kk0*kk0 + kk1*kk1;
#pragma unroll
    for (int o = 16; o; o >>= 1) ss += __shfl_xor_sync(0xffffffffu, ss, o);
    float inv = 1.f / fmaxf(sqrtf(ss), 1e-12f);
    kk0 *= inv; kk1 *= inv;

    g_ain[base + lane]      = -kk0;
    g_ain[base + 32 + lane] = -kk1;
    g_bin[base + lane]      = kk0 * a0;
    g_bin[base + 32 + lane] = kk1 * a1;
    g_k[base + lane]        = k0v * (1.f + (a0 - 1.f) * kac[c0 + lane]);
    g_k[base + 32 + lane]   = k1v * (1.f + (a1 - 1.f) * kac[c0 + 32 + lane]);
}

// ---------------- sequential RWKV-7 recurrence (v3: chunked, barrier-lite) --
// One block per (b,h), 512 threads. Thread owns S[row, cp*8 .. cp*8+7].
// RCHUNK timesteps staged per smem buffer; ONE __syncthreads per chunk.
// All per-step reductions are intra-warp shuffles.
#define RBUF_FLOATS (6*RCHUNK*64)          // 6144 per buffer
#define RSMEM_BYTES (2*RBUF_FLOATS*4)      // 49152

__global__ void __launch_bounds__(512, 1) rec_kernel()
{
    int bh = blockIdx.x;
    int b = bh >> 4, h = bh & 15;
    size_t base = (size_t)b * T_ * C_ + h * D_;

    extern __shared__ float rsm[];   // [2][6][RCHUNK][64]

    int tid = threadIdx.x;
    int row = tid >> 3;          // 0..63
    int cp  = tid & 7;           // 0..7
    int c0  = cp * 8;

    // loader mapping: flat f = tid + it*512 -> (vec, step, quad)
    const float* srcs[6] = { g_r, g_decay, g_k, g_v, g_ain, g_bin };
    const float* gp[3];
    uint32_t sp_[3];
#pragma unroll
    for (int it = 0; it < 3; it++) {
        int f  = tid + it * 512;
        int q  = f & 15;
        int st = (f >> 4) & (RCHUNK-1);
        int vc = f >> 8;
        gp[it]  = srcs[vc] + base + (size_t)st * C_ + q * 4;
        sp_[it] = (uint32_t)((vc * RCHUNK + st) * 64 + q * 4);
    }

    unsigned long long S[4] = {0ull, 0ull, 0ull, 0ull};

    float4 pf[3];
#pragma unroll
    for (int it = 0; it < 3; it++) pf[it] = *(const float4*)gp[it];

    const int NCH = T_ / RCHUNK;
    for (int ch = 0; ch < NCH; ch++) {
        float* buf = rsm + (ch & 1) * RBUF_FLOATS;
#pragma unroll
        for (int it = 0; it < 3; it++)
            *(float4*)(buf + sp_[it]) = pf[it];
        __syncthreads();
        if (ch + 1 < NCH) {
            size_t adv = (size_t)(ch + 1) * RCHUNK * C_;
#pragma unroll
            for (int it = 0; it < 3; it++)
                pf[it] = *(const float4*)(gp[it] + adv);
        }

        size_t obase = base + (size_t)ch * RCHUNK * C_ + row;
#pragma unroll 4
        for (int s = 0; s < RCHUNK; s++) {
            const float* rv = buf + (0*RCHUNK + s) * 64;
            const float* wv = buf + (1*RCHUNK + s) * 64;
            const float* kv = buf + (2*RCHUNK + s) * 64;
            const float* vv = buf + (3*RCHUNK + s) * 64;
            const float* av = buf + (4*RCHUNK + s) * 64;
            const float* bv = buf + (5*RCHUNK + s) * 64;

            ulonglong2 aA = *(const ulonglong2*)(av + c0);
            ulonglong2 aB = *(const ulonglong2*)(av + c0 + 4);
            unsigned long long sacc = f32x2_fma(S[0], aA.x, 0ull);
            sacc = f32x2_fma(S[1], aA.y, sacc);
            sacc = f32x2_fma(S[2], aB.x, sacc);
            sacc = f32x2_fma(S[3], aB.y, sacc);
            float2 spp = f32x2_unpack(sacc);
            float sa = spp.x + spp.y;
            sa += __shfl_xor_sync(0xffffffffu, sa, 1);
            sa += __shfl_xor_sync(0xffffffffu, sa, 2);
            sa += __shfl_xor_sync(0xffffffffu, sa, 4);

            float vj = vv[row];
            ulonglong2 wA = *(const ulonglong2*)(wv + c0);
            ulonglong2 wB = *(const ulonglong2*)(wv + c0 + 4);
            ulonglong2 bA = *(const ulonglong2*)(bv + c0);
            ulonglong2 bB = *(const ulonglong2*)(bv + c0 + 4);
            ulonglong2 kA = *(const ulonglong2*)(kv + c0);
            ulonglong2 kB = *(const ulonglong2*)(kv + c0 + 4);
            ulonglong2 rA = *(const ulonglong2*)(rv + c0);
            ulonglong2 rB = *(const ulonglong2*)(rv + c0 + 4);

            unsigned long long sa2 = f32x2_pack(sa, sa);
            unsigned long long v2  = f32x2_pack(vj, vj);

            S[0] = f32x2_fma(v2, kA.x, f32x2_fma(sa2, bA.x, f32x2_fma(S[0], wA.x, 0ull)));
            S[1] = f32x2_fma(v2, kA.y, f32x2_fma(sa2, bA.y, f32x2_fma(S[1], wA.y, 0ull)));
            S[2] = f32x2_fma(v2, kB.x, f32x2_fma(sa2, bB.x, f32x2_fma(S[2], wB.x, 0ull)));
            S[3] = f32x2_fma(v2, kB.y, f32x2_fma(sa2, bB.y, f32x2_fma(S[3], wB.y, 0ull)));

            unsigned long long oacc = f32x2_fma(S[0], rA.x, 0ull);
            oacc = f32x2_fma(S[1], rA.y, oacc);
            oacc = f32x2_fma(S[2], rB.x, oacc);
            oacc = f32x2_fma(S[3], rB.y, oacc);
            float2 op = f32x2_unpack(oacc);
            float o = op.x + op.y;
            o += __shfl_xor_sync(0xffffffffu, o, 1);
            o += __shfl_xor_sync(0xffffffffu, o, 2);
            o += __shfl_xor_sync(0xffffffffu, o, 4);
            if (cp == 0) g_o[obase + (size_t)s * C_] = o;
        }
        // next chunk writes the other buffer; its last readers finished
        // before the sync above (see round-7 analysis) -> one sync/chunk.
    }
}

// ---------------- GroupNorm + bonus + gate (emits bf16 hi/lo) --------------
__global__ void post_kernel(const float* __restrict__ rk,
                            const float* __restrict__ gnw,
                            const float* __restrict__ gnb)
{
    int gid  = blockIdx.x * blockDim.x + threadIdx.x;
    int lane = gid & 31;
    int grp  = gid >> 5;
    if (grp >= BT_*H_) return;
    int bt = grp / H_, h = grp % H_;
    int base = bt * C_ + h * D_;
    int c0   = h * D_;

    float o0 = g_o[base + lane], o1 = g_o[base + 32 + lane];
    float su = o0 + o1;
    float sq = o0*o0 + o1*o1;
    float r0 = g_r[base + lane], r1 = g_r[base + 32 + lane];
    float k0 = g_k[base + lane], k1 = g_k[base + 32 + lane];
    float bsum = r0*k0*rk[c0 + lane] + r1*k1*rk[c0 + 32 + lane];
#pragma unroll
    for (int o = 16; o; o >>= 1) {
        su   += __shfl_xor_sync(0xffffffffu, su,   o);
        sq   += __shfl_xor_sync(0xffffffffu, sq,   o);
        bsum += __shfl_xor_sync(0xffffffffu, bsum, o);
    }
    float mu  = su / 64.f;
    float var = sq / 64.f - mu * mu;
    float inv = rsqrtf(var + EPS_);

    float v0 = g_v[base + lane], v1 = g_v[base + 32 + lane];
    float on0 = (o0 - mu) * inv * gnw[c0 + lane]      + gnb[c0 + lane];
    float on1 = (o1 - mu) * inv * gnw[c0 + 32 + lane] + gnb[c0 + 32 + lane];
    float p0 = (on0 + bsum * v0) * g_g[base + lane];
    float p1 = (on1 + bsum * v1) * g_g[base + 32 + lane];

    __nv_bfloat16 h0 = __float2bfloat16_rn(p0);
    __nv_bfloat16 h1 = __float2bfloat16_rn(p1);
    g_preh[base + lane]      = h0;
    g_preh[base + 32 + lane] = h1;
    g_prel[base + lane]      = __float2bfloat16_rn(p0 - __bfloat162float(h0));
    g_prel[base + 32 + lane] = __float2bfloat16_rn(p1 - __bfloat162float(h1));
}

// ---------------- host launcher ---------------------------------------------
extern "C" void kernel_launch(void* const* d_in, const int* in_sizes, int n_in,
                              void* d_out, int out_size)
{
    const float* x        = (const float*)d_in[0];
    const float* x_r      = (const float*)d_in[1];
    const float* x_w      = (const float*)d_in[2];
    const float* x_k      = (const float*)d_in[3];
    const float* x_v      = (const float*)d_in[4];
    const float* x_a      = (const float*)d_in[5];
    const float* x_g      = (const float*)d_in[6];
    const float* k_k      = (const float*)d_in[7];
    const float* k_a      = (const float*)d_in[8];
    const float* r_k      = (const float*)d_in[9];
    const float* Wr       = (const float*)d_in[10];
    const float* Wk       = (const float*)d_in[11];
    const float* Wv       = (const float*)d_in[12];
    const float* Wo       = (const float*)d_in[13];
    const float* wA       = (const float*)d_in[14];
    const float* wB       = (const float*)d_in[15];
    const float* wBias    = (const float*)d_in[16];
    const float* aA       = (const float*)d_in[17];
    const float* aB       = (const float*)d_in[18];
    const float* aBias    = (const float*)d_in[19];
    const float* gA       = (const float*)d_in[20];
    const float* gB       = (const float*)d_in[21];
    const float* gnw      = (const float*)d_in[22];
    const float* gnb      = (const float*)d_in[23];
    const float* w0_base  = (const float*)d_in[24];
    const float* w0_delta = (const float*)d_in[25];
    float* out = (float*)d_out;

    float *p_xw,*p_xa,*p_xg;
    float *p_r,*p_k,*p_v,*p_w1,*p_a1,*p_g1;
    float *p_dec,*p_a,*p_g;
    __nv_bfloat16 *p_xrh,*p_xrl,*p_xkh,*p_xkl,*p_xvh,*p_xvl,*p_preh,*p_prel;
    __nv_bfloat16 *p_wh,*p_wl;
    cudaGetSymbolAddress((void**)&p_xw, g_xw);
    cudaGetSymbolAddress((void**)&p_xa, g_xa);
    cudaGetSymbolAddress((void**)&p_xg, g_xg);
    cudaGetSymbolAddress((void**)&p_r,  g_r);
    cudaGetSymbolAddress((void**)&p_k,  g_k);
    cudaGetSymbolAddress((void**)&p_v,  g_v);
    cudaGetSymbolAddress((void**)&p_w1, g_w1);
    cudaGetSymbolAddress((void**)&p_a1, g_a1);
    cudaGetSymbolAddress((void**)&p_g1, g_g1);
    cudaGetSymbolAddress((void**)&p_dec,g_decay);
    cudaGetSymbolAddress((void**)&p_a,  g_a);
    cudaGetSymbolAddress((void**)&p_g,  g_g);
    cudaGetSymbolAddress((void**)&p_xrh, g_xrh);
    cudaGetSymbolAddress((void**)&p_xrl, g_xrl);
    cudaGetSymbolAddress((void**)&p_xkh, g_xkh);
    cudaGetSymbolAddress((void**)&p_xkl, g_xkl);
    cudaGetSymbolAddress((void**)&p_xvh, g_xvh);
    cudaGetSymbolAddress((void**)&p_xvl, g_xvl);
    cudaGetSymbolAddress((void**)&p_preh, g_preh);
    cudaGetSymbolAddress((void**)&p_prel, g_prel);
    cudaGetSymbolAddress((void**)&p_wh, g_wh);
    cudaGetSymbolAddress((void**)&p_wl, g_wl);

    cudaFuncSetAttribute(hgemm_kernel, cudaFuncAttributeMaxDynamicSharedMemorySize,
                         HSMEM_BYTES);
    cudaFuncSetAttribute(rec_kernel, cudaFuncAttributeMaxDynamicSharedMemorySize,
                         RSMEM_BYTES);

    // 0) weight fp32 -> bf16 hi/lo
    {
        WConvJobs wj;
        wj.src[0] = Wr; wj.src[1] = Wk; wj.src[2] = Wv; wj.src[3] = Wo;
        wconv_kernel<<<dim3(C_*C_/4/256, 4), 256>>>(wj);
    }

    // 1) token-shift mixes (+ bf16 hi/lo for xr/xk/xv)
    mix_kernel<<<(BT_*C_/4 + 255)/256, 256>>>(x, x_r, x_w, x_k, x_v, x_a, x_g);

    // 2) w0 scan
    w0_kernel<<<1, C_>>>(w0_base, w0_delta);

    // 3) big r/k/v projections (bf16-split HMMA)
    {
        HJobs hj;
        hj.j[0] = { p_xrh, p_xrl, p_wh + 0*C_*C_, p_wl + 0*C_*C_, p_r };
        hj.j[1] = { p_xkh, p_xkl, p_wh + 1*C_*C_, p_wl + 1*C_*C_, p_k };
        hj.j[2] = { p_xvh, p_xvl, p_wh + 2*C_*C_, p_wl + 2*C_*C_, p_v };
        hgemm_kernel<<<dim3(C_/128, BT_/128, 3), 256, HSMEM_BYTES>>>(hj);
    }

    // 4) LoRA stage 1 fused, M-tile 64 for block parallelism
    {
        Jobs3 jb;
        jb.j[0] = { p_xw, wA, p_w1, nullptr, RW_, C_, 1 };
        jb.j[1] = { p_xa, aA, p_a1, nullptr, RA_, C_, 0 };
        jb.j[2] = { p_xg, gA, p_g1, nullptr, RG_, C_, 2 };
        fgemm_kernel<64><<<dim3((RG_+127)/128, BT_/64, 3), 256>>>(jb);
    }

    // 5) LoRA stage 2 fused
    {
        Jobs3 jb;
        jb.j[0] = { p_w1, wB, p_dec, wBias,   C_, RW_, 3 };
        jb.j[1] = { p_a1, aB, p_a,   aBias,   C_, RA_, 2 };
        jb.j[2] = { p_g1, gB, p_g,   nullptr, C_, RG_, 0 };
        fgemm_kernel<128><<<dim3(C_/128, BT_/128, 3), 256>>>(jb);
    }

    // 6) kk normalize / a_in / b_in / k update
    kk_kernel<<<(BT_*H_*32 + 255)/256, 256>>>(k_k, k_a);

    // 7) sequential recurrence (chunked)
    rec_kernel<<<B_*H_, 512, RSMEM_BYTES>>>();

    // 8) GroupNorm + bonus + gate (-> bf16 hi/lo)
    post_kernel<<<(BT_*H_*32 + 255)/256, 256>>>(r_k, gnw, gnb);

    // 9) output projection (HMMA)
    {
        HJobs hj;
        hj.j[0] = { p_preh, p_prel, p_wh + 3*C_*C_, p_wl + 3*C_*C_, out };
        hj.j[1] = hj.j[0];
        hj.j[2] = hj.j[0];
        hgemm_kernel<<<dim3(C_/128, BT_/128, 1), 256, HSMEM_BYTES>>>(hj);
    }
}

// round 9
// speedup vs baseline: 2.6233x; 1.7179x over previous
#include <cuda_runtime.h>
#include <cuda_bf16.h>
#include <math.h>
#include <stdint.h>

#define B_ 2
#define T_ 2048
#define C_ 1024
#define H_ 16
#define D_ 64
#define BT_ (B_*T_)
#define RW_ 64
#define RA_ 64
#define RG_ 160
#define EPS_ 6.4e-4f   // D * 1e-5
#define RCHUNK 8       // recurrence timesteps per smem chunk
#define RROWS 16       // state rows per block (64/4)

// ---------------- packed f32x2 helpers --------------------------------------
__device__ __forceinline__ unsigned long long f32x2_fma(
    unsigned long long a, unsigned long long b, unsigned long long c) {
    unsigned long long d;
    asm("fma.rn.f32x2 %0, %1, %2, %3;" : "=l"(d) : "l"(a), "l"(b), "l"(c));
    return d;
}
__device__ __forceinline__ unsigned long long f32x2_pack(float lo, float hi) {
    unsigned long long d;
    asm("mov.b64 %0, {%1, %2};" : "=l"(d) : "f"(lo), "f"(hi));
    return d;
}
__device__ __forceinline__ float2 f32x2_unpack(unsigned long long v) {
    float lo, hi;
    asm("mov.b64 {%0, %1}, %2;" : "=f"(lo), "=f"(hi) : "l"(v));
    return make_float2(lo, hi);
}
__device__ __forceinline__ uint32_t smem_u32(const void* p) {
    uint32_t a;
    asm("{ .reg .u64 t; cvta.to.shared.u64 t, %1; cvt.u32.u64 %0, t; }"
        : "=r"(a) : "l"(p));
    return a;
}

// ---------------- scratch (device globals: allocation-free) ----------------
__device__ float g_xw[BT_*C_];
__device__ float g_xa[BT_*C_];
__device__ float g_xg[BT_*C_];
__device__ __nv_bfloat16 g_xrh[BT_*C_], g_xrl[BT_*C_];
__device__ __nv_bfloat16 g_xkh[BT_*C_], g_xkl[BT_*C_];
__device__ __nv_bfloat16 g_xvh[BT_*C_], g_xvl[BT_*C_];
__device__ __nv_bfloat16 g_preh[BT_*C_], g_prel[BT_*C_];
__device__ __nv_bfloat16 g_wh[4][C_*C_], g_wl[4][C_*C_];   // Wr,Wk,Wv,Wo hi/lo
__device__ float g_r [BT_*C_];
__device__ float g_k [BT_*C_];
__device__ float g_v [BT_*C_];
__device__ float g_w1[BT_*RW_];
__device__ float g_a1[BT_*RA_];
__device__ float g_g1[BT_*RG_];
__device__ float g_decay[BT_*C_];
__device__ float g_a [BT_*C_];
__device__ float g_g [BT_*C_];
__device__ float g_ain[BT_*C_];
__device__ float g_bin[BT_*C_];
__device__ float g_o [BT_*C_];
__device__ float g_w0[C_];

// ---------------- fp32 -> bf16 hi/lo split helper ---------------------------
__device__ __forceinline__ void split4(float4 m, uint2& hi, uint2& lo) {
    __nv_bfloat16 h0 = __float2bfloat16_rn(m.x);
    __nv_bfloat16 h1 = __float2bfloat16_rn(m.y);
    __nv_bfloat16 h2 = __float2bfloat16_rn(m.z);
    __nv_bfloat16 h3 = __float2bfloat16_rn(m.w);
    __nv_bfloat16 l0 = __float2bfloat16_rn(m.x - __bfloat162float(h0));
    __nv_bfloat16 l1 = __float2bfloat16_rn(m.y - __bfloat162float(h1));
    __nv_bfloat16 l2 = __float2bfloat16_rn(m.z - __bfloat162float(h2));
    __nv_bfloat16 l3 = __float2bfloat16_rn(m.w - __bfloat162float(h3));
    __nv_bfloat162 ph0 = __halves2bfloat162(h0, h1);
    __nv_bfloat162 ph1 = __halves2bfloat162(h2, h3);
    __nv_bfloat162 pl0 = __halves2bfloat162(l0, l1);
    __nv_bfloat162 pl1 = __halves2bfloat162(l2, l3);
    hi.x = *reinterpret_cast<uint32_t*>(&ph0);
    hi.y = *reinterpret_cast<uint32_t*>(&ph1);
    lo.x = *reinterpret_cast<uint32_t*>(&pl0);
    lo.y = *reinterpret_cast<uint32_t*>(&pl1);
}

// ---------------- weight conversion: fp32 -> bf16 hi/lo --------------------
struct WConvJobs { const float* src[4]; };
__global__ void wconv_kernel(WConvJobs jobs)
{
    int w = blockIdx.y;
    int i = (blockIdx.x * blockDim.x + threadIdx.x) * 4;
    if (i >= C_*C_) return;
    float4 v = *(const float4*)(jobs.src[w] + i);
    uint2 hi, lo;
    split4(v, hi, lo);
    *(uint2*)(&g_wh[w][i]) = hi;
    *(uint2*)(&g_wl[w][i]) = lo;
}

// ---------------- token-shift mixing ----------------------------------------
__global__ void mix_kernel(const float* __restrict__ x,
    const float* __restrict__ cr, const float* __restrict__ cw,
    const float* __restrict__ ck, const float* __restrict__ cv,
    const float* __restrict__ ca, const float* __restrict__ cg)
{
    int i = blockIdx.x * blockDim.x + threadIdx.x;
    if (i >= BT_*C_/4) return;
    int idx = i * 4;
    int c  = idx & (C_-1);
    int bt = idx >> 10;
    int t  = bt & (T_-1);
    float4 xv = *(const float4*)(x + idx);
    float4 xs = make_float4(0.f,0.f,0.f,0.f);
    if (t) xs = *(const float4*)(x + idx - C_);
    float4 d = make_float4(xs.x-xv.x, xs.y-xv.y, xs.z-xv.z, xs.w-xv.w);
#define MIXV(cf, o) { float4 cc = *(const float4*)((cf)+c); \
    o = make_float4(xv.x + d.x*cc.x, xv.y + d.y*cc.y, \
                    xv.z + d.z*cc.z, xv.w + d.w*cc.w); }
    float4 m;
    uint2 hi, lo;
    MIXV(cr, m) split4(m, hi, lo);
    *(uint2*)(g_xrh + idx) = hi; *(uint2*)(g_xrl + idx) = lo;
    MIXV(ck, m) split4(m, hi, lo);
    *(uint2*)(g_xkh + idx) = hi; *(uint2*)(g_xkl + idx) = lo;
    MIXV(cv, m) split4(m, hi, lo);
    *(uint2*)(g_xvh + idx) = hi; *(uint2*)(g_xvl + idx) = lo;
    MIXV(cw, m) *(float4*)(g_xw + idx) = m;
    MIXV(ca, m) *(float4*)(g_xa + idx) = m;
    MIXV(cg, m) *(float4*)(g_xg + idx) = m;
#undef MIXV
}

// ---------------- w0 = base + cumsum(softplus(delta)) ----------------------
__global__ void w0_kernel(const float* __restrict__ base,
                          const float* __restrict__ delta)
{
    __shared__ float s[C_];
    int tid = threadIdx.x;
    float v = 0.f;
    if (tid > 0) {
        float d = delta[tid-1];
        v = (d > 20.f) ? d : log1pf(expf(d));
    }
    s[tid] = v;
    __syncthreads();
    for (int off = 1; off < C_; off <<= 1) {
        float t = (tid >= off) ? s[tid-off] : 0.f;
        __syncthreads();
        s[tid] += t;
        __syncthreads();
    }
    g_w0[tid] = base[0] + s[tid];
}

// ================ HMMA bf16-split GEMM (base-PTX mma.sync) ==================
struct HJob { const __nv_bfloat16 *Ah, *Al, *Bh, *Bl; float* C; };
struct HJobs { HJob j[3]; };

#define LDK 40                         // 32 + 8 pad (80B row stride)
#define HTILE (128*LDK)
#define HSMEM_BYTES (2*4*HTILE*2)      // 81920

__device__ __forceinline__ void ldm_x4(uint32_t addr, uint32_t r[4]) {
    asm volatile("ldmatrix.sync.aligned.m8n8.x4.shared.b16 {%0,%1,%2,%3}, [%4];"
        : "=r"(r[0]), "=r"(r[1]), "=r"(r[2]), "=r"(r[3]) : "r"(addr));
}
__device__ __forceinline__ void ldm_x2(uint32_t addr, uint32_t r[2]) {
    asm volatile("ldmatrix.sync.aligned.m8n8.x2.shared.b16 {%0,%1}, [%2];"
        : "=r"(r[0]), "=r"(r[1]) : "r"(addr));
}
__device__ __forceinline__ void mma_bf16(float* d, const uint32_t* a,
                                         const uint32_t* b) {
    asm volatile("mma.sync.aligned.m16n8k16.row.col.f32.bf16.bf16.f32 "
        "{%0,%1,%2,%3}, {%4,%5,%6,%7}, {%8,%9}, {%0,%1,%2,%3};"
        : "+f"(d[0]), "+f"(d[1]), "+f"(d[2]), "+f"(d[3])
        : "r"(a[0]), "r"(a[1]), "r"(a[2]), "r"(a[3]), "r"(b[0]), "r"(b[1]));
}

__global__ void __launch_bounds__(256, 1) hgemm_kernel(HJobs jobs)
{
    HJob jb = jobs.j[blockIdx.z];
    const int m0 = blockIdx.y * 128;
    const int n0 = blockIdx.x * 128;

    extern __shared__ __nv_bfloat16 sm[];

    int tid  = threadIdx.x;
    int wid  = tid >> 5;
    int lane = tid & 31;
    int wm = (wid & 1) * 64;
    int wn = (wid >> 1) * 32;

    int lrow = tid >> 1, lseg = tid & 1;
    const __nv_bfloat16* gsrc[4] = {
        jb.Ah + (size_t)(m0 + lrow) * C_ + lseg * 16,
        jb.Al + (size_t)(m0 + lrow) * C_ + lseg * 16,
        jb.Bh + (size_t)(n0 + lrow) * C_ + lseg * 16,
        jb.Bl + (size_t)(n0 + lrow) * C_ + lseg * 16 };
    uint32_t sdst = lrow * LDK + lseg * 16;

    float acc[4][4][4];
#pragma unroll
    for (int i = 0; i < 4; i++)
#pragma unroll
        for (int j = 0; j < 4; j++)
#pragma unroll
            for (int q = 0; q < 4; q++) acc[i][j][q] = 0.f;

    uint32_t rowA = (lane & 15) * (LDK*2);
    uint32_t colA = (lane >> 4) * 16;
    uint32_t rowB = (lane & 7)  * (LDK*2);
    uint32_t colB = ((lane >> 3) & 1) * 16;

    uint4 pf[4][2];
#pragma unroll
    for (int tl = 0; tl < 4; tl++) {
        pf[tl][0] = *(const uint4*)(gsrc[tl]);
        pf[tl][1] = *(const uint4*)(gsrc[tl] + 8);
    }

    for (int c = 0; c < 32; c++) {
        __nv_bfloat16* buf = sm + (size_t)(c & 1) * 4 * HTILE;
#pragma unroll
        for (int tl = 0; tl < 4; tl++) {
            *(uint4*)(buf + tl*HTILE + sdst)     = pf[tl][0];
            *(uint4*)(buf + tl*HTILE + sdst + 8) = pf[tl][1];
        }
        __syncthreads();
        if (c + 1 < 32) {
#pragma unroll
            for (int tl = 0; tl < 4; tl++) {
                pf[tl][0] = *(const uint4*)(gsrc[tl] + (c+1)*32);
                pf[tl][1] = *(const uint4*)(gsrc[tl] + (c+1)*32 + 8);
            }
        }
        uint32_t sb = smem_u32(buf);
#pragma unroll
        for (int p = 0; p < 3; p++) {
            uint32_t abase = sb + ((p == 2) ? 1 : 0) * (HTILE*2);
            uint32_t bbase = sb + ((p == 1) ? 3 : 2) * (HTILE*2);
#pragma unroll
            for (int ks = 0; ks < 2; ks++) {
                uint32_t af[4][4], bfr[4][2];
#pragma unroll
                for (int mt = 0; mt < 4; mt++)
                    ldm_x4(abase + (wm + mt*16) * (LDK*2) + rowA + ks*32 + colA,
                           af[mt]);
#pragma unroll
                for (int nt = 0; nt < 4; nt++)
                    ldm_x2(bbase + (wn + nt*8) * (LDK*2) + rowB + ks*32 + colB,
                           bfr[nt]);
#pragma unroll
                for (int mt = 0; mt < 4; mt++)
#pragma unroll
                    for (int nt = 0; nt < 4; nt++)
                        mma_bf16(acc[mt][nt], af[mt], bfr[nt]);
            }
        }
    }

    int g = lane >> 2, tg = lane & 3;
#pragma unroll
    for (int mt = 0; mt < 4; mt++) {
#pragma unroll
        for (int nt = 0; nt < 4; nt++) {
            float* p0 = jb.C + (size_t)(m0 + wm + mt*16 + g) * C_
                             + n0 + wn + nt*8 + 2*tg;
            *(float2*)p0            = make_float2(acc[mt][nt][0], acc[mt][nt][1]);
            *(float2*)(p0 + 8*C_)   = make_float2(acc[mt][nt][2], acc[mt][nt][3]);
        }
    }
}

// ---------------- fused f32x2 SGEMM (LoRA path), templated M-tile -----------
struct GemmJob { const float* A; const float* Bm; float* C;
                 const float* bias; int N; int K; int act; };
struct Jobs3 { GemmJob j[3]; };

template<int MT>
__global__ void __launch_bounds__(256)
fgemm_kernel(Jobs3 jobs)
{
    GemmJob jb = jobs.j[blockIdx.z];
    const int N = jb.N, K = jb.K;
    const int m0 = blockIdx.y * MT;
    const int n0 = blockIdx.x * 128;
    if (n0 >= N) return;

    constexpr int MROWS = MT/16;
    __shared__ alignas(16) float As[8][MT+4];
    __shared__ alignas(16) float Bs[8][132];

    int tid = threadIdx.x;
    int tx = tid & 15;
    int ty = tid >> 4;

    int blr = tid >> 1, blq = (tid & 1) * 4;
    int alr, alq;
    if (MT == 128) { alr = tid >> 1; alq = (tid & 1) * 4; }
    else           { alr = tid & 63; alq = ((tid >> 6) & 1) * 4; }

    const float* Ap = jb.A  + (size_t)(m0 + alr) * K + alq;
    const float* Bp = jb.Bm + (size_t)(n0 + blr) * K + blq;
    bool bok = (n0 + blr) < N;

    unsigned long long acc[MROWS][4];
#pragma unroll
    for (int i = 0; i < MROWS; i++)
#pragma unroll
        for (int j = 0; j < 4; j++) acc[i][j] = 0ull;

    float4 av = *(const float4*)Ap;
    float4 bv = make_float4(0.f,0.f,0.f,0.f);
    if (bok) bv = *(const float4*)Bp;

    for (int k0 = 0; k0 < K; k0 += 8) {
        __syncthreads();
        As[alq+0][alr] = av.x; As[alq+1][alr] = av.y;
        As[alq+2][alr] = av.z; As[alq+3][alr] = av.w;
        Bs[blq+0][blr] = bv.x; Bs[blq+1][blr] = bv.y;
        Bs[blq+2][blr] = bv.z; Bs[blq+3][blr] = bv.w;
        __syncthreads();
        if (k0 + 8 < K) {
            av = *(const float4*)(Ap + k0 + 8);
            if (bok) bv = *(const float4*)(Bp + k0 + 8);
        }
#pragma unroll
        for (int kk = 0; kk < 8; kk++) {
            float a_[MROWS];
#pragma unroll
            for (int i = 0; i < MROWS; i += 4)
                *(float4*)&a_[i] = *(const float4*)&As[kk][ty*MROWS + i];
            ulonglong2 b0 = *(const ulonglong2*)&Bs[kk][tx*8];
            ulonglong2 b1 = *(const ulonglong2*)&Bs[kk][tx*8+4];
#pragma unroll
            for (int i = 0; i < MROWS; i++) {
                unsigned long long a2 = f32x2_pack(a_[i], a_[i]);
                acc[i][0] = f32x2_fma(a2, b0.x, acc[i][0]);
                acc[i][1] = f32x2_fma(a2, b0.y, acc[i][1]);
                acc[i][2] = f32x2_fma(a2, b1.x, acc[i][2]);
                acc[i][3] = f32x2_fma(a2, b1.y, acc[i][3]);
            }
        }
    }

    const int act = jb.act;
#pragma unroll
    for (int i = 0; i < MROWS; i++) {
        int m = m0 + ty*MROWS + i;
#pragma unroll
        for (int jq = 0; jq < 4; jq++) {
            float2 y = f32x2_unpack(acc[i][jq]);
            float ys[2] = { y.x, y.y };
            int nb = n0 + tx*8 + jq*2;
#pragma unroll
            for (int s = 0; s < 2; s++) {
                int nn = nb + s;
                if (nn < N) {
                    float yy = ys[s];
                    if (act == 1) {
                        yy = tanhf(yy);
                    } else if (act == 2) {
                        float bb = jb.bias ? jb.bias[nn] : 0.f;
                        yy = 1.f / (1.f + expf(-(yy + bb)));
                    } else if (act == 3) {
                        float tt = g_w0[nn] + yy + jb.bias[nn];
                        float nt = -tt;
                        float sp = (nt > 20.f) ? nt : log1pf(expf(nt));
                        yy = expf(-expf(-sp - 0.5f));
                    }
                    jb.C[(size_t)m * N + nn] = yy;
                }
            }
        }
    }
}

// ---------------- kk normalize / a_in / b_in / k update --------------------
__global__ void kk_kernel(const float* __restrict__ kkc,
                          const float* __restrict__ kac)
{
    int gid  = blockIdx.x * blockDim.x + threadIdx.x;
    int lane = gid & 31;
    int grp  = gid >> 5;
    if (grp >= BT_*H_) return;
    int bt = grp / H_, h = grp % H_;
    int base = bt * C_ + h * D_;
    int c0   = h * D_;

    float k0v = g_k[base + lane],      k1v = g_k[base + 32 + lane];
    float a0  = g_a[base + lane],      a1  = g_a[base + 32 + lane];
    float kk0 = k0v * kkc[c0 + lane],  kk1 = k1v * kkc[c0 + 32 + lane];

    float ss = kk0*kk0 + kk1*kk1;
#pragma unroll
    for (int o = 16; o; o >>= 1) ss += __shfl_xor_sync(0xffffffffu, ss, o);
    float inv = 1.f / fmaxf(sqrtf(ss), 1e-12f);
    kk0 *= inv; kk1 *= inv;

    g_ain[base + lane]      = -kk0;
    g_ain[base + 32 + lane] = -kk1;
    g_bin[base + lane]      = kk0 * a0;
    g_bin[base + 32 + lane] = kk1 * a1;
    g_k[base + lane]        = k0v * (1.f + (a0 - 1.f) * kac[c0 + lane]);
    g_k[base + 32 + lane]   = k1v * (1.f + (a1 - 1.f) * kac[c0 + 32 + lane]);
}

// ---------------- RWKV-7 recurrence (v4: row-split, 128 blocks) -------------
// Rows of S are independent: block = (b, h, row-group of 16 rows).
// 128 blocks x 128 threads; thread owns S[row, cp*8..cp*8+7].
// Per-SM MIO traffic is 1/4 of v3; 128 SMs active instead of 32.
__global__ void __launch_bounds__(128, 1) rec_kernel()
{
    int blk = blockIdx.x;            // 0..127
    int bh  = blk >> 2;              // 0..31
    int rb  = blk & 3;               // row group
    int b = bh >> 4, h = bh & 15;
    size_t base = (size_t)b * T_ * C_ + h * D_;

    __shared__ alignas(16) float rsm[2][6][RCHUNK][64];

    int tid = threadIdx.x;           // 0..127
    int row = rb * RROWS + (tid >> 3);   // global row 0..63
    int cp  = tid & 7;
    int c0  = cp * 8;

    // loaders: 6 vecs x RCHUNK steps x 16 quads = 768 float4 slots / 128 thr
    const float* srcs[6] = { g_r, g_decay, g_k, g_v, g_ain, g_bin };
    const float* gp[6];
    uint32_t sp_[6];
#pragma unroll
    for (int it = 0; it < 6; it++) {
        int f  = tid + it * 128;     // 0..767
        int q  = f & 15;
        int st = (f >> 4) & (RCHUNK-1);
        int vc = f >> 7;             // 0..5
        gp[it]  = srcs[vc] + base + (size_t)st * C_ + q * 4;
        sp_[it] = (uint32_t)((vc * RCHUNK + st) * 64 + q * 4);
    }

    unsigned long long S[4] = {0ull, 0ull, 0ull, 0ull};

    float4 pf[6];
#pragma unroll
    for (int it = 0; it < 6; it++) pf[it] = *(const float4*)gp[it];

    float* smbase = &rsm[0][0][0][0];
    const int NCH = T_ / RCHUNK;
    for (int ch = 0; ch < NCH; ch++) {
        float* buf = smbase + (ch & 1) * (6*RCHUNK*64);
#pragma unroll
        for (int it = 0; it < 6; it++)
            *(float4*)(buf + sp_[it]) = pf[it];
        __syncthreads();
        if (ch + 1 < NCH) {
            size_t adv = (size_t)(ch + 1) * RCHUNK * C_;
#pragma unroll
            for (int it = 0; it < 6; it++)
                pf[it] = *(const float4*)(gp[it] + adv);
        }

        size_t obase = base + (size_t)ch * RCHUNK * C_ + row;
#pragma unroll 2
        for (int s = 0; s < RCHUNK; s++) {
            const float* rv = buf + (0*RCHUNK + s) * 64;
            const float* wv = buf + (1*RCHUNK + s) * 64;
            const float* kv = buf + (2*RCHUNK + s) * 64;
            const float* vv = buf + (3*RCHUNK + s) * 64;
            const float* av = buf + (4*RCHUNK + s) * 64;
            const float* bv = buf + (5*RCHUNK + s) * 64;

            ulonglong2 aA = *(const ulonglong2*)(av + c0);
            ulonglong2 aB = *(const ulonglong2*)(av + c0 + 4);
            unsigned long long sacc = f32x2_fma(S[0], aA.x, 0ull);
            sacc = f32x2_fma(S[1], aA.y, sacc);
            sacc = f32x2_fma(S[2], aB.x, sacc);
            sacc = f32x2_fma(S[3], aB.y, sacc);
            float2 spp = f32x2_unpack(sacc);
            float sa = spp.x + spp.y;
            sa += __shfl_xor_sync(0xffffffffu, sa, 1);
            sa += __shfl_xor_sync(0xffffffffu, sa, 2);
            sa += __shfl_xor_sync(0xffffffffu, sa, 4);

            float vj = vv[row];
            ulonglong2 wA = *(const ulonglong2*)(wv + c0);
            ulonglong2 wB = *(const ulonglong2*)(wv + c0 + 4);
            ulonglong2 bA = *(const ulonglong2*)(bv + c0);
            ulonglong2 bB = *(const ulonglong2*)(bv + c0 + 4);
            ulonglong2 kA = *(const ulonglong2*)(kv + c0);
            ulonglong2 kB = *(const ulonglong2*)(kv + c0 + 4);
            ulonglong2 rA = *(const ulonglong2*)(rv + c0);
            ulonglong2 rB = *(const ulonglong2*)(rv + c0 + 4);

            unsigned long long sa2 = f32x2_pack(sa, sa);
            unsigned long long v2  = f32x2_pack(vj, vj);

            S[0] = f32x2_fma(v2, kA.x, f32x2_fma(sa2, bA.x, f32x2_fma(S[0], wA.x, 0ull)));
            S[1] = f32x2_fma(v2, kA.y, f32x2_fma(sa2, bA.y, f32x2_fma(S[1], wA.y, 0ull)));
            S[2] = f32x2_fma(v2, kB.x, f32x2_fma(sa2, bB.x, f32x2_fma(S[2], wB.x, 0ull)));
            S[3] = f32x2_fma(v2, kB.y, f32x2_fma(sa2, bB.y, f32x2_fma(S[3], wB.y, 0ull)));

            unsigned long long oacc = f32x2_fma(S[0], rA.x, 0ull);
            oacc = f32x2_fma(S[1], rA.y, oacc);
            oacc = f32x2_fma(S[2], rB.x, oacc);
            oacc = f32x2_fma(S[3], rB.y, oacc);
            float2 op = f32x2_unpack(oacc);
            float o = op.x + op.y;
            o += __shfl_xor_sync(0xffffffffu, o, 1);
            o += __shfl_xor_sync(0xffffffffu, o, 2);
            o += __shfl_xor_sync(0xffffffffu, o, 4);
            if (cp == 0) g_o[obase + (size_t)s * C_] = o;
        }
    }
}

// ---------------- GroupNorm + bonus + gate (emits bf16 hi/lo) --------------
__global__ void post_kernel(const float* __restrict__ rk,
                            const float* __restrict__ gnw,
                            const float* __restrict__ gnb)
{
    int gid  = blockIdx.x * blockDim.x + threadIdx.x;
    int lane = gid & 31;
    int grp  = gid >> 5;
    if (grp >= BT_*H_) return;
    int bt = grp / H_, h = grp % H_;
    int base = bt * C_ + h * D_;
    int c0   = h * D_;

    float o0 = g_o[base + lane], o1 = g_o[base + 32 + lane];
    float su = o0 + o1;
    float sq = o0*o0 + o1*o1;
    float r0 = g_r[base + lane], r1 = g_r[base + 32 + lane];
    float k0 = g_k[base + lane], k1 = g_k[base + 32 + lane];
    float bsum = r0*k0*rk[c0 + lane] + r1*k1*rk[c0 + 32 + lane];
#pragma unroll
    for (int o = 16; o; o >>= 1) {
        su   += __shfl_xor_sync(0xffffffffu, su,   o);
        sq   += __shfl_xor_sync(0xffffffffu, sq,   o);
        bsum += __shfl_xor_sync(0xffffffffu, bsum, o);
    }
    float mu  = su / 64.f;
    float var = sq / 64.f - mu * mu;
    float inv = rsqrtf(var + EPS_);

    float v0 = g_v[base + lane], v1 = g_v[base + 32 + lane];
    float on0 = (o0 - mu) * inv * gnw[c0 + lane]      + gnb[c0 + lane];
    float on1 = (o1 - mu) * inv * gnw[c0 + 32 + lane] + gnb[c0 + 32 + lane];
    float p0 = (on0 + bsum * v0) * g_g[base + lane];
    float p1 = (on1 + bsum * v1) * g_g[base + 32 + lane];

    __nv_bfloat16 h0 = __float2bfloat16_rn(p0);
    __nv_bfloat16 h1 = __float2bfloat16_rn(p1);
    g_preh[base + lane]      = h0;
    g_preh[base + 32 + lane] = h1;
    g_prel[base + lane]      = __float2bfloat16_rn(p0 - __bfloat162float(h0));
    g_prel[base + 32 + lane] = __float2bfloat16_rn(p1 - __bfloat162float(h1));
}

// ---------------- host launcher ---------------------------------------------
extern "C" void kernel_launch(void* const* d_in, const int* in_sizes, int n_in,
                              void* d_out, int out_size)
{
    const float* x        = (const float*)d_in[0];
    const float* x_r      = (const float*)d_in[1];
    const float* x_w      = (const float*)d_in[2];
    const float* x_k      = (const float*)d_in[3];
    const float* x_v      = (const float*)d_in[4];
    const float* x_a      = (const float*)d_in[5];
    const float* x_g      = (const float*)d_in[6];
    const float* k_k      = (const float*)d_in[7];
    const float* k_a      = (const float*)d_in[8];
    const float* r_k      = (const float*)d_in[9];
    const float* Wr       = (const float*)d_in[10];
    const float* Wk       = (const float*)d_in[11];
    const float* Wv       = (const float*)d_in[12];
    const float* Wo       = (const float*)d_in[13];
    const float* wA       = (const float*)d_in[14];
    const float* wB       = (const float*)d_in[15];
    const float* wBias    = (const float*)d_in[16];
    const float* aA       = (const float*)d_in[17];
    const float* aB       = (const float*)d_in[18];
    const float* aBias    = (const float*)d_in[19];
    const float* gA       = (const float*)d_in[20];
    const float* gB       = (const float*)d_in[21];
    const float* gnw      = (const float*)d_in[22];
    const float* gnb      = (const float*)d_in[23];
    const float* w0_base  = (const float*)d_in[24];
    const float* w0_delta = (const float*)d_in[25];
    float* out = (float*)d_out;

    float *p_xw,*p_xa,*p_xg;
    float *p_r,*p_k,*p_v,*p_w1,*p_a1,*p_g1;
    float *p_dec,*p_a,*p_g;
    __nv_bfloat16 *p_xrh,*p_xrl,*p_xkh,*p_xkl,*p_xvh,*p_xvl,*p_preh,*p_prel;
    __nv_bfloat16 *p_wh,*p_wl;
    cudaGetSymbolAddress((void**)&p_xw, g_xw);
    cudaGetSymbolAddress((void**)&p_xa, g_xa);
    cudaGetSymbolAddress((void**)&p_xg, g_xg);
    cudaGetSymbolAddress((void**)&p_r,  g_r);
    cudaGetSymbolAddress((void**)&p_k,  g_k);
    cudaGetSymbolAddress((void**)&p_v,  g_v);
    cudaGetSymbolAddress((void**)&p_w1, g_w1);
    cudaGetSymbolAddress((void**)&p_a1, g_a1);
    cudaGetSymbolAddress((void**)&p_g1, g_g1);
    cudaGetSymbolAddress((void**)&p_dec,g_decay);
    cudaGetSymbolAddress((void**)&p_a,  g_a);
    cudaGetSymbolAddress((void**)&p_g,  g_g);
    cudaGetSymbolAddress((void**)&p_xrh, g_xrh);
    cudaGetSymbolAddress((void**)&p_xrl, g_xrl);
    cudaGetSymbolAddress((void**)&p_xkh, g_xkh);
    cudaGetSymbolAddress((void**)&p_xkl, g_xkl);
    cudaGetSymbolAddress((void**)&p_xvh, g_xvh);
    cudaGetSymbolAddress((void**)&p_xvl, g_xvl);
    cudaGetSymbolAddress((void**)&p_preh, g_preh);
    cudaGetSymbolAddress((void**)&p_prel, g_prel);
    cudaGetSymbolAddress((void**)&p_wh, g_wh);
    cudaGetSymbolAddress((void**)&p_wl, g_wl);

    cudaFuncSetAttribute(hgemm_kernel, cudaFuncAttributeMaxDynamicSharedMemorySize,
                         HSMEM_BYTES);

    // 0) weight fp32 -> bf16 hi/lo
    {
        WConvJobs wj;
        wj.src[0] = Wr; wj.src[1] = Wk; wj.src[2] = Wv; wj.src[3] = Wo;
        wconv_kernel<<<dim3(C_*C_/4/256, 4), 256>>>(wj);
    }

    // 1) token-shift mixes (+ bf16 hi/lo for xr/xk/xv)
    mix_kernel<<<(BT_*C_/4 + 255)/256, 256>>>(x, x_r, x_w, x_k, x_v, x_a, x_g);

    // 2) w0 scan
    w0_kernel<<<1, C_>>>(w0_base, w0_delta);

    // 3) big r/k/v projections (bf16-split HMMA)
    {
        HJobs hj;
        hj.j[0] = { p_xrh, p_xrl, p_wh + 0*C_*C_, p_wl + 0*C_*C_, p_r };
        hj.j[1] = { p_xkh, p_xkl, p_wh + 1*C_*C_, p_wl + 1*C_*C_, p_k };
        hj.j[2] = { p_xvh, p_xvl, p_wh + 2*C_*C_, p_wl + 2*C_*C_, p_v };
        hgemm_kernel<<<dim3(C_/128, BT_/128, 3), 256, HSMEM_BYTES>>>(hj);
    }

    // 4) LoRA stage 1 fused, MT=64
    {
        Jobs3 jb;
        jb.j[0] = { p_xw, wA, p_w1, nullptr, RW_, C_, 1 };
        jb.j[1] = { p_xa, aA, p_a1, nullptr, RA_, C_, 0 };
        jb.j[2] = { p_xg, gA, p_g1, nullptr, RG_, C_, 2 };
        fgemm_kernel<64><<<dim3((RG_+127)/128, BT_/64, 3), 256>>>(jb);
    }

    // 5) LoRA stage 2 fused, MT=64
    {
        Jobs3 jb;
        jb.j[0] = { p_w1, wB, p_dec, wBias,   C_, RW_, 3 };
        jb.j[1] = { p_a1, aB, p_a,   aBias,   C_, RA_, 2 };
        jb.j[2] = { p_g1, gB, p_g,   nullptr, C_, RG_, 0 };
        fgemm_kernel<64><<<dim3(C_/128, BT_/64, 3), 256>>>(jb);
    }

    // 6) kk normalize / a_in / b_in / k update
    kk_kernel<<<(BT_*H_*32 + 255)/256, 256>>>(k_k, k_a);

    // 7) sequential recurrence (row-split: 128 blocks)
    rec_kernel<<<128, 128>>>();

    // 8) GroupNorm + bonus + gate (-> bf16 hi/lo)
    post_kernel<<<(BT_*H_*32 + 255)/256, 256>>>(r_k, gnw, gnb);

    // 9) output projection (HMMA)
    {
        HJobs hj;
        hj.j[0] = { p_preh, p_prel, p_wh + 3*C_*C_, p_wl + 3*C_*C_, out };
        hj.j[1] = hj.j[0];
        hj.j[2] = hj.j[0];
        hgemm_kernel<<<dim3(C_/128, BT_/128, 1), 256, HSMEM_BYTES>>>(hj);
    }
}

// round 10
// speedup vs baseline: 3.1972x; 1.2188x over previous
#include <cuda_runtime.h>
#include <cuda_bf16.h>
#include <math.h>
#include <stdint.h>

#define B_ 2
#define T_ 2048
#define C_ 1024
#define H_ 16
#define D_ 64
#define BT_ (B_*T_)
#define RW_ 64
#define RA_ 64
#define RG_ 160
#define EPS_ 6.4e-4f   // D * 1e-5
#define RCHUNK 8
#define RROWS 16

// ---------------- packed f32x2 helpers --------------------------------------
__device__ __forceinline__ unsigned long long f32x2_fma(
    unsigned long long a, unsigned long long b, unsigned long long c) {
    unsigned long long d;
    asm("fma.rn.f32x2 %0, %1, %2, %3;" : "=l"(d) : "l"(a), "l"(b), "l"(c));
    return d;
}
__device__ __forceinline__ unsigned long long f32x2_pack(float lo, float hi) {
    unsigned long long d;
    asm("mov.b64 %0, {%1, %2};" : "=l"(d) : "f"(lo), "f"(hi));
    return d;
}
__device__ __forceinline__ float2 f32x2_unpack(unsigned long long v) {
    float lo, hi;
    asm("mov.b64 {%0, %1}, %2;" : "=f"(lo), "=f"(hi) : "l"(v));
    return make_float2(lo, hi);
}
__device__ __forceinline__ uint32_t smem_u32(const void* p) {
    uint32_t a;
    asm("{ .reg .u64 t; cvta.to.shared.u64 t, %1; cvt.u32.u64 %0, t; }"
        : "=r"(a) : "l"(p));
    return a;
}

// ---------------- scratch (device globals: allocation-free) ----------------
__device__ __nv_bfloat16 g_xrh[BT_*C_], g_xrl[BT_*C_];
__device__ __nv_bfloat16 g_xkh[BT_*C_], g_xkl[BT_*C_];
__device__ __nv_bfloat16 g_xvh[BT_*C_], g_xvl[BT_*C_];
__device__ __nv_bfloat16 g_xwh[BT_*C_], g_xwl[BT_*C_];
__device__ __nv_bfloat16 g_xah[BT_*C_], g_xal[BT_*C_];
__device__ __nv_bfloat16 g_xgh[BT_*C_], g_xgl[BT_*C_];
__device__ __nv_bfloat16 g_preh[BT_*C_], g_prel[BT_*C_];
__device__ __nv_bfloat16 g_wh[4][C_*C_], g_wl[4][C_*C_];   // Wr,Wk,Wv,Wo
__device__ __nv_bfloat16 g_wAh[RW_*C_], g_wAl[RW_*C_];
__device__ __nv_bfloat16 g_aAh[RA_*C_], g_aAl[RA_*C_];
__device__ __nv_bfloat16 g_gAh[RG_*C_], g_gAl[RG_*C_];
__device__ __nv_bfloat16 g_wBh[C_*RW_], g_wBl[C_*RW_];
__device__ __nv_bfloat16 g_aBh[C_*RA_], g_aBl[C_*RA_];
__device__ __nv_bfloat16 g_gBh[C_*RG_], g_gBl[C_*RG_];
__device__ __nv_bfloat16 g_w1h[BT_*RW_], g_w1l[BT_*RW_];
__device__ __nv_bfloat16 g_a1h[BT_*RA_], g_a1l[BT_*RA_];
__device__ __nv_bfloat16 g_g1h[BT_*RG_], g_g1l[BT_*RG_];
__device__ float g_r [BT_*C_];
__device__ float g_k [BT_*C_];
__device__ float g_v [BT_*C_];
__device__ float g_decay[BT_*C_];
__device__ float g_a [BT_*C_];
__device__ float g_g [BT_*C_];
__device__ float g_ain[BT_*C_];
__device__ float g_bin[BT_*C_];
__device__ float g_o [BT_*C_];
__device__ float g_w0[C_];

// ---------------- fp32 -> bf16 hi/lo split helpers --------------------------
__device__ __forceinline__ void split4(float4 m, uint2& hi, uint2& lo) {
    __nv_bfloat16 h0 = __float2bfloat16_rn(m.x);
    __nv_bfloat16 h1 = __float2bfloat16_rn(m.y);
    __nv_bfloat16 h2 = __float2bfloat16_rn(m.z);
    __nv_bfloat16 h3 = __float2bfloat16_rn(m.w);
    __nv_bfloat16 l0 = __float2bfloat16_rn(m.x - __bfloat162float(h0));
    __nv_bfloat16 l1 = __float2bfloat16_rn(m.y - __bfloat162float(h1));
    __nv_bfloat16 l2 = __float2bfloat16_rn(m.z - __bfloat162float(h2));
    __nv_bfloat16 l3 = __float2bfloat16_rn(m.w - __bfloat162float(h3));
    __nv_bfloat162 ph0 = __halves2bfloat162(h0, h1);
    __nv_bfloat162 ph1 = __halves2bfloat162(h2, h3);
    __nv_bfloat162 pl0 = __halves2bfloat162(l0, l1);
    __nv_bfloat162 pl1 = __halves2bfloat162(l2, l3);
    hi.x = *reinterpret_cast<uint32_t*>(&ph0);
    hi.y = *reinterpret_cast<uint32_t*>(&ph1);
    lo.x = *reinterpret_cast<uint32_t*>(&pl0);
    lo.y = *reinterpret_cast<uint32_t*>(&pl1);
}
__device__ __forceinline__ uint32_t pack_bf2(float a, float b, uint32_t& lov) {
    __nv_bfloat16 h0 = __float2bfloat16_rn(a), h1 = __float2bfloat16_rn(b);
    __nv_bfloat16 l0 = __float2bfloat16_rn(a - __bfloat162float(h0));
    __nv_bfloat16 l1 = __float2bfloat16_rn(b - __bfloat162float(h1));
    __nv_bfloat162 hh = __halves2bfloat162(h0, h1);
    __nv_bfloat162 ll = __halves2bfloat162(l0, l1);
    lov = *reinterpret_cast<uint32_t*>(&ll);
    return *reinterpret_cast<uint32_t*>(&hh);
}

// ---------------- weight conversion: fp32 -> bf16 hi/lo ---------------------
struct WcJob { const float* src; __nv_bfloat16 *h, *l; int n; };
struct WcJobs { WcJob j[10]; };
__global__ void wconv_kernel(WcJobs jobs)
{
    WcJob jb = jobs.j[blockIdx.y];
    int i = (blockIdx.x * blockDim.x + threadIdx.x) * 4;
    if (i >= jb.n) return;
    float4 v = *(const float4*)(jb.src + i);
    uint2 hi, lo;
    split4(v, hi, lo);
    *(uint2*)(jb.h + i) = hi;
    *(uint2*)(jb.l + i) = lo;
}

// ---------------- token-shift mixing: all 6 emitted as bf16 hi/lo -----------
__global__ void mix_kernel(const float* __restrict__ x,
    const float* __restrict__ cr, const float* __restrict__ cw,
    const float* __restrict__ ck, const float* __restrict__ cv,
    const float* __restrict__ ca, const float* __restrict__ cg)
{
    int i = blockIdx.x * blockDim.x + threadIdx.x;
    if (i >= BT_*C_/4) return;
    int idx = i * 4;
    int c  = idx & (C_-1);
    int bt = idx >> 10;
    int t  = bt & (T_-1);
    float4 xv = *(const float4*)(x + idx);
    float4 xs = make_float4(0.f,0.f,0.f,0.f);
    if (t) xs = *(const float4*)(x + idx - C_);
    float4 d = make_float4(xs.x-xv.x, xs.y-xv.y, xs.z-xv.z, xs.w-xv.w);
    float4 m; uint2 hi, lo;
#define MIXS(cf, ah, al) { float4 cc = *(const float4*)((cf)+c); \
    m = make_float4(xv.x + d.x*cc.x, xv.y + d.y*cc.y, \
                    xv.z + d.z*cc.z, xv.w + d.w*cc.w); \
    split4(m, hi, lo); \
    *(uint2*)((ah) + idx) = hi; *(uint2*)((al) + idx) = lo; }
    MIXS(cr, g_xrh, g_xrl)
    MIXS(ck, g_xkh, g_xkl)
    MIXS(cv, g_xvh, g_xvl)
    MIXS(cw, g_xwh, g_xwl)
    MIXS(ca, g_xah, g_xal)
    MIXS(cg, g_xgh, g_xgl)
#undef MIXS
}

// ---------------- w0 = base + cumsum(softplus(delta)) ----------------------
__global__ void w0_kernel(const float* __restrict__ base,
                          const float* __restrict__ delta)
{
    __shared__ float s[C_];
    int tid = threadIdx.x;
    float v = 0.f;
    if (tid > 0) {
        float d = delta[tid-1];
        v = (d > 20.f) ? d : log1pf(expf(d));
    }
    s[tid] = v;
    __syncthreads();
    for (int off = 1; off < C_; off <<= 1) {
        float t = (tid >= off) ? s[tid-off] : 0.f;
        __syncthreads();
        s[tid] += t;
        __syncthreads();
    }
    g_w0[tid] = base[0] + s[tid];
}

// ================ generic HMMA bf16-split GEMM ==============================
// C[M,N] = act(A[M,K]*(B[N,K])^T [+bias]); A,B as bf16 hi/lo pairs.
// acts: 0 none->f32 | 1 tanh->bf16split | 2 sigmoid->bf16split |
//       3 decay(w0+bias)->f32 | 5 sigmoid(+bias)->f32 | 6 none->bf16split
struct HJob { const __nv_bfloat16 *Ah, *Al, *Bh, *Bl;
              float* Cf; __nv_bfloat16 *Ch, *Cl;
              const float* bias; int N, K, act; };
struct HJobs { HJob j[3]; };

#define LDK 40
#define ASZ (128*LDK)

__device__ __forceinline__ void ldm_x4(uint32_t addr, uint32_t r[4]) {
    asm volatile("ldmatrix.sync.aligned.m8n8.x4.shared.b16 {%0,%1,%2,%3}, [%4];"
        : "=r"(r[0]), "=r"(r[1]), "=r"(r[2]), "=r"(r[3]) : "r"(addr));
}
__device__ __forceinline__ void ldm_x2(uint32_t addr, uint32_t r[2]) {
    asm volatile("ldmatrix.sync.aligned.m8n8.x2.shared.b16 {%0,%1}, [%2];"
        : "=r"(r[0]), "=r"(r[1]) : "r"(addr));
}
__device__ __forceinline__ void mma_bf16(float* d, const uint32_t* a,
                                         const uint32_t* b) {
    asm volatile("mma.sync.aligned.m16n8k16.row.col.f32.bf16.bf16.f32 "
        "{%0,%1,%2,%3}, {%4,%5,%6,%7}, {%8,%9}, {%0,%1,%2,%3};"
        : "+f"(d[0]), "+f"(d[1]), "+f"(d[2]), "+f"(d[3])
        : "r"(a[0]), "r"(a[1]), "r"(a[2]), "r"(a[3]), "r"(b[0]), "r"(b[1]));
}

__device__ __forceinline__ void emit2(const HJob& jb, int row, int col,
                                      float v0, float v1)
{
    size_t idx = (size_t)row * jb.N + col;
    int act = jb.act;
    if (act == 0) {
        *(float2*)(jb.Cf + idx) = make_float2(v0, v1);
    } else if (act == 3) {
        float t0 = g_w0[col]   + v0 + jb.bias[col];
        float t1 = g_w0[col+1] + v1 + jb.bias[col+1];
        float n0 = -t0, n1 = -t1;
        float s0 = (n0 > 20.f) ? n0 : log1pf(expf(n0));
        float s1 = (n1 > 20.f) ? n1 : log1pf(expf(n1));
        *(float2*)(jb.Cf + idx) =
            make_float2(expf(-expf(-s0 - 0.5f)), expf(-expf(-s1 - 0.5f)));
    } else if (act == 5) {
        float y0 = 1.f / (1.f + expf(-(v0 + jb.bias[col])));
        float y1 = 1.f / (1.f + expf(-(v1 + jb.bias[col+1])));
        *(float2*)(jb.Cf + idx) = make_float2(y0, y1);
    } else {
        if (act == 1) { v0 = tanhf(v0); v1 = tanhf(v1); }
        else if (act == 2) {
            v0 = 1.f / (1.f + expf(-v0));
            v1 = 1.f / (1.f + expf(-v1));
        }
        uint32_t lov;
        uint32_t hiv = pack_bf2(v0, v1, lov);
        *(uint32_t*)(jb.Ch + idx) = hiv;
        *(uint32_t*)(jb.Cl + idx) = lov;
    }
}

template<int NT>
__global__ void __launch_bounds__(256, 1) hg2_kernel(HJobs jobs)
{
    HJob jb = jobs.j[blockIdx.z];
    const int N = jb.N, K = jb.K;
    const int m0 = blockIdx.y * 128;
    const int n0 = blockIdx.x * NT;
    if (n0 >= N) return;

    constexpr int BSZ = NT * LDK;
    constexpr int STGE = 2*ASZ + 2*BSZ;        // elems per stage
    constexpr int MTt  = (NT == 128) ? 4 : 2;  // m-subtiles per warp

    extern __shared__ __nv_bfloat16 sm2[];

    int tid  = threadIdx.x;
    int wid  = tid >> 5;
    int lane = tid & 31;
    int wm, wn;
    if (NT == 128) { wm = (wid & 1) * 64; wn = (wid >> 1) * 32; }
    else           { wm = (wid & 3) * 32; wn = (wid >> 2) * 32; }

    // A loaders: row tid>>1, 16-elem seg tid&1
    int alr = tid >> 1, alseg = tid & 1;
    const __nv_bfloat16* sAh = jb.Ah + (size_t)(m0 + alr) * K + alseg * 16;
    const __nv_bfloat16* sAl = jb.Al + (size_t)(m0 + alr) * K + alseg * 16;
    uint32_t aoff = alr * LDK + alseg * 16;

    // B loaders
    int brow, bcol;
    uint32_t boff;
    if (NT == 128) { brow = tid >> 1; bcol = (tid & 1) * 16; }
    else           { brow = tid >> 2; bcol = (tid & 3) * 8;  }
    boff = brow * LDK + bcol;
    bool bok = (n0 + brow) < N;
    const __nv_bfloat16* sBh = jb.Bh + (size_t)(n0 + brow) * K + bcol;
    const __nv_bfloat16* sBl = jb.Bl + (size_t)(n0 + brow) * K + bcol;

    float acc[MTt][4][4];
#pragma unroll
    for (int i = 0; i < MTt; i++)
#pragma unroll
        for (int j = 0; j < 4; j++)
#pragma unroll
            for (int q = 0; q < 4; q++) acc[i][j][q] = 0.f;

    uint32_t rowA = (lane & 15) * (LDK*2);
    uint32_t colA = (lane >> 4) * 16;
    uint32_t rowB = (lane & 7)  * (LDK*2);
    uint32_t colB = ((lane >> 3) & 1) * 16;

    const uint4 z4 = make_uint4(0,0,0,0);
    uint4 pah[2], pal[2], pbh[2], pbl[2];
    pah[0] = *(const uint4*)sAh; pah[1] = *(const uint4*)(sAh + 8);
    pal[0] = *(const uint4*)sAl; pal[1] = *(const uint4*)(sAl + 8);
    if (NT == 128) {
        pbh[0] = bok ? *(const uint4*)sBh : z4;
        pbh[1] = bok ? *(const uint4*)(sBh + 8) : z4;
        pbl[0] = bok ? *(const uint4*)sBl : z4;
        pbl[1] = bok ? *(const uint4*)(sBl + 8) : z4;
    } else {
        pbh[0] = bok ? *(const uint4*)sBh : z4;
        pbl[0] = bok ? *(const uint4*)sBl : z4;
    }

    const int ncit = K >> 5;
    for (int c = 0; c < ncit; c++) {
        __nv_bfloat16* buf = sm2 + (size_t)(c & 1) * STGE;
        *(uint4*)(buf + aoff)           = pah[0];
        *(uint4*)(buf + aoff + 8)       = pah[1];
        *(uint4*)(buf + ASZ + aoff)     = pal[0];
        *(uint4*)(buf + ASZ + aoff + 8) = pal[1];
        if (NT == 128) {
            *(uint4*)(buf + 2*ASZ + boff)           = pbh[0];
            *(uint4*)(buf + 2*ASZ + boff + 8)       = pbh[1];
            *(uint4*)(buf + 2*ASZ + BSZ + boff)     = pbl[0];
            *(uint4*)(buf + 2*ASZ + BSZ + boff + 8) = pbl[1];
        } else {
            *(uint4*)(buf + 2*ASZ + boff)       = pbh[0];
            *(uint4*)(buf + 2*ASZ + BSZ + boff) = pbl[0];
        }
        __syncthreads();
        if (c + 1 < ncit) {
            int adv = (c + 1) * 32;
            pah[0] = *(const uint4*)(sAh + adv);
            pah[1] = *(const uint4*)(sAh + adv + 8);
            pal[0] = *(const uint4*)(sAl + adv);
            pal[1] = *(const uint4*)(sAl + adv + 8);
            if (NT == 128) {
                pbh[0] = bok ? *(const uint4*)(sBh + adv) : z4;
                pbh[1] = bok ? *(const uint4*)(sBh + adv + 8) : z4;
                pbl[0] = bok ? *(const uint4*)(sBl + adv) : z4;
                pbl[1] = bok ? *(const uint4*)(sBl + adv + 8) : z4;
            } else {
                pbh[0] = bok ? *(const uint4*)(sBh + adv) : z4;
                pbl[0] = bok ? *(const uint4*)(sBl + adv) : z4;
            }
        }
        uint32_t s0  = smem_u32(buf);
        uint32_t sAh_b = s0;
        uint32_t sAl_b = s0 + ASZ*2;
        uint32_t sBh_b = s0 + 2*ASZ*2;
        uint32_t sBl_b = s0 + (2*ASZ + BSZ)*2;

        // fragment-reuse: load all frags once per k-slice, then 3 MMA sets
#pragma unroll
        for (int ks = 0; ks < 2; ks++) {
            uint32_t afh[MTt][4], afl[MTt][4], bfh[4][2], bfl[4][2];
#pragma unroll
            for (int mt = 0; mt < MTt; mt++) {
                uint32_t ao = (wm + mt*16) * (LDK*2) + rowA + ks*32 + colA;
                ldm_x4(sAh_b + ao, afh[mt]);
                ldm_x4(sAl_b + ao, afl[mt]);
            }
#pragma unroll
            for (int nt = 0; nt < 4; nt++) {
                uint32_t bo = (wn + nt*8) * (LDK*2) + rowB + ks*32 + colB;
                ldm_x2(sBh_b + bo, bfh[nt]);
                ldm_x2(sBl_b + bo, bfl[nt]);
            }
#pragma unroll
            for (int mt = 0; mt < MTt; mt++)
#pragma unroll
                for (int nt = 0; nt < 4; nt++) {
                    mma_bf16(acc[mt][nt], afh[mt], bfh[nt]);
                    mma_bf16(acc[mt][nt], afh[mt], bfl[nt]);
                    mma_bf16(acc[mt][nt], afl[mt], bfh[nt]);
                }
        }
        if (c + 1 < ncit) __syncthreads();
    }

    int g = lane >> 2, tg = lane & 3;
#pragma unroll
    for (int mt = 0; mt < MTt; mt++) {
#pragma unroll
        for (int nt = 0; nt < 4; nt++) {
            int cb = n0 + wn + nt*8 + 2*tg;
            if (NT == 64 && cb >= N) continue;
            int r0 = m0 + wm + mt*16 + g;
            emit2(jb, r0,     cb, acc[mt][nt][0], acc[mt][nt][1]);
            emit2(jb, r0 + 8, cb, acc[mt][nt][2], acc[mt][nt][3]);
        }
    }
}

#define HSM128 ((2*ASZ + 2*128*LDK) * 2 * 2)
#define HSM64  ((2*ASZ + 2*64*LDK)  * 2 * 2)

// ---------------- kk normalize / a_in / b_in / k update --------------------
__global__ void kk_kernel(const float* __restrict__ kkc,
                          const float* __restrict__ kac)
{
    int gid  = blockIdx.x * blockDim.x + threadIdx.x;
    int lane = gid & 31;
    int grp  = gid >> 5;
    if (grp >= BT_*H_) return;
    int bt = grp / H_, h = grp % H_;
    int base = bt * C_ + h * D_;
    int c0   = h * D_;

    float k0v = g_k[base + lane],      k1v = g_k[base + 32 + lane];
    float a0  = g_a[base + lane],      a1  = g_a[base + 32 + lane];
    float kk0 = k0v * kkc[c0 + lane],  kk1 = k1v * kkc[c0 + 32 + lane];

    float ss = kk0*kk0 + kk1*kk1;
#pragma unroll
    for (int o = 16; o; o >>= 1) ss += __shfl_xor_sync(0xffffffffu, ss, o);
    float inv = 1.f / fmaxf(sqrtf(ss), 1e-12f);
    kk0 *= inv; kk1 *= inv;

    g_ain[base + lane]      = -kk0;
    g_ain[base + 32 + lane] = -kk1;
    g_bin[base + lane]      = kk0 * a0;
    g_bin[base + 32 + lane] = kk1 * a1;
    g_k[base + lane]        = k0v * (1.f + (a0 - 1.f) * kac[c0 + lane]);
    g_k[base + 32 + lane]   = k1v * (1.f + (a1 - 1.f) * kac[c0 + 32 + lane]);
}

// ---------------- RWKV-7 recurrence (row-split, 128 blocks) -----------------
__global__ void __launch_bounds__(128, 1) rec_kernel()
{
    int blk = blockIdx.x;
    int bh  = blk >> 2;
    int rb  = blk & 3;
    int b = bh >> 4, h = bh & 15;
    size_t base = (size_t)b * T_ * C_ + h * D_;

    __shared__ alignas(16) float rsm[2][6][RCHUNK][64];

    int tid = threadIdx.x;
    int row = rb * RROWS + (tid >> 3);
    int cp  = tid & 7;
    int c0  = cp * 8;

    const float* srcs[6] = { g_r, g_decay, g_k, g_v, g_ain, g_bin };
    const float* gp[6];
    uint32_t sp_[6];
#pragma unroll
    for (int it = 0; it < 6; it++) {
        int f  = tid + it * 128;
        int q  = f & 15;
        int st = (f >> 4) & (RCHUNK-1);
        int vc = f >> 7;
        gp[it]  = srcs[vc] + base + (size_t)st * C_ + q * 4;
        sp_[it] = (uint32_t)((vc * RCHUNK + st) * 64 + q * 4);
    }

    unsigned long long S[4] = {0ull, 0ull, 0ull, 0ull};

    float4 pf[6];
#pragma unroll
    for (int it = 0; it < 6; it++) pf[it] = *(const float4*)gp[it];

    float* smbase = &rsm[0][0][0][0];
    const int NCH = T_ / RCHUNK;
    for (int ch = 0; ch < NCH; ch++) {
        float* buf = smbase + (ch & 1) * (6*RCHUNK*64);
#pragma unroll
        for (int it = 0; it < 6; it++)
            *(float4*)(buf + sp_[it]) = pf[it];
        __syncthreads();
        if (ch + 1 < NCH) {
            size_t adv = (size_t)(ch + 1) * RCHUNK * C_;
#pragma unroll
            for (int it = 0; it < 6; it++)
                pf[it] = *(const float4*)(gp[it] + adv);
        }

        size_t obase = base + (size_t)ch * RCHUNK * C_ + row;
#pragma unroll 2
        for (int s = 0; s < RCHUNK; s++) {
            const float* rv = buf + (0*RCHUNK + s) * 64;
            const float* wv = buf + (1*RCHUNK + s) * 64;
            const float* kv = buf + (2*RCHUNK + s) * 64;
            const float* vv = buf + (3*RCHUNK + s) * 64;
            const float* av = buf + (4*RCHUNK + s) * 64;
            const float* bv = buf + (5*RCHUNK + s) * 64;

            ulonglong2 aA = *(const ulonglong2*)(av + c0);
            ulonglong2 aB = *(const ulonglong2*)(av + c0 + 4);
            unsigned long long sacc = f32x2_fma(S[0], aA.x, 0ull);
            sacc = f32x2_fma(S[1], aA.y, sacc);
            sacc = f32x2_fma(S[2], aB.x, sacc);
            sacc = f32x2_fma(S[3], aB.y, sacc);
            float2 spp = f32x2_unpack(sacc);
            float sa = spp.x + spp.y;
            sa += __shfl_xor_sync(0xffffffffu, sa, 1);
            sa += __shfl_xor_sync(0xffffffffu, sa, 2);
            sa += __shfl_xor_sync(0xffffffffu, sa, 4);

            float vj = vv[row];
            ulonglong2 wA = *(const ulonglong2*)(wv + c0);
            ulonglong2 wB = *(const ulonglong2*)(wv + c0 + 4);
            ulonglong2 bA = *(const ulonglong2*)(bv + c0);
            ulonglong2 bB = *(const ulonglong2*)(bv + c0 + 4);
            ulonglong2 kA = *(const ulonglong2*)(kv + c0);
            ulonglong2 kB = *(const ulonglong2*)(kv + c0 + 4);
            ulonglong2 rA = *(const ulonglong2*)(rv + c0);
            ulonglong2 rB = *(const ulonglong2*)(rv + c0 + 4);

            unsigned long long sa2 = f32x2_pack(sa, sa);
            unsigned long long v2  = f32x2_pack(vj, vj);

            S[0] = f32x2_fma(v2, kA.x, f32x2_fma(sa2, bA.x, f32x2_fma(S[0], wA.x, 0ull)));
            S[1] = f32x2_fma(v2, kA.y, f32x2_fma(sa2, bA.y, f32x2_fma(S[1], wA.y, 0ull)));
            S[2] = f32x2_fma(v2, kB.x, f32x2_fma(sa2, bB.x, f32x2_fma(S[2], wB.x, 0ull)));
            S[3] = f32x2_fma(v2, kB.y, f32x2_fma(sa2, bB.y, f32x2_fma(S[3], wB.y, 0ull)));

            unsigned long long oacc = f32x2_fma(S[0], rA.x, 0ull);
            oacc = f32x2_fma(S[1], rA.y, oacc);
            oacc = f32x2_fma(S[2], rB.x, oacc);
            oacc = f32x2_fma(S[3], rB.y, oacc);
            float2 op = f32x2_unpack(oacc);
            float o = op.x + op.y;
            o += __shfl_xor_sync(0xffffffffu, o, 1);
            o += __shfl_xor_sync(0xffffffffu, o, 2);
            o += __shfl_xor_sync(0xffffffffu, o, 4);
            if (cp == 0) g_o[obase + (size_t)s * C_] = o;
        }
    }
}

// ---------------- GroupNorm + bonus + gate (emits bf16 hi/lo) --------------
__global__ void post_kernel(const float* __restrict__ rk,
                            const float* __restrict__ gnw,
                            const float* __restrict__ gnb)
{
    int gid  = blockIdx.x * blockDim.x + threadIdx.x;
    int lane = gid & 31;
    int grp  = gid >> 5;
    if (grp >= BT_*H_) return;
    int bt = grp / H_, h = grp % H_;
    int base = bt * C_ + h * D_;
    int c0   = h * D_;

    float o0 = g_o[base + lane], o1 = g_o[base + 32 + lane];
    float su = o0 + o1;
    float sq = o0*o0 + o1*o1;
    float r0 = g_r[base + lane], r1 = g_r[base + 32 + lane];
    float k0 = g_k[base + lane], k1 = g_k[base + 32 + lane];
    float bsum = r0*k0*rk[c0 + lane] + r1*k1*rk[c0 + 32 + lane];
#pragma unroll
    for (int o = 16; o; o >>= 1) {
        su   += __shfl_xor_sync(0xffffffffu, su,   o);
        sq   += __shfl_xor_sync(0xffffffffu, sq,   o);
        bsum += __shfl_xor_sync(0xffffffffu, bsum, o);
    }
    float mu  = su / 64.f;
    float var = sq / 64.f - mu * mu;
    float inv = rsqrtf(var + EPS_);

    float v0 = g_v[base + lane], v1 = g_v[base + 32 + lane];
    float on0 = (o0 - mu) * inv * gnw[c0 + lane]      + gnb[c0 + lane];
    float on1 = (o1 - mu) * inv * gnw[c0 + 32 + lane] + gnb[c0 + 32 + lane];
    float p0 = (on0 + bsum * v0) * g_g[base + lane];
    float p1 = (on1 + bsum * v1) * g_g[base + 32 + lane];

    __nv_bfloat16 h0 = __float2bfloat16_rn(p0);
    __nv_bfloat16 h1 = __float2bfloat16_rn(p1);
    g_preh[base + lane]      = h0;
    g_preh[base + 32 + lane] = h1;
    g_prel[base + lane]      = __float2bfloat16_rn(p0 - __bfloat162float(h0));
    g_prel[base + 32 + lane] = __float2bfloat16_rn(p1 - __bfloat162float(h1));
}

// ---------------- host launcher ---------------------------------------------
extern "C" void kernel_launch(void* const* d_in, const int* in_sizes, int n_in,
                              void* d_out, int out_size)
{
    const float* x        = (const float*)d_in[0];
    const float* x_r      = (const float*)d_in[1];
    const float* x_w      = (const float*)d_in[2];
    const float* x_k      = (const float*)d_in[3];
    const float* x_v      = (const float*)d_in[4];
    const float* x_a      = (const float*)d_in[5];
    const float* x_g      = (const float*)d_in[6];
    const float* k_k      = (const float*)d_in[7];
    const float* k_a      = (const float*)d_in[8];
    const float* r_k      = (const float*)d_in[9];
    const float* Wr       = (const float*)d_in[10];
    const float* Wk       = (const float*)d_in[11];
    const float* Wv       = (const float*)d_in[12];
    const float* Wo       = (const float*)d_in[13];
    const float* wA       = (const float*)d_in[14];
    const float* wB       = (const float*)d_in[15];
    const float* wBias    = (const float*)d_in[16];
    const float* aA       = (const float*)d_in[17];
    const float* aB       = (const float*)d_in[18];
    const float* aBias    = (const float*)d_in[19];
    const float* gA       = (const float*)d_in[20];
    const float* gB       = (const float*)d_in[21];
    const float* gnw      = (const float*)d_in[22];
    const float* gnb      = (const float*)d_in[23];
    const float* w0_base  = (const float*)d_in[24];
    const float* w0_delta = (const float*)d_in[25];
    float* out = (float*)d_out;

#define SYM(p, s) cudaGetSymbolAddress((void**)&p, s)
    float *p_r,*p_k,*p_v,*p_dec,*p_a,*p_g;
    __nv_bfloat16 *p_xrh,*p_xrl,*p_xkh,*p_xkl,*p_xvh,*p_xvl;
    __nv_bfloat16 *p_xwh,*p_xwl,*p_xah,*p_xal,*p_xgh,*p_xgl;
    __nv_bfloat16 *p_preh,*p_prel,*p_wh,*p_wl;
    __nv_bfloat16 *p_wAh,*p_wAl,*p_aAh,*p_aAl,*p_gAh,*p_gAl;
    __nv_bfloat16 *p_wBh,*p_wBl,*p_aBh,*p_aBl,*p_gBh,*p_gBl;
    __nv_bfloat16 *p_w1h,*p_w1l,*p_a1h,*p_a1l,*p_g1h,*p_g1l;
    SYM(p_r, g_r); SYM(p_k, g_k); SYM(p_v, g_v);
    SYM(p_dec, g_decay); SYM(p_a, g_a); SYM(p_g, g_g);
    SYM(p_xrh, g_xrh); SYM(p_xrl, g_xrl);
    SYM(p_xkh, g_xkh); SYM(p_xkl, g_xkl);
    SYM(p_xvh, g_xvh); SYM(p_xvl, g_xvl);
    SYM(p_xwh, g_xwh); SYM(p_xwl, g_xwl);
    SYM(p_xah, g_xah); SYM(p_xal, g_xal);
    SYM(p_xgh, g_xgh); SYM(p_xgl, g_xgl);
    SYM(p_preh, g_preh); SYM(p_prel, g_prel);
    SYM(p_wh, g_wh); SYM(p_wl, g_wl);
    SYM(p_wAh, g_wAh); SYM(p_wAl, g_wAl);
    SYM(p_aAh, g_aAh); SYM(p_aAl, g_aAl);
    SYM(p_gAh, g_gAh); SYM(p_gAl, g_gAl);
    SYM(p_wBh, g_wBh); SYM(p_wBl, g_wBl);
    SYM(p_aBh, g_aBh); SYM(p_aBl, g_aBl);
    SYM(p_gBh, g_gBh); SYM(p_gBl, g_gBl);
    SYM(p_w1h, g_w1h); SYM(p_w1l, g_w1l);
    SYM(p_a1h, g_a1h); SYM(p_a1l, g_a1l);
    SYM(p_g1h, g_g1h); SYM(p_g1l, g_g1l);
#undef SYM

    cudaFuncSetAttribute(hg2_kernel<128>,
        cudaFuncAttributeMaxDynamicSharedMemorySize, HSM128);
    cudaFuncSetAttribute(hg2_kernel<64>,
        cudaFuncAttributeMaxDynamicSharedMemorySize, HSM64);

    // 0) all weights fp32 -> bf16 hi/lo
    {
        WcJobs wj;
        wj.j[0] = { Wr, p_wh + 0*C_*C_, p_wl + 0*C_*C_, C_*C_ };
        wj.j[1] = { Wk, p_wh + 1*C_*C_, p_wl + 1*C_*C_, C_*C_ };
        wj.j[2] = { Wv, p_wh + 2*C_*C_, p_wl + 2*C_*C_, C_*C_ };
        wj.j[3] = { Wo, p_wh + 3*C_*C_, p_wl + 3*C_*C_, C_*C_ };
        wj.j[4] = { wA, p_wAh, p_wAl, RW_*C_ };
        wj.j[5] = { aA, p_aAh, p_aAl, RA_*C_ };
        wj.j[6] = { gA, p_gAh, p_gAl, RG_*C_ };
        wj.j[7] = { wB, p_wBh, p_wBl, C_*RW_ };
        wj.j[8] = { aB, p_aBh, p_aBl, C_*RA_ };
        wj.j[9] = { gB, p_gBh, p_gBl, C_*RG_ };
        wconv_kernel<<<dim3(C_*C_/4/256, 10), 256>>>(wj);
    }

    // 1) token-shift mixes -> bf16 hi/lo (all six)
    mix_kernel<<<(BT_*C_/4 + 255)/256, 256>>>(x, x_r, x_w, x_k, x_v, x_a, x_g);

    // 2) w0 scan
    w0_kernel<<<1, C_>>>(w0_base, w0_delta);

    // 3) r/k/v projections (HMMA, frag-reuse)
    {
        HJobs hj;
        hj.j[0] = { p_xrh, p_xrl, p_wh + 0*C_*C_, p_wl + 0*C_*C_,
                    p_r, nullptr, nullptr, nullptr, C_, C_, 0 };
        hj.j[1] = { p_xkh, p_xkl, p_wh + 1*C_*C_, p_wl + 1*C_*C_,
                    p_k, nullptr, nullptr, nullptr, C_, C_, 0 };
        hj.j[2] = { p_xvh, p_xvl, p_wh + 2*C_*C_, p_wl + 2*C_*C_,
                    p_v, nullptr, nullptr, nullptr, C_, C_, 0 };
        hg2_kernel<128><<<dim3(C_/128, BT_/128, 3), 256, HSM128>>>(hj);
    }

    // 4) LoRA stage 1 (HMMA, NT=64, epilogue emits bf16 hi/lo)
    {
        HJobs hj;
        hj.j[0] = { p_xwh, p_xwl, p_wAh, p_wAl,
                    nullptr, p_w1h, p_w1l, nullptr, RW_, C_, 1 };   // tanh
        hj.j[1] = { p_xah, p_xal, p_aAh, p_aAl,
                    nullptr, p_a1h, p_a1l, nullptr, RA_, C_, 6 };   // none
        hj.j[2] = { p_xgh, p_xgl, p_gAh, p_gAl,
                    nullptr, p_g1h, p_g1l, nullptr, RG_, C_, 2 };   // sigmoid
        hg2_kernel<64><<<dim3((RG_+63)/64, BT_/128, 3), 256, HSM64>>>(hj);
    }

    // 5) LoRA stage 2 (HMMA, NT=128, fused epilogues)
    {
        HJobs hj;
        hj.j[0] = { p_w1h, p_w1l, p_wBh, p_wBl,
                    p_dec, nullptr, nullptr, wBias, C_, RW_, 3 };   // decay
        hj.j[1] = { p_a1h, p_a1l, p_aBh, p_aBl,
                    p_a, nullptr, nullptr, aBias, C_, RA_, 5 };     // sigm+bias
        hj.j[2] = { p_g1h, p_g1l, p_gBh, p_gBl,
                    p_g, nullptr, nullptr, nullptr, C_, RG_, 0 };
        hg2_kernel<128><<<dim3(C_/128, BT_/128, 3), 256, HSM128>>>(hj);
    }

    // 6) kk normalize / a_in / b_in / k update
    kk_kernel<<<(BT_*H_*32 + 255)/256, 256>>>(k_k, k_a);

    // 7) sequential recurrence (row-split)
    rec_kernel<<<128, 128>>>();

    // 8) GroupNorm + bonus + gate (-> bf16 hi/lo)
    post_kernel<<<(BT_*H_*32 + 255)/256, 256>>>(r_k, gnw, gnb);

    // 9) output projection (HMMA)
    {
        HJobs hj;
        hj.j[0] = { p_preh, p_prel, p_wh + 3*C_*C_, p_wl + 3*C_*C_,
                    out, nullptr, nullptr, nullptr, C_, C_, 0 };
        hj.j[1] = hj.j[0];
        hj.j[2] = hj.j[0];
        hg2_kernel<128><<<dim3(C_/128, BT_/128, 1), 256, HSM128>>>(hj);
    }
}

// round 11
// speedup vs baseline: 3.4356x; 1.0746x over previous
#include <cuda_runtime.h>
#include <cuda_bf16.h>
#include <math.h>
#include <stdint.h>

#define B_ 2
#define T_ 2048
#define C_ 1024
#define H_ 16
#define D_ 64
#define BT_ (B_*T_)
#define RW_ 64
#define RA_ 64
#define RG_ 160
#define EPS_ 6.4e-4f   // D * 1e-5
#define RCHUNK 8
#define RROWS 16

// ---------------- packed f32x2 helpers --------------------------------------
__device__ __forceinline__ unsigned long long f32x2_fma(
    unsigned long long a, unsigned long long b, unsigned long long c) {
    unsigned long long d;
    asm("fma.rn.f32x2 %0, %1, %2, %3;" : "=l"(d) : "l"(a), "l"(b), "l"(c));
    return d;
}
__device__ __forceinline__ unsigned long long f32x2_pack(float lo, float hi) {
    unsigned long long d;
    asm("mov.b64 %0, {%1, %2};" : "=l"(d) : "f"(lo), "f"(hi));
    return d;
}
__device__ __forceinline__ float2 f32x2_unpack(unsigned long long v) {
    float lo, hi;
    asm("mov.b64 {%0, %1}, %2;" : "=f"(lo), "=f"(hi) : "l"(v));
    return make_float2(lo, hi);
}
__device__ __forceinline__ uint32_t smem_u32(const void* p) {
    uint32_t a;
    asm("{ .reg .u64 t; cvta.to.shared.u64 t, %1; cvt.u32.u64 %0, t; }"
        : "=r"(a) : "l"(p));
    return a;
}
__device__ __forceinline__ void cp16(uint32_t d, const void* s) {
    asm volatile("cp.async.cg.shared.global [%0], [%1], 16;"
                 :: "r"(d), "l"(s));
}
__device__ __forceinline__ void cp16z(uint32_t d, const void* s, bool ok) {
    int n = ok ? 16 : 0;
    asm volatile("cp.async.cg.shared.global [%0], [%1], 16, %2;"
                 :: "r"(d), "l"(s), "r"(n));
}

// ---------------- scratch (device globals: allocation-free) ----------------
__device__ __nv_bfloat16 g_xrh[BT_*C_], g_xrl[BT_*C_];
__device__ __nv_bfloat16 g_xkh[BT_*C_], g_xkl[BT_*C_];
__device__ __nv_bfloat16 g_xvh[BT_*C_], g_xvl[BT_*C_];
__device__ __nv_bfloat16 g_xwh[BT_*C_], g_xwl[BT_*C_];
__device__ __nv_bfloat16 g_xah[BT_*C_], g_xal[BT_*C_];
__device__ __nv_bfloat16 g_xgh[BT_*C_], g_xgl[BT_*C_];
__device__ __nv_bfloat16 g_preh[BT_*C_], g_prel[BT_*C_];
__device__ __nv_bfloat16 g_wh[4][C_*C_], g_wl[4][C_*C_];   // Wr,Wk,Wv,Wo
__device__ __nv_bfloat16 g_wAh[RW_*C_], g_wAl[RW_*C_];
__device__ __nv_bfloat16 g_aAh[RA_*C_], g_aAl[RA_*C_];
__device__ __nv_bfloat16 g_gAh[RG_*C_], g_gAl[RG_*C_];
__device__ __nv_bfloat16 g_wBh[C_*RW_], g_wBl[C_*RW_];
__device__ __nv_bfloat16 g_aBh[C_*RA_], g_aBl[C_*RA_];
__device__ __nv_bfloat16 g_gBh[C_*RG_], g_gBl[C_*RG_];
__device__ __nv_bfloat16 g_w1h[BT_*RW_], g_w1l[BT_*RW_];
__device__ __nv_bfloat16 g_a1h[BT_*RA_], g_a1l[BT_*RA_];
__device__ __nv_bfloat16 g_g1h[BT_*RG_], g_g1l[BT_*RG_];
__device__ float g_r [BT_*C_];
__device__ float g_k [BT_*C_];
__device__ float g_v [BT_*C_];
__device__ float g_decay[BT_*C_];
__device__ float g_a [BT_*C_];
__device__ float g_g [BT_*C_];
__device__ float g_ain[BT_*C_];
__device__ float g_bin[BT_*C_];
__device__ float g_o [BT_*C_];
__device__ float g_w0[C_];

// ---------------- fp32 -> bf16 hi/lo split helpers --------------------------
__device__ __forceinline__ void split4(float4 m, uint2& hi, uint2& lo) {
    __nv_bfloat16 h0 = __float2bfloat16_rn(m.x);
    __nv_bfloat16 h1 = __float2bfloat16_rn(m.y);
    __nv_bfloat16 h2 = __float2bfloat16_rn(m.z);
    __nv_bfloat16 h3 = __float2bfloat16_rn(m.w);
    __nv_bfloat16 l0 = __float2bfloat16_rn(m.x - __bfloat162float(h0));
    __nv_bfloat16 l1 = __float2bfloat16_rn(m.y - __bfloat162float(h1));
    __nv_bfloat16 l2 = __float2bfloat16_rn(m.z - __bfloat162float(h2));
    __nv_bfloat16 l3 = __float2bfloat16_rn(m.w - __bfloat162float(h3));
    __nv_bfloat162 ph0 = __halves2bfloat162(h0, h1);
    __nv_bfloat162 ph1 = __halves2bfloat162(h2, h3);
    __nv_bfloat162 pl0 = __halves2bfloat162(l0, l1);
    __nv_bfloat162 pl1 = __halves2bfloat162(l2, l3);
    hi.x = *reinterpret_cast<uint32_t*>(&ph0);
    hi.y = *reinterpret_cast<uint32_t*>(&ph1);
    lo.x = *reinterpret_cast<uint32_t*>(&pl0);
    lo.y = *reinterpret_cast<uint32_t*>(&pl1);
}
__device__ __forceinline__ uint32_t pack_bf2(float a, float b, uint32_t& lov) {
    __nv_bfloat16 h0 = __float2bfloat16_rn(a), h1 = __float2bfloat16_rn(b);
    __nv_bfloat16 l0 = __float2bfloat16_rn(a - __bfloat162float(h0));
    __nv_bfloat16 l1 = __float2bfloat16_rn(b - __bfloat162float(h1));
    __nv_bfloat162 hh = __halves2bfloat162(h0, h1);
    __nv_bfloat162 ll = __halves2bfloat162(l0, l1);
    lov = *reinterpret_cast<uint32_t*>(&ll);
    return *reinterpret_cast<uint32_t*>(&hh);
}

// ---------------- weight conversion: fp32 -> bf16 hi/lo ---------------------
struct WcJob { const float* src; __nv_bfloat16 *h, *l; int n; };
struct WcJobs { WcJob j[10]; };
__global__ void wconv_kernel(WcJobs jobs)
{
    WcJob jb = jobs.j[blockIdx.y];
    int i = (blockIdx.x * blockDim.x + threadIdx.x) * 4;
    if (i >= jb.n) return;
    float4 v = *(const float4*)(jb.src + i);
    uint2 hi, lo;
    split4(v, hi, lo);
    *(uint2*)(jb.h + i) = hi;
    *(uint2*)(jb.l + i) = lo;
}

// ---------------- token-shift mixing: all 6 emitted as bf16 hi/lo -----------
__global__ void mix_kernel(const float* __restrict__ x,
    const float* __restrict__ cr, const float* __restrict__ cw,
    const float* __restrict__ ck, const float* __restrict__ cv,
    const float* __restrict__ ca, const float* __restrict__ cg)
{
    int i = blockIdx.x * blockDim.x + threadIdx.x;
    if (i >= BT_*C_/4) return;
    int idx = i * 4;
    int c  = idx & (C_-1);
    int bt = idx >> 10;
    int t  = bt & (T_-1);
    float4 xv = *(const float4*)(x + idx);
    float4 xs = make_float4(0.f,0.f,0.f,0.f);
    if (t) xs = *(const float4*)(x + idx - C_);
    float4 d = make_float4(xs.x-xv.x, xs.y-xv.y, xs.z-xv.z, xs.w-xv.w);
    float4 m; uint2 hi, lo;
#define MIXS(cf, ah, al) { float4 cc = *(const float4*)((cf)+c); \
    m = make_float4(xv.x + d.x*cc.x, xv.y + d.y*cc.y, \
                    xv.z + d.z*cc.z, xv.w + d.w*cc.w); \
    split4(m, hi, lo); \
    *(uint2*)((ah) + idx) = hi; *(uint2*)((al) + idx) = lo; }
    MIXS(cr, g_xrh, g_xrl)
    MIXS(ck, g_xkh, g_xkl)
    MIXS(cv, g_xvh, g_xvl)
    MIXS(cw, g_xwh, g_xwl)
    MIXS(ca, g_xah, g_xal)
    MIXS(cg, g_xgh, g_xgl)
#undef MIXS
}

// ---------------- w0 = base + cumsum(softplus(delta)) ----------------------
__global__ void w0_kernel(const float* __restrict__ base,
                          const float* __restrict__ delta)
{
    __shared__ float s[C_];
    int tid = threadIdx.x;
    float v = 0.f;
    if (tid > 0) {
        float d = delta[tid-1];
        v = (d > 20.f) ? d : log1pf(expf(d));
    }
    s[tid] = v;
    __syncthreads();
    for (int off = 1; off < C_; off <<= 1) {
        float t = (tid >= off) ? s[tid-off] : 0.f;
        __syncthreads();
        s[tid] += t;
        __syncthreads();
    }
    g_w0[tid] = base[0] + s[tid];
}

// ================ generic HMMA bf16-split GEMM (512 thr, 256xNT tile) =======
// C[M,N] = act(A[M,K]*(B[N,K])^T [+bias]); A,B as bf16 hi/lo pairs.
// acts: 0 none->f32 | 1 tanh->bf16split | 2 sigmoid->bf16split |
//       3 decay(w0+bias)->f32 | 5 sigmoid(+bias)->f32 | 6 none->bf16split
struct HJob { const __nv_bfloat16 *Ah, *Al, *Bh, *Bl;
              float* Cf; __nv_bfloat16 *Ch, *Cl;
              const float* bias; int N, K, act; };
struct HJobs { HJob j[3]; };

#define LDK 40
#define AROWS 256
#define ASZ2 (AROWS*LDK)

__device__ __forceinline__ void ldm_x4(uint32_t addr, uint32_t r[4]) {
    asm volatile("ldmatrix.sync.aligned.m8n8.x4.shared.b16 {%0,%1,%2,%3}, [%4];"
        : "=r"(r[0]), "=r"(r[1]), "=r"(r[2]), "=r"(r[3]) : "r"(addr));
}
__device__ __forceinline__ void ldm_x2(uint32_t addr, uint32_t r[2]) {
    asm volatile("ldmatrix.sync.aligned.m8n8.x2.shared.b16 {%0,%1}, [%2];"
        : "=r"(r[0]), "=r"(r[1]) : "r"(addr));
}
__device__ __forceinline__ void mma_bf16(float* d, const uint32_t* a,
                                         const uint32_t* b) {
    asm volatile("mma.sync.aligned.m16n8k16.row.col.f32.bf16.bf16.f32 "
        "{%0,%1,%2,%3}, {%4,%5,%6,%7}, {%8,%9}, {%0,%1,%2,%3};"
        : "+f"(d[0]), "+f"(d[1]), "+f"(d[2]), "+f"(d[3])
        : "r"(a[0]), "r"(a[1]), "r"(a[2]), "r"(a[3]), "r"(b[0]), "r"(b[1]));
}

__device__ __forceinline__ void emit2(const HJob& jb, int row, int col,
                                      float v0, float v1)
{
    size_t idx = (size_t)row * jb.N + col;
    int act = jb.act;
    if (act == 0) {
        *(float2*)(jb.Cf + idx) = make_float2(v0, v1);
    } else if (act == 3) {
        float t0 = g_w0[col]   + v0 + jb.bias[col];
        float t1 = g_w0[col+1] + v1 + jb.bias[col+1];
        float n0 = -t0, n1 = -t1;
        float s0 = (n0 > 20.f) ? n0 : log1pf(expf(n0));
        float s1 = (n1 > 20.f) ? n1 : log1pf(expf(n1));
        *(float2*)(jb.Cf + idx) =
            make_float2(expf(-expf(-s0 - 0.5f)), expf(-expf(-s1 - 0.5f)));
    } else if (act == 5) {
        float y0 = 1.f / (1.f + expf(-(v0 + jb.bias[col])));
        float y1 = 1.f / (1.f + expf(-(v1 + jb.bias[col+1])));
        *(float2*)(jb.Cf + idx) = make_float2(y0, y1);
    } else {
        if (act == 1) { v0 = tanhf(v0); v1 = tanhf(v1); }
        else if (act == 2) {
            v0 = 1.f / (1.f + expf(-v0));
            v1 = 1.f / (1.f + expf(-v1));
        }
        uint32_t lov;
        uint32_t hiv = pack_bf2(v0, v1, lov);
        *(uint32_t*)(jb.Ch + idx) = hiv;
        *(uint32_t*)(jb.Cl + idx) = lov;
    }
}

template<int NT>
__global__ void __launch_bounds__(512, 1) hg3_kernel(HJobs jobs)
{
    HJob jb = jobs.j[blockIdx.z];
    const int N = jb.N, K = jb.K;
    const int m0 = blockIdx.y * AROWS;
    const int n0 = blockIdx.x * NT;
    if (n0 >= N) return;

    constexpr int BSZ  = NT * LDK;               // B tile elems (one matrix)
    constexpr int STGE = 2*ASZ2 + 2*BSZ;         // elems per stage
    constexpr int MTt  = (NT == 128) ? 4 : 2;    // m-subtiles per warp

    extern __shared__ __nv_bfloat16 sm3[];
    uint32_t s0 = smem_u32(sm3);

    int tid  = threadIdx.x;
    int wid  = tid >> 5;
    int lane = tid & 31;
    int wm, wn;
    if (NT == 128) { wm = (wid & 3) * 64; wn = (wid >> 2) * 32; }
    else           { wm = (wid & 7) * 32; wn = (wid >> 3) * 32; }

    // A loaders: 256 rows x 2 segs over 512 threads
    int alr = tid >> 1, alseg = tid & 1;
    const __nv_bfloat16* sAh = jb.Ah + (size_t)(m0 + alr) * K + alseg * 16;
    const __nv_bfloat16* sAl = jb.Al + (size_t)(m0 + alr) * K + alseg * 16;
    uint32_t aoff = (alr * LDK + alseg * 16) * 2;    // bytes

    // B loaders: NT rows x 2 segs over first NT*2 threads
    bool bthr = tid < NT*2;
    int brow = (tid >> 1) & (NT-1), bseg = tid & 1;
    bool bok = bthr && ((n0 + brow) < N);
    const __nv_bfloat16* sBh = jb.Bh + (size_t)(n0 + brow) * K + bseg * 16;
    const __nv_bfloat16* sBl = jb.Bl + (size_t)(n0 + brow) * K + bseg * 16;
    uint32_t boff = (2*ASZ2 + brow * LDK + bseg * 16) * 2;

    float acc[MTt][4][4];
#pragma unroll
    for (int i = 0; i < MTt; i++)
#pragma unroll
        for (int j = 0; j < 4; j++)
#pragma unroll
            for (int q = 0; q < 4; q++) acc[i][j][q] = 0.f;

    uint32_t rowA = (lane & 15) * (LDK*2);
    uint32_t colA = (lane >> 4) * 16;
    uint32_t rowB = (lane & 7)  * (LDK*2);
    uint32_t colB = ((lane >> 3) & 1) * 16;

    const int ncit = K >> 5;

#define HG3_ISSUE(c) do { \
        uint32_t dbase = s0 + ((c) & 1) * (STGE*2); \
        int adv = (c) * 32; \
        cp16(dbase + aoff,               sAh + adv); \
        cp16(dbase + aoff + 16,          sAh + adv + 8); \
        cp16(dbase + ASZ2*2 + aoff,      sAl + adv); \
        cp16(dbase + ASZ2*2 + aoff + 16, sAl + adv + 8); \
        if (bthr) { \
            cp16z(dbase + boff,               sBh + adv,     bok); \
            cp16z(dbase + boff + 16,          sBh + adv + 8, bok); \
            cp16z(dbase + BSZ*2 + boff,       sBl + adv,     bok); \
            cp16z(dbase + BSZ*2 + boff + 16,  sBl + adv + 8, bok); \
        } \
        asm volatile("cp.async.commit_group;"); \
    } while (0)

    HG3_ISSUE(0);

    for (int c = 0; c < ncit; c++) {
        if (c + 1 < ncit) {
            HG3_ISSUE(c + 1);
            asm volatile("cp.async.wait_group 1;");
        } else {
            asm volatile("cp.async.wait_group 0;");
        }
        __syncthreads();

        uint32_t sb    = s0 + (c & 1) * (STGE*2);
        uint32_t sAh_b = sb;
        uint32_t sAl_b = sb + ASZ2*2;
        uint32_t sBh_b = sb + 2*ASZ2*2;
        uint32_t sBl_b = sb + (2*ASZ2 + BSZ)*2;

#pragma unroll
        for (int ks = 0; ks < 2; ks++) {
            uint32_t bfh[4][2], bfl[4][2];
#pragma unroll
            for (int nt = 0; nt < 4; nt++) {
                uint32_t bo = (wn + nt*8) * (LDK*2) + rowB + ks*32 + colB;
                ldm_x2(sBh_b + bo, bfh[nt]);
                ldm_x2(sBl_b + bo, bfl[nt]);
            }
#pragma unroll
            for (int mt = 0; mt < MTt; mt++) {
                uint32_t afh[4], afl[4];
                uint32_t ao = (wm + mt*16) * (LDK*2) + rowA + ks*32 + colA;
                ldm_x4(sAh_b + ao, afh);
                ldm_x4(sAl_b + ao, afl);
#pragma unroll
                for (int nt = 0; nt < 4; nt++) {
                    mma_bf16(acc[mt][nt], afh, bfh[nt]);
                    mma_bf16(acc[mt][nt], afh, bfl[nt]);
                    mma_bf16(acc[mt][nt], afl, bfh[nt]);
                }
            }
        }
        __syncthreads();   // buffer (c&1) free for issue of c+2
    }
#undef HG3_ISSUE

    int g = lane >> 2, tg = lane & 3;
#pragma unroll
    for (int mt = 0; mt < MTt; mt++) {
#pragma unroll
        for (int nt = 0; nt < 4; nt++) {
            int cb = n0 + wn + nt*8 + 2*tg;
            if (NT == 64 && cb >= N) continue;
            int r0 = m0 + wm + mt*16 + g;
            emit2(jb, r0,     cb, acc[mt][nt][0], acc[mt][nt][1]);
            emit2(jb, r0 + 8, cb, acc[mt][nt][2], acc[mt][nt][3]);
        }
    }
}

#define HS3_128 ((2*ASZ2 + 2*128*LDK) * 2 * 2)
#define HS3_64  ((2*ASZ2 + 2*64*LDK)  * 2 * 2)

// ---------------- kk normalize / a_in / b_in / k update --------------------
__global__ void kk_kernel(const float* __restrict__ kkc,
                          const float* __restrict__ kac)
{
    int gid  = blockIdx.x * blockDim.x + threadIdx.x;
    int lane = gid & 31;
    int grp  = gid >> 5;
    if (grp >= BT_*H_) return;
    int bt = grp / H_, h = grp % H_;
    int base = bt * C_ + h * D_;
    int c0   = h * D_;

    float k0v = g_k[base + lane],      k1v = g_k[base + 32 + lane];
    float a0  = g_a[base + lane],      a1  = g_a[base + 32 + lane];
    float kk0 = k0v * kkc[c0 + lane],  kk1 = k1v * kkc[c0 + 32 + lane];

    float ss = kk0*kk0 + kk1*kk1;
#pragma unroll
    for (int o = 16; o; o >>= 1) ss += __shfl_xor_sync(0xffffffffu, ss, o);
    float inv = 1.f / fmaxf(sqrtf(ss), 1e-12f);
    kk0 *= inv; kk1 *= inv;

    g_ain[base + lane]      = -kk0;
    g_ain[base + 32 + lane] = -kk1;
    g_bin[base + lane]      = kk0 * a0;
    g_bin[base + 32 + lane] = kk1 * a1;
    g_k[base + lane]        = k0v * (1.f + (a0 - 1.f) * kac[c0 + lane]);
    g_k[base + 32 + lane]   = k1v * (1.f + (a1 - 1.f) * kac[c0 + 32 + lane]);
}

// ---------------- RWKV-7 recurrence (row-split, 128 blocks) -----------------
__global__ void __launch_bounds__(128, 1) rec_kernel()
{
    int blk = blockIdx.x;
    int bh  = blk >> 2;
    int rb  = blk & 3;
    int b = bh >> 4, h = bh & 15;
    size_t base = (size_t)b * T_ * C_ + h * D_;

    __shared__ alignas(16) float rsm[2][6][RCHUNK][64];

    int tid = threadIdx.x;
    int row = rb * RROWS + (tid >> 3);
    int cp  = tid & 7;
    int c0  = cp * 8;

    const float* srcs[6] = { g_r, g_decay, g_k, g_v, g_ain, g_bin };
    const float* gp[6];
    uint32_t sp_[6];
#pragma unroll
    for (int it = 0; it < 6; it++) {
        int f  = tid + it * 128;
        int q  = f & 15;
        int st = (f >> 4) & (RCHUNK-1);
        int vc = f >> 7;
        gp[it]  = srcs[vc] + base + (size_t)st * C_ + q * 4;
        sp_[it] = (uint32_t)((vc * RCHUNK + st) * 64 + q * 4);
    }

    unsigned long long S[4] = {0ull, 0ull, 0ull, 0ull};

    float4 pf[6];
#pragma unroll
    for (int it = 0; it < 6; it++) pf[it] = *(const float4*)gp[it];

    float* smbase = &rsm[0][0][0][0];
    const int NCH = T_ / RCHUNK;
    for (int ch = 0; ch < NCH; ch++) {
        float* buf = smbase + (ch & 1) * (6*RCHUNK*64);
#pragma unroll
        for (int it = 0; it < 6; it++)
            *(float4*)(buf + sp_[it]) = pf[it];
        __syncthreads();
        if (ch + 1 < NCH) {
            size_t adv = (size_t)(ch + 1) * RCHUNK * C_;
#pragma unroll
            for (int it = 0; it < 6; it++)
                pf[it] = *(const float4*)(gp[it] + adv);
        }

        size_t obase = base + (size_t)ch * RCHUNK * C_ + row;
#pragma unroll 2
        for (int s = 0; s < RCHUNK; s++) {
            const float* rv = buf + (0*RCHUNK + s) * 64;
            const float* wv = buf + (1*RCHUNK + s) * 64;
            const float* kv = buf + (2*RCHUNK + s) * 64;
            const float* vv = buf + (3*RCHUNK + s) * 64;
            const float* av = buf + (4*RCHUNK + s) * 64;
            const float* bv = buf + (5*RCHUNK + s) * 64;

            ulonglong2 aA = *(const ulonglong2*)(av + c0);
            ulonglong2 aB = *(const ulonglong2*)(av + c0 + 4);
            unsigned long long sacc = f32x2_fma(S[0], aA.x, 0ull);
            sacc = f32x2_fma(S[1], aA.y, sacc);
            sacc = f32x2_fma(S[2], aB.x, sacc);
            sacc = f32x2_fma(S[3], aB.y, sacc);
            float2 spp = f32x2_unpack(sacc);
            float sa = spp.x + spp.y;
            sa += __shfl_xor_sync(0xffffffffu, sa, 1);
            sa += __shfl_xor_sync(0xffffffffu, sa, 2);
            sa += __shfl_xor_sync(0xffffffffu, sa, 4);

            float vj = vv[row];
            ulonglong2 wA = *(const ulonglong2*)(wv + c0);
            ulonglong2 wB = *(const ulonglong2*)(wv + c0 + 4);
            ulonglong2 bA = *(const ulonglong2*)(bv + c0);
            ulonglong2 bB = *(const ulonglong2*)(bv + c0 + 4);
            ulonglong2 kA = *(const ulonglong2*)(kv + c0);
            ulonglong2 kB = *(const ulonglong2*)(kv + c0 + 4);
            ulonglong2 rA = *(const ulonglong2*)(rv + c0);
            ulonglong2 rB = *(const ulonglong2*)(rv + c0 + 4);

            unsigned long long sa2 = f32x2_pack(sa, sa);
            unsigned long long v2  = f32x2_pack(vj, vj);

            S[0] = f32x2_fma(v2, kA.x, f32x2_fma(sa2, bA.x, f32x2_fma(S[0], wA.x, 0ull)));
            S[1] = f32x2_fma(v2, kA.y, f32x2_fma(sa2, bA.y, f32x2_fma(S[1], wA.y, 0ull)));
            S[2] = f32x2_fma(v2, kB.x, f32x2_fma(sa2, bB.x, f32x2_fma(S[2], wB.x, 0ull)));
            S[3] = f32x2_fma(v2, kB.y, f32x2_fma(sa2, bB.y, f32x2_fma(S[3], wB.y, 0ull)));

            unsigned long long oacc = f32x2_fma(S[0], rA.x, 0ull);
            oacc = f32x2_fma(S[1], rA.y, oacc);
            oacc = f32x2_fma(S[2], rB.x, oacc);
            oacc = f32x2_fma(S[3], rB.y, oacc);
            float2 op = f32x2_unpack(oacc);
            float o = op.x + op.y;
            o += __shfl_xor_sync(0xffffffffu, o, 1);
            o += __shfl_xor_sync(0xffffffffu, o, 2);
            o += __shfl_xor_sync(0xffffffffu, o, 4);
            if (cp == 0) g_o[obase + (size_t)s * C_] = o;
        }
    }
}

// ---------------- GroupNorm + bonus + gate (emits bf16 hi/lo) --------------
__global__ void post_kernel(const float* __restrict__ rk,
                            const float* __restrict__ gnw,
                            const float* __restrict__ gnb)
{
    int gid  = blockIdx.x * blockDim.x + threadIdx.x;
    int lane = gid & 31;
    int grp  = gid >> 5;
    if (grp >= BT_*H_) return;
    int bt = grp / H_, h = grp % H_;
    int base = bt * C_ + h * D_;
    int c0   = h * D_;

    float o0 = g_o[base + lane], o1 = g_o[base + 32 + lane];
    float su = o0 + o1;
    float sq = o0*o0 + o1*o1;
    float r0 = g_r[base + lane], r1 = g_r[base + 32 + lane];
    float k0 = g_k[base + lane], k1 = g_k[base + 32 + lane];
    float bsum = r0*k0*rk[c0 + lane] + r1*k1*rk[c0 + 32 + lane];
#pragma unroll
    for (int o = 16; o; o >>= 1) {
        su   += __shfl_xor_sync(0xffffffffu, su,   o);
        sq   += __shfl_xor_sync(0xffffffffu, sq,   o);
        bsum += __shfl_xor_sync(0xffffffffu, bsum, o);
    }
    float mu  = su / 64.f;
    float var = sq / 64.f - mu * mu;
    float inv = rsqrtf(var + EPS_);

    float v0 = g_v[base + lane], v1 = g_v[base + 32 + lane];
    float on0 = (o0 - mu) * inv * gnw[c0 + lane]      + gnb[c0 + lane];
    float on1 = (o1 - mu) * inv * gnw[c0 + 32 + lane] + gnb[c0 + 32 + lane];
    float p0 = (on0 + bsum * v0) * g_g[base + lane];
    float p1 = (on1 + bsum * v1) * g_g[base + 32 + lane];

    __nv_bfloat16 h0 = __float2bfloat16_rn(p0);
    __nv_bfloat16 h1 = __float2bfloat16_rn(p1);
    g_preh[base + lane]      = h0;
    g_preh[base + 32 + lane] = h1;
    g_prel[base + lane]      = __float2bfloat16_rn(p0 - __bfloat162float(h0));
    g_prel[base + 32 + lane] = __float2bfloat16_rn(p1 - __bfloat162float(h1));
}

// ---------------- host launcher ---------------------------------------------
extern "C" void kernel_launch(void* const* d_in, const int* in_sizes, int n_in,
                              void* d_out, int out_size)
{
    const float* x        = (const float*)d_in[0];
    const float* x_r      = (const float*)d_in[1];
    const float* x_w      = (const float*)d_in[2];
    const float* x_k      = (const float*)d_in[3];
    const float* x_v      = (const float*)d_in[4];
    const float* x_a      = (const float*)d_in[5];
    const float* x_g      = (const float*)d_in[6];
    const float* k_k      = (const float*)d_in[7];
    const float* k_a      = (const float*)d_in[8];
    const float* r_k      = (const float*)d_in[9];
    const float* Wr       = (const float*)d_in[10];
    const float* Wk       = (const float*)d_in[11];
    const float* Wv       = (const float*)d_in[12];
    const float* Wo       = (const float*)d_in[13];
    const float* wA       = (const float*)d_in[14];
    const float* wB       = (const float*)d_in[15];
    const float* wBias    = (const float*)d_in[16];
    const float* aA       = (const float*)d_in[17];
    const float* aB       = (const float*)d_in[18];
    const float* aBias    = (const float*)d_in[19];
    const float* gA       = (const float*)d_in[20];
    const float* gB       = (const float*)d_in[21];
    const float* gnw      = (const float*)d_in[22];
    const float* gnb      = (const float*)d_in[23];
    const float* w0_base  = (const float*)d_in[24];
    const float* w0_delta = (const float*)d_in[25];
    float* out = (float*)d_out;

#define SYM(p, s) cudaGetSymbolAddress((void**)&p, s)
    float *p_r,*p_k,*p_v,*p_dec,*p_a,*p_g;
    __nv_bfloat16 *p_xrh,*p_xrl,*p_xkh,*p_xkl,*p_xvh,*p_xvl;
    __nv_bfloat16 *p_xwh,*p_xwl,*p_xah,*p_xal,*p_xgh,*p_xgl;
    __nv_bfloat16 *p_preh,*p_prel,*p_wh,*p_wl;
    __nv_bfloat16 *p_wAh,*p_wAl,*p_aAh,*p_aAl,*p_gAh,*p_gAl;
    __nv_bfloat16 *p_wBh,*p_wBl,*p_aBh,*p_aBl,*p_gBh,*p_gBl;
    __nv_bfloat16 *p_w1h,*p_w1l,*p_a1h,*p_a1l,*p_g1h,*p_g1l;
    SYM(p_r, g_r); SYM(p_k, g_k); SYM(p_v, g_v);
    SYM(p_dec, g_decay); SYM(p_a, g_a); SYM(p_g, g_g);
    SYM(p_xrh, g_xrh); SYM(p_xrl, g_xrl);
    SYM(p_xkh, g_xkh); SYM(p_xkl, g_xkl);
    SYM(p_xvh, g_xvh); SYM(p_xvl, g_xvl);
    SYM(p_xwh, g_xwh); SYM(p_xwl, g_xwl);
    SYM(p_xah, g_xah); SYM(p_xal, g_xal);
    SYM(p_xgh, g_xgh); SYM(p_xgl, g_xgl);
    SYM(p_preh, g_preh); SYM(p_prel, g_prel);
    SYM(p_wh, g_wh); SYM(p_wl, g_wl);
    SYM(p_wAh, g_wAh); SYM(p_wAl, g_wAl);
    SYM(p_aAh, g_aAh); SYM(p_aAl, g_aAl);
    SYM(p_gAh, g_gAh); SYM(p_gAl, g_gAl);
    SYM(p_wBh, g_wBh); SYM(p_wBl, g_wBl);
    SYM(p_aBh, g_aBh); SYM(p_aBl, g_aBl);
    SYM(p_gBh, g_gBh); SYM(p_gBl, g_gBl);
    SYM(p_w1h, g_w1h); SYM(p_w1l, g_w1l);
    SYM(p_a1h, g_a1h); SYM(p_a1l, g_a1l);
    SYM(p_g1h, g_g1h); SYM(p_g1l, g_g1l);
#undef SYM

    cudaFuncSetAttribute(hg3_kernel<128>,
        cudaFuncAttributeMaxDynamicSharedMemorySize, HS3_128);
    cudaFuncSetAttribute(hg3_kernel<64>,
        cudaFuncAttributeMaxDynamicSharedMemorySize, HS3_64);

    // 0) all weights fp32 -> bf16 hi/lo
    {
        WcJobs wj;
        wj.j[0] = { Wr, p_wh + 0*C_*C_, p_wl + 0*C_*C_, C_*C_ };
        wj.j[1] = { Wk, p_wh + 1*C_*C_, p_wl + 1*C_*C_, C_*C_ };
        wj.j[2] = { Wv, p_wh + 2*C_*C_, p_wl + 2*C_*C_, C_*C_ };
        wj.j[3] = { Wo, p_wh + 3*C_*C_, p_wl + 3*C_*C_, C_*C_ };
        wj.j[4] = { wA, p_wAh, p_wAl, RW_*C_ };
        wj.j[5] = { aA, p_aAh, p_aAl, RA_*C_ };
        wj.j[6] = { gA, p_gAh, p_gAl, RG_*C_ };
        wj.j[7] = { wB, p_wBh, p_wBl, C_*RW_ };
        wj.j[8] = { aB, p_aBh, p_aBl, C_*RA_ };
        wj.j[9] = { gB, p_gBh, p_gBl, C_*RG_ };
        wconv_kernel<<<dim3(C_*C_/4/256, 10), 256>>>(wj);
    }

    // 1) token-shift mixes -> bf16 hi/lo (all six)
    mix_kernel<<<(BT_*C_/4 + 255)/256, 256>>>(x, x_r, x_w, x_k, x_v, x_a, x_g);

    // 2) w0 scan
    w0_kernel<<<1, C_>>>(w0_base, w0_delta);

    // 3) r/k/v projections (HMMA 256x128, cp.async)
    {
        HJobs hj;
        hj.j[0] = { p_xrh, p_xrl, p_wh + 0*C_*C_, p_wl + 0*C_*C_,
                    p_r, nullptr, nullptr, nullptr, C_, C_, 0 };
        hj.j[1] = { p_xkh, p_xkl, p_wh + 1*C_*C_, p_wl + 1*C_*C_,
                    p_k, nullptr, nullptr, nullptr, C_, C_, 0 };
        hj.j[2] = { p_xvh, p_xvl, p_wh + 2*C_*C_, p_wl + 2*C_*C_,
                    p_v, nullptr, nullptr, nullptr, C_, C_, 0 };
        hg3_kernel<128><<<dim3(C_/128, BT_/AROWS, 3), 512, HS3_128>>>(hj);
    }

    // 4) LoRA stage 1 (NT=64, epilogue emits bf16 hi/lo)
    {
        HJobs hj;
        hj.j[0] = { p_xwh, p_xwl, p_wAh, p_wAl,
                    nullptr, p_w1h, p_w1l, nullptr, RW_, C_, 1 };   // tanh
        hj.j[1] = { p_xah, p_xal, p_aAh, p_aAl,
                    nullptr, p_a1h, p_a1l, nullptr, RA_, C_, 6 };   // none
        hj.j[2] = { p_xgh, p_xgl, p_gAh, p_gAl,
                    nullptr, p_g1h, p_g1l, nullptr, RG_, C_, 2 };   // sigmoid
        hg3_kernel<64><<<dim3((RG_+63)/64, BT_/AROWS, 3), 512, HS3_64>>>(hj);
    }

    // 5) LoRA stage 2 (NT=128, fused epilogues)
    {
        HJobs hj;
        hj.j[0] = { p_w1h, p_w1l, p_wBh, p_wBl,
                    p_dec, nullptr, nullptr, wBias, C_, RW_, 3 };   // decay
        hj.j[1] = { p_a1h, p_a1l, p_aBh, p_aBl,
                    p_a, nullptr, nullptr, aBias, C_, RA_, 5 };     // sigm+bias
        hj.j[2] = { p_g1h, p_g1l, p_gBh, p_gBl,
                    p_g, nullptr, nullptr, nullptr, C_, RG_, 0 };
        hg3_kernel<128><<<dim3(C_/128, BT_/AROWS, 3), 512, HS3_128>>>(hj);
    }

    // 6) kk normalize / a_in / b_in / k update
    kk_kernel<<<(BT_*H_*32 + 255)/256, 256>>>(k_k, k_a);

    // 7) sequential recurrence (row-split)
    rec_kernel<<<128, 128>>>();

    // 8) GroupNorm + bonus + gate (-> bf16 hi/lo)
    post_kernel<<<(BT_*H_*32 + 255)/256, 256>>>(r_k, gnw, gnb);

    // 9) output projection (HMMA)
    {
        HJobs hj;
        hj.j[0] = { p_preh, p_prel, p_wh + 3*C_*C_, p_wl + 3*C_*C_,
                    out, nullptr, nullptr, nullptr, C_, C_, 0 };
        hj.j[1] = hj.j[0];
        hj.j[2] = hj.j[0];
        hg3_kernel<128><<<dim3(C_/128, BT_/AROWS, 1), 512, HS3_128>>>(hj);
    }
}

// round 12
// speedup vs baseline: 3.5871x; 1.0441x over previous
#include <cuda_runtime.h>
#include <cuda_bf16.h>
#include <math.h>
#include <stdint.h>

#define B_ 2
#define T_ 2048
#define C_ 1024
#define H_ 16
#define D_ 64
#define BT_ (B_*T_)
#define RW_ 64
#define RA_ 64
#define RG_ 160
#define EPS_ 6.4e-4f   // D * 1e-5
#define RCHUNK 8
#define RROWS 16

// ---------------- packed f32x2 helpers --------------------------------------
__device__ __forceinline__ unsigned long long f32x2_fma(
    unsigned long long a, unsigned long long b, unsigned long long c) {
    unsigned long long d;
    asm("fma.rn.f32x2 %0, %1, %2, %3;" : "=l"(d) : "l"(a), "l"(b), "l"(c));
    return d;
}
__device__ __forceinline__ unsigned long long f32x2_pack(float lo, float hi) {
    unsigned long long d;
    asm("mov.b64 %0, {%1, %2};" : "=l"(d) : "f"(lo), "f"(hi));
    return d;
}
__device__ __forceinline__ float2 f32x2_unpack(unsigned long long v) {
    float lo, hi;
    asm("mov.b64 {%0, %1}, %2;" : "=f"(lo), "=f"(hi) : "l"(v));
    return make_float2(lo, hi);
}
__device__ __forceinline__ uint32_t smem_u32(const void* p) {
    uint32_t a;
    asm("{ .reg .u64 t; cvta.to.shared.u64 t, %1; cvt.u32.u64 %0, t; }"
        : "=r"(a) : "l"(p));
    return a;
}
__device__ __forceinline__ void cp16(uint32_t d, const void* s) {
    asm volatile("cp.async.cg.shared.global [%0], [%1], 16;"
                 :: "r"(d), "l"(s));
}
__device__ __forceinline__ void cp16z(uint32_t d, const void* s, bool ok) {
    int n = ok ? 16 : 0;
    asm volatile("cp.async.cg.shared.global [%0], [%1], 16, %2;"
                 :: "r"(d), "l"(s), "r"(n));
}

// ---------------- scratch (device globals: allocation-free) ----------------
__device__ __nv_bfloat16 g_xrh[BT_*C_], g_xrl[BT_*C_];
__device__ __nv_bfloat16 g_xkh[BT_*C_], g_xkl[BT_*C_];
__device__ __nv_bfloat16 g_xvh[BT_*C_], g_xvl[BT_*C_];
__device__ __nv_bfloat16 g_xwh[BT_*C_], g_xwl[BT_*C_];
__device__ __nv_bfloat16 g_xah[BT_*C_], g_xal[BT_*C_];
__device__ __nv_bfloat16 g_xgh[BT_*C_], g_xgl[BT_*C_];
__device__ __nv_bfloat16 g_preh[BT_*C_], g_prel[BT_*C_];
__device__ __nv_bfloat16 g_wh[4][C_*C_], g_wl[4][C_*C_];   // Wr,Wk,Wv,Wo
__device__ __nv_bfloat16 g_wAh[RW_*C_], g_wAl[RW_*C_];
__device__ __nv_bfloat16 g_aAh[RA_*C_], g_aAl[RA_*C_];
__device__ __nv_bfloat16 g_gAh[RG_*C_], g_gAl[RG_*C_];
__device__ __nv_bfloat16 g_wBh[C_*RW_], g_wBl[C_*RW_];
__device__ __nv_bfloat16 g_aBh[C_*RA_], g_aBl[C_*RA_];
__device__ __nv_bfloat16 g_gBh[C_*RG_], g_gBl[C_*RG_];
__device__ __nv_bfloat16 g_w1h[BT_*RW_], g_w1l[BT_*RW_];
__device__ __nv_bfloat16 g_a1h[BT_*RA_], g_a1l[BT_*RA_];
__device__ __nv_bfloat16 g_g1h[BT_*RG_], g_g1l[BT_*RG_];
__device__ float g_r [BT_*C_];
__device__ float g_k [BT_*C_];
__device__ float g_v [BT_*C_];
__device__ float g_decay[BT_*C_];
__device__ float g_a [BT_*C_];
__device__ float g_g [BT_*C_];
__device__ float g_ain[BT_*C_];
__device__ float g_bin[BT_*C_];
__device__ float g_o [BT_*C_];
__device__ float g_w0[C_];

// ---------------- fp32 -> bf16 hi/lo split helpers --------------------------
__device__ __forceinline__ void split4(float4 m, uint2& hi, uint2& lo) {
    __nv_bfloat16 h0 = __float2bfloat16_rn(m.x);
    __nv_bfloat16 h1 = __float2bfloat16_rn(m.y);
    __nv_bfloat16 h2 = __float2bfloat16_rn(m.z);
    __nv_bfloat16 h3 = __float2bfloat16_rn(m.w);
    __nv_bfloat16 l0 = __float2bfloat16_rn(m.x - __bfloat162float(h0));
    __nv_bfloat16 l1 = __float2bfloat16_rn(m.y - __bfloat162float(h1));
    __nv_bfloat16 l2 = __float2bfloat16_rn(m.z - __bfloat162float(h2));
    __nv_bfloat16 l3 = __float2bfloat16_rn(m.w - __bfloat162float(h3));
    __nv_bfloat162 ph0 = __halves2bfloat162(h0, h1);
    __nv_bfloat162 ph1 = __halves2bfloat162(h2, h3);
    __nv_bfloat162 pl0 = __halves2bfloat162(l0, l1);
    __nv_bfloat162 pl1 = __halves2bfloat162(l2, l3);
    hi.x = *reinterpret_cast<uint32_t*>(&ph0);
    hi.y = *reinterpret_cast<uint32_t*>(&ph1);
    lo.x = *reinterpret_cast<uint32_t*>(&pl0);
    lo.y = *reinterpret_cast<uint32_t*>(&pl1);
}
__device__ __forceinline__ uint32_t pack_bf2(float a, float b, uint32_t& lov) {
    __nv_bfloat16 h0 = __float2bfloat16_rn(a), h1 = __float2bfloat16_rn(b);
    __nv_bfloat16 l0 = __float2bfloat16_rn(a - __bfloat162float(h0));
    __nv_bfloat16 l1 = __float2bfloat16_rn(b - __bfloat162float(h1));
    __nv_bfloat162 hh = __halves2bfloat162(h0, h1);
    __nv_bfloat162 ll = __halves2bfloat162(l0, l1);
    lov = *reinterpret_cast<uint32_t*>(&ll);
    return *reinterpret_cast<uint32_t*>(&hh);
}

// ---------------- weight conversion: fp32 -> bf16 hi/lo ---------------------
struct WcJob { const float* src; __nv_bfloat16 *h, *l; int n; };
struct WcJobs { WcJob j[10]; };
__global__ void wconv_kernel(WcJobs jobs)
{
    WcJob jb = jobs.j[blockIdx.y];
    int i = (blockIdx.x * blockDim.x + threadIdx.x) * 4;
    if (i >= jb.n) return;
    float4 v = *(const float4*)(jb.src + i);
    uint2 hi, lo;
    split4(v, hi, lo);
    *(uint2*)(jb.h + i) = hi;
    *(uint2*)(jb.l + i) = lo;
}

// ---------------- token-shift mixing: all 6 emitted as bf16 hi/lo -----------
__global__ void mix_kernel(const float* __restrict__ x,
    const float* __restrict__ cr, const float* __restrict__ cw,
    const float* __restrict__ ck, const float* __restrict__ cv,
    const float* __restrict__ ca, const float* __restrict__ cg)
{
    int i = blockIdx.x * blockDim.x + threadIdx.x;
    if (i >= BT_*C_/4) return;
    int idx = i * 4;
    int c  = idx & (C_-1);
    int bt = idx >> 10;
    int t  = bt & (T_-1);
    float4 xv = *(const float4*)(x + idx);
    float4 xs = make_float4(0.f,0.f,0.f,0.f);
    if (t) xs = *(const float4*)(x + idx - C_);
    float4 d = make_float4(xs.x-xv.x, xs.y-xv.y, xs.z-xv.z, xs.w-xv.w);
    float4 m; uint2 hi, lo;
#define MIXS(cf, ah, al) { float4 cc = *(const float4*)((cf)+c); \
    m = make_float4(xv.x + d.x*cc.x, xv.y + d.y*cc.y, \
                    xv.z + d.z*cc.z, xv.w + d.w*cc.w); \
    split4(m, hi, lo); \
    *(uint2*)((ah) + idx) = hi; *(uint2*)((al) + idx) = lo; }
    MIXS(cr, g_xrh, g_xrl)
    MIXS(ck, g_xkh, g_xkl)
    MIXS(cv, g_xvh, g_xvl)
    MIXS(cw, g_xwh, g_xwl)
    MIXS(ca, g_xah, g_xal)
    MIXS(cg, g_xgh, g_xgl)
#undef MIXS
}

// ---------------- w0 = base + cumsum(softplus(delta)) ----------------------
__global__ void w0_kernel(const float* __restrict__ base,
                          const float* __restrict__ delta)
{
    __shared__ float s[C_];
    int tid = threadIdx.x;
    float v = 0.f;
    if (tid > 0) {
        float d = delta[tid-1];
        v = (d > 20.f) ? d : log1pf(expf(d));
    }
    s[tid] = v;
    __syncthreads();
    for (int off = 1; off < C_; off <<= 1) {
        float t = (tid >= off) ? s[tid-off] : 0.f;
        __syncthreads();
        s[tid] += t;
        __syncthreads();
    }
    g_w0[tid] = base[0] + s[tid];
}

// ================ generic HMMA bf16-split GEMM (512 thr, 3-stage async) =====
// C[M,N] = act(A[M,K]*(B[N,K])^T [+bias]); A,B as bf16 hi/lo pairs.
// acts: 0 none->f32 | 1 tanh->bf16split | 2 sigmoid->bf16split |
//       3 decay(w0+bias)->f32 | 5 sigmoid(+bias)->f32 | 6 none->bf16split
struct HJob { const __nv_bfloat16 *Ah, *Al, *Bh, *Bl;
              float* Cf; __nv_bfloat16 *Ch, *Cl;
              const float* bias; int N, K, act; };
struct HJobs { HJob j[3]; };

#define LDK 40
#define AROWS 256
#define ASZ2 (AROWS*LDK)

__device__ __forceinline__ void ldm_x4(uint32_t addr, uint32_t r[4]) {
    asm volatile("ldmatrix.sync.aligned.m8n8.x4.shared.b16 {%0,%1,%2,%3}, [%4];"
        : "=r"(r[0]), "=r"(r[1]), "=r"(r[2]), "=r"(r[3]) : "r"(addr));
}
__device__ __forceinline__ void ldm_x2(uint32_t addr, uint32_t r[2]) {
    asm volatile("ldmatrix.sync.aligned.m8n8.x2.shared.b16 {%0,%1}, [%2];"
        : "=r"(r[0]), "=r"(r[1]) : "r"(addr));
}
__device__ __forceinline__ void mma_bf16(float* d, const uint32_t* a,
                                         const uint32_t* b) {
    asm volatile("mma.sync.aligned.m16n8k16.row.col.f32.bf16.bf16.f32 "
        "{%0,%1,%2,%3}, {%4,%5,%6,%7}, {%8,%9}, {%0,%1,%2,%3};"
        : "+f"(d[0]), "+f"(d[1]), "+f"(d[2]), "+f"(d[3])
        : "r"(a[0]), "r"(a[1]), "r"(a[2]), "r"(a[3]), "r"(b[0]), "r"(b[1]));
}

__device__ __forceinline__ void emit2(const HJob& jb, int row, int col,
                                      float v0, float v1)
{
    size_t idx = (size_t)row * jb.N + col;
    int act = jb.act;
    if (act == 0) {
        *(float2*)(jb.Cf + idx) = make_float2(v0, v1);
    } else if (act == 3) {
        float t0 = g_w0[col]   + v0 + jb.bias[col];
        float t1 = g_w0[col+1] + v1 + jb.bias[col+1];
        float n0 = -t0, n1 = -t1;
        float s0 = (n0 > 20.f) ? n0 : log1pf(expf(n0));
        float s1 = (n1 > 20.f) ? n1 : log1pf(expf(n1));
        *(float2*)(jb.Cf + idx) =
            make_float2(expf(-expf(-s0 - 0.5f)), expf(-expf(-s1 - 0.5f)));
    } else if (act == 5) {
        float y0 = 1.f / (1.f + expf(-(v0 + jb.bias[col])));
        float y1 = 1.f / (1.f + expf(-(v1 + jb.bias[col+1])));
        *(float2*)(jb.Cf + idx) = make_float2(y0, y1);
    } else {
        if (act == 1) { v0 = tanhf(v0); v1 = tanhf(v1); }
        else if (act == 2) {
            v0 = 1.f / (1.f + expf(-v0));
            v1 = 1.f / (1.f + expf(-v1));
        }
        uint32_t lov;
        uint32_t hiv = pack_bf2(v0, v1, lov);
        *(uint32_t*)(jb.Ch + idx) = hiv;
        *(uint32_t*)(jb.Cl + idx) = lov;
    }
}

template<int NT>
__global__ void __launch_bounds__(512, 1) hg3_kernel(HJobs jobs)
{
    HJob jb = jobs.j[blockIdx.z];
    const int N = jb.N, K = jb.K;
    const int m0 = blockIdx.y * AROWS;
    const int n0 = blockIdx.x * NT;
    if (n0 >= N) return;

    constexpr int BSZ  = NT * LDK;
    constexpr int STGE = 2*ASZ2 + 2*BSZ;         // elems per stage
    constexpr int MTt  = (NT == 128) ? 4 : 2;

    extern __shared__ __nv_bfloat16 sm3[];
    uint32_t s0 = smem_u32(sm3);

    int tid  = threadIdx.x;
    int wid  = tid >> 5;
    int lane = tid & 31;
    int wm, wn;
    if (NT == 128) { wm = (wid & 3) * 64; wn = (wid >> 2) * 32; }
    else           { wm = (wid & 7) * 32; wn = (wid >> 3) * 32; }

    int alr = tid >> 1, alseg = tid & 1;
    const __nv_bfloat16* sAh = jb.Ah + (size_t)(m0 + alr) * K + alseg * 16;
    const __nv_bfloat16* sAl = jb.Al + (size_t)(m0 + alr) * K + alseg * 16;
    uint32_t aoff = (alr * LDK + alseg * 16) * 2;

    bool bthr = tid < NT*2;
    int brow = (tid >> 1) & (NT-1), bseg = tid & 1;
    bool bok = bthr && ((n0 + brow) < N);
    const __nv_bfloat16* sBh = jb.Bh + (size_t)(n0 + brow) * K + bseg * 16;
    const __nv_bfloat16* sBl = jb.Bl + (size_t)(n0 + brow) * K + bseg * 16;
    uint32_t boff = (2*ASZ2 + brow * LDK + bseg * 16) * 2;

    float acc[MTt][4][4];
#pragma unroll
    for (int i = 0; i < MTt; i++)
#pragma unroll
        for (int j = 0; j < 4; j++)
#pragma unroll
            for (int q = 0; q < 4; q++) acc[i][j][q] = 0.f;

    uint32_t rowA = (lane & 15) * (LDK*2);
    uint32_t colA = (lane >> 4) * 16;
    uint32_t rowB = (lane & 7)  * (LDK*2);
    uint32_t colB = ((lane >> 3) & 1) * 16;

    const int ncit = K >> 5;

#define HG3_ISSUE(c, st) do { \
        uint32_t dbase = s0 + (uint32_t)(st) * (STGE*2); \
        int adv = (c) * 32; \
        cp16(dbase + aoff,               sAh + adv); \
        cp16(dbase + aoff + 16,          sAh + adv + 8); \
        cp16(dbase + ASZ2*2 + aoff,      sAl + adv); \
        cp16(dbase + ASZ2*2 + aoff + 16, sAl + adv + 8); \
        if (bthr) { \
            cp16z(dbase + boff,               sBh + adv,     bok); \
            cp16z(dbase + boff + 16,          sBh + adv + 8, bok); \
            cp16z(dbase + BSZ*2 + boff,       sBl + adv,     bok); \
            cp16z(dbase + BSZ*2 + boff + 16,  sBl + adv + 8, bok); \
        } \
        asm volatile("cp.async.commit_group;"); \
    } while (0)

    // prime 2 stages
    HG3_ISSUE(0, 0);
    if (ncit > 1) HG3_ISSUE(1, 1);

    int st = 0;   // stage of chunk c
    for (int c = 0; c < ncit; c++) {
        if (c + 1 < ncit)
            asm volatile("cp.async.wait_group 1;");   // stage c complete
        else
            asm volatile("cp.async.wait_group 0;");
        __syncthreads();   // also: all warps done with stage (c-1)%3

        // issue chunk c+2 into stage (c+2)%3 == (c-1)%3 (freed by barrier)
        if (c + 2 < ncit) {
            int st2 = st + 2; if (st2 >= 3) st2 -= 3;
            HG3_ISSUE(c + 2, st2);
        }

        uint32_t sb    = s0 + (uint32_t)st * (STGE*2);
        uint32_t sAh_b = sb;
        uint32_t sAl_b = sb + ASZ2*2;
        uint32_t sBh_b = sb + 2*ASZ2*2;
        uint32_t sBl_b = sb + (2*ASZ2 + BSZ)*2;

#pragma unroll
        for (int ks = 0; ks < 2; ks++) {
            uint32_t bfh[4][2], bfl[4][2];
#pragma unroll
            for (int nt = 0; nt < 4; nt++) {
                uint32_t bo = (wn + nt*8) * (LDK*2) + rowB + ks*32 + colB;
                ldm_x2(sBh_b + bo, bfh[nt]);
                ldm_x2(sBl_b + bo, bfl[nt]);
            }
#pragma unroll
            for (int mt = 0; mt < MTt; mt++) {
                uint32_t afh[4], afl[4];
                uint32_t ao = (wm + mt*16) * (LDK*2) + rowA + ks*32 + colA;
                ldm_x4(sAh_b + ao, afh);
                ldm_x4(sAl_b + ao, afl);
#pragma unroll
                for (int nt = 0; nt < 4; nt++) {
                    mma_bf16(acc[mt][nt], afh, bfh[nt]);
                    mma_bf16(acc[mt][nt], afh, bfl[nt]);
                    mma_bf16(acc[mt][nt], afl, bfh[nt]);
                }
            }
        }
        if (++st == 3) st = 0;
    }
#undef HG3_ISSUE

    int g = lane >> 2, tg = lane & 3;
#pragma unroll
    for (int mt = 0; mt < MTt; mt++) {
#pragma unroll
        for (int nt = 0; nt < 4; nt++) {
            int cb = n0 + wn + nt*8 + 2*tg;
            if (NT == 64 && cb >= N) continue;
            int r0 = m0 + wm + mt*16 + g;
            emit2(jb, r0,     cb, acc[mt][nt][0], acc[mt][nt][1]);
            emit2(jb, r0 + 8, cb, acc[mt][nt][2], acc[mt][nt][3]);
        }
    }
}

#define HS3_128 ((2*ASZ2 + 2*128*LDK) * 2 * 3)
#define HS3_64  ((2*ASZ2 + 2*64*LDK)  * 2 * 3)

// ---------------- kk normalize / a_in / b_in / k update --------------------
__global__ void kk_kernel(const float* __restrict__ kkc,
                          const float* __restrict__ kac)
{
    int gid  = blockIdx.x * blockDim.x + threadIdx.x;
    int lane = gid & 31;
    int grp  = gid >> 5;
    if (grp >= BT_*H_) return;
    int bt = grp / H_, h = grp % H_;
    int base = bt * C_ + h * D_;
    int c0   = h * D_;

    float k0v = g_k[base + lane],      k1v = g_k[base + 32 + lane];
    float a0  = g_a[base + lane],      a1  = g_a[base + 32 + lane];
    float kk0 = k0v * kkc[c0 + lane],  kk1 = k1v * kkc[c0 + 32 + lane];

    float ss = kk0*kk0 + kk1*kk1;
#pragma unroll
    for (int o = 16; o; o >>= 1) ss += __shfl_xor_sync(0xffffffffu, ss, o);
    float inv = 1.f / fmaxf(sqrtf(ss), 1e-12f);
    kk0 *= inv; kk1 *= inv;

    g_ain[base + lane]      = -kk0;
    g_ain[base + 32 + lane] = -kk1;
    g_bin[base + lane]      = kk0 * a0;
    g_bin[base + 32 + lane] = kk1 * a1;
    g_k[base + lane]        = k0v * (1.f + (a0 - 1.f) * kac[c0 + lane]);
    g_k[base + 32 + lane]   = k1v * (1.f + (a1 - 1.f) * kac[c0 + 32 + lane]);
}

// ---------------- RWKV-7 recurrence (row-split, 128 blocks) -----------------
__global__ void __launch_bounds__(128, 1) rec_kernel()
{
    int blk = blockIdx.x;
    int bh  = blk >> 2;
    int rb  = blk & 3;
    int b = bh >> 4, h = bh & 15;
    size_t base = (size_t)b * T_ * C_ + h * D_;

    __shared__ alignas(16) float rsm[2][6][RCHUNK][64];

    int tid = threadIdx.x;
    int row = rb * RROWS + (tid >> 3);
    int cp  = tid & 7;
    int c0  = cp * 8;

    const float* srcs[6] = { g_r, g_decay, g_k, g_v, g_ain, g_bin };
    const float* gp[6];
    uint32_t sp_[6];
#pragma unroll
    for (int it = 0; it < 6; it++) {
        int f  = tid + it * 128;
        int q  = f & 15;
        int st = (f >> 4) & (RCHUNK-1);
        int vc = f >> 7;
        gp[it]  = srcs[vc] + base + (size_t)st * C_ + q * 4;
        sp_[it] = (uint32_t)((vc * RCHUNK + st) * 64 + q * 4);
    }

    unsigned long long S[4] = {0ull, 0ull, 0ull, 0ull};

    float4 pf[6];
#pragma unroll
    for (int it = 0; it < 6; it++) pf[it] = *(const float4*)gp[it];

    float* smbase = &rsm[0][0][0][0];
    const int NCH = T_ / RCHUNK;
    for (int ch = 0; ch < NCH; ch++) {
        float* buf = smbase + (ch & 1) * (6*RCHUNK*64);
#pragma unroll
        for (int it = 0; it < 6; it++)
            *(float4*)(buf + sp_[it]) = pf[it];
        __syncthreads();
        if (ch + 1 < NCH) {
            size_t adv = (size_t)(ch + 1) * RCHUNK * C_;
#pragma unroll
            for (int it = 0; it < 6; it++)
                pf[it] = *(const float4*)(gp[it] + adv);
        }

        size_t obase = base + (size_t)ch * RCHUNK * C_ + row;
#pragma unroll 2
        for (int s = 0; s < RCHUNK; s++) {
            const float* rv = buf + (0*RCHUNK + s) * 64;
            const float* wv = buf + (1*RCHUNK + s) * 64;
            const float* kv = buf + (2*RCHUNK + s) * 64;
            const float* vv = buf + (3*RCHUNK + s) * 64;
            const float* av = buf + (4*RCHUNK + s) * 64;
            const float* bv = buf + (5*RCHUNK + s) * 64;

            ulonglong2 aA = *(const ulonglong2*)(av + c0);
            ulonglong2 aB = *(const ulonglong2*)(av + c0 + 4);
            unsigned long long sacc = f32x2_fma(S[0], aA.x, 0ull);
            sacc = f32x2_fma(S[1], aA.y, sacc);
            sacc = f32x2_fma(S[2], aB.x, sacc);
            sacc = f32x2_fma(S[3], aB.y, sacc);
            float2 spp = f32x2_unpack(sacc);
            float sa = spp.x + spp.y;
            sa += __shfl_xor_sync(0xffffffffu, sa, 1);
            sa += __shfl_xor_sync(0xffffffffu, sa, 2);
            sa += __shfl_xor_sync(0xffffffffu, sa, 4);

            float vj = vv[row];
            ulonglong2 wA = *(const ulonglong2*)(wv + c0);
            ulonglong2 wB = *(const ulonglong2*)(wv + c0 + 4);
            ulonglong2 bA = *(const ulonglong2*)(bv + c0);
            ulonglong2 bB = *(const ulonglong2*)(bv + c0 + 4);
            ulonglong2 kA = *(const ulonglong2*)(kv + c0);
            ulonglong2 kB = *(const ulonglong2*)(kv + c0 + 4);
            ulonglong2 rA = *(const ulonglong2*)(rv + c0);
            ulonglong2 rB = *(const ulonglong2*)(rv + c0 + 4);

            unsigned long long sa2 = f32x2_pack(sa, sa);
            unsigned long long v2  = f32x2_pack(vj, vj);

            S[0] = f32x2_fma(v2, kA.x, f32x2_fma(sa2, bA.x, f32x2_fma(S[0], wA.x, 0ull)));
            S[1] = f32x2_fma(v2, kA.y, f32x2_fma(sa2, bA.y, f32x2_fma(S[1], wA.y, 0ull)));
            S[2] = f32x2_fma(v2, kB.x, f32x2_fma(sa2, bB.x, f32x2_fma(S[2], wB.x, 0ull)));
            S[3] = f32x2_fma(v2, kB.y, f32x2_fma(sa2, bB.y, f32x2_fma(S[3], wB.y, 0ull)));

            unsigned long long oacc = f32x2_fma(S[0], rA.x, 0ull);
            oacc = f32x2_fma(S[1], rA.y, oacc);
            oacc = f32x2_fma(S[2], rB.x, oacc);
            oacc = f32x2_fma(S[3], rB.y, oacc);
            float2 op = f32x2_unpack(oacc);
            float o = op.x + op.y;
            o += __shfl_xor_sync(0xffffffffu, o, 1);
            o += __shfl_xor_sync(0xffffffffu, o, 2);
            o += __shfl_xor_sync(0xffffffffu, o, 4);
            if (cp == 0) g_o[obase + (size_t)s * C_] = o;
        }
    }
}

// ---------------- GroupNorm + bonus + gate (emits bf16 hi/lo) --------------
__global__ void post_kernel(const float* __restrict__ rk,
                            const float* __restrict__ gnw,
                            const float* __restrict__ gnb)
{
    int gid  = blockIdx.x * blockDim.x + threadIdx.x;
    int lane = gid & 31;
    int grp  = gid >> 5;
    if (grp >= BT_*H_) return;
    int bt = grp / H_, h = grp % H_;
    int base = bt * C_ + h * D_;
    int c0   = h * D_;

    float o0 = g_o[base + lane], o1 = g_o[base + 32 + lane];
    float su = o0 + o1;
    float sq = o0*o0 + o1*o1;
    float r0 = g_r[base + lane], r1 = g_r[base + 32 + lane];
    float k0 = g_k[base + lane], k1 = g_k[base + 32 + lane];
    float bsum = r0*k0*rk[c0 + lane] + r1*k1*rk[c0 + 32 + lane];
#pragma unroll
    for (int o = 16; o; o >>= 1) {
        su   += __shfl_xor_sync(0xffffffffu, su,   o);
        sq   += __shfl_xor_sync(0xffffffffu, sq,   o);
        bsum += __shfl_xor_sync(0xffffffffu, bsum, o);
    }
    float mu  = su / 64.f;
    float var = sq / 64.f - mu * mu;
    float inv = rsqrtf(var + EPS_);

    float v0 = g_v[base + lane], v1 = g_v[base + 32 + lane];
    float on0 = (o0 - mu) * inv * gnw[c0 + lane]      + gnb[c0 + lane];
    float on1 = (o1 - mu) * inv * gnw[c0 + 32 + lane] + gnb[c0 + 32 + lane];
    float p0 = (on0 + bsum * v0) * g_g[base + lane];
    float p1 = (on1 + bsum * v1) * g_g[base + 32 + lane];

    __nv_bfloat16 h0 = __float2bfloat16_rn(p0);
    __nv_bfloat16 h1 = __float2bfloat16_rn(p1);
    g_preh[base + lane]      = h0;
    g_preh[base + 32 + lane] = h1;
    g_prel[base + lane]      = __float2bfloat16_rn(p0 - __bfloat162float(h0));
    g_prel[base + 32 + lane] = __float2bfloat16_rn(p1 - __bfloat162float(h1));
}

// ---------------- host launcher ---------------------------------------------
extern "C" void kernel_launch(void* const* d_in, const int* in_sizes, int n_in,
                              void* d_out, int out_size)
{
    const float* x        = (const float*)d_in[0];
    const float* x_r      = (const float*)d_in[1];
    const float* x_w      = (const float*)d_in[2];
    const float* x_k      = (const float*)d_in[3];
    const float* x_v      = (const float*)d_in[4];
    const float* x_a      = (const float*)d_in[5];
    const float* x_g      = (const float*)d_in[6];
    const float* k_k      = (const float*)d_in[7];
    const float* k_a      = (const float*)d_in[8];
    const float* r_k      = (const float*)d_in[9];
    const float* Wr       = (const float*)d_in[10];
    const float* Wk       = (const float*)d_in[11];
    const float* Wv       = (const float*)d_in[12];
    const float* Wo       = (const float*)d_in[13];
    const float* wA       = (const float*)d_in[14];
    const float* wB       = (const float*)d_in[15];
    const float* wBias    = (const float*)d_in[16];
    const float* aA       = (const float*)d_in[17];
    const float* aB       = (const float*)d_in[18];
    const float* aBias    = (const float*)d_in[19];
    const float* gA       = (const float*)d_in[20];
    const float* gB       = (const float*)d_in[21];
    const float* gnw      = (const float*)d_in[22];
    const float* gnb      = (const float*)d_in[23];
    const float* w0_base  = (const float*)d_in[24];
    const float* w0_delta = (const float*)d_in[25];
    float* out = (float*)d_out;

#define SYM(p, s) cudaGetSymbolAddress((void**)&p, s)
    float *p_r,*p_k,*p_v,*p_dec,*p_a,*p_g;
    __nv_bfloat16 *p_xrh,*p_xrl,*p_xkh,*p_xkl,*p_xvh,*p_xvl;
    __nv_bfloat16 *p_xwh,*p_xwl,*p_xah,*p_xal,*p_xgh,*p_xgl;
    __nv_bfloat16 *p_preh,*p_prel,*p_wh,*p_wl;
    __nv_bfloat16 *p_wAh,*p_wAl,*p_aAh,*p_aAl,*p_gAh,*p_gAl;
    __nv_bfloat16 *p_wBh,*p_wBl,*p_aBh,*p_aBl,*p_gBh,*p_gBl;
    __nv_bfloat16 *p_w1h,*p_w1l,*p_a1h,*p_a1l,*p_g1h,*p_g1l;
    SYM(p_r, g_r); SYM(p_k, g_k); SYM(p_v, g_v);
    SYM(p_dec, g_decay); SYM(p_a, g_a); SYM(p_g, g_g);
    SYM(p_xrh, g_xrh); SYM(p_xrl, g_xrl);
    SYM(p_xkh, g_xkh); SYM(p_xkl, g_xkl);
    SYM(p_xvh, g_xvh); SYM(p_xvl, g_xvl);
    SYM(p_xwh, g_xwh); SYM(p_xwl, g_xwl);
    SYM(p_xah, g_xah); SYM(p_xal, g_xal);
    SYM(p_xgh, g_xgh); SYM(p_xgl, g_xgl);
    SYM(p_preh, g_preh); SYM(p_prel, g_prel);
    SYM(p_wh, g_wh); SYM(p_wl, g_wl);
    SYM(p_wAh, g_wAh); SYM(p_wAl, g_wAl);
    SYM(p_aAh, g_aAh); SYM(p_aAl, g_aAl);
    SYM(p_gAh, g_gAh); SYM(p_gAl, g_gAl);
    SYM(p_wBh, g_wBh); SYM(p_wBl, g_wBl);
    SYM(p_aBh, g_aBh); SYM(p_aBl, g_aBl);
    SYM(p_gBh, g_gBh); SYM(p_gBl, g_gBl);
    SYM(p_w1h, g_w1h); SYM(p_w1l, g_w1l);
    SYM(p_a1h, g_a1h); SYM(p_a1l, g_a1l);
    SYM(p_g1h, g_g1h); SYM(p_g1l, g_g1l);
#undef SYM

    cudaFuncSetAttribute(hg3_kernel<128>,
        cudaFuncAttributeMaxDynamicSharedMemorySize, HS3_128);
    cudaFuncSetAttribute(hg3_kernel<64>,
        cudaFuncAttributeMaxDynamicSharedMemorySize, HS3_64);

    // 0) all weights fp32 -> bf16 hi/lo
    {
        WcJobs wj;
        wj.j[0] = { Wr, p_wh + 0*C_*C_, p_wl + 0*C_*C_, C_*C_ };
        wj.j[1] = { Wk, p_wh + 1*C_*C_, p_wl + 1*C_*C_, C_*C_ };
        wj.j[2] = { Wv, p_wh + 2*C_*C_, p_wl + 2*C_*C_, C_*C_ };
        wj.j[3] = { Wo, p_wh + 3*C_*C_, p_wl + 3*C_*C_, C_*C_ };
        wj.j[4] = { wA, p_wAh, p_wAl, RW_*C_ };
        wj.j[5] = { aA, p_aAh, p_aAl, RA_*C_ };
        wj.j[6] = { gA, p_gAh, p_gAl, RG_*C_ };
        wj.j[7] = { wB, p_wBh, p_wBl, C_*RW_ };
        wj.j[8] = { aB, p_aBh, p_aBl, C_*RA_ };
        wj.j[9] = { gB, p_gBh, p_gBl, C_*RG_ };
        wconv_kernel<<<dim3(C_*C_/4/256, 10), 256>>>(wj);
    }

    // 1) token-shift mixes -> bf16 hi/lo (all six)
    mix_kernel<<<(BT_*C_/4 + 255)/256, 256>>>(x, x_r, x_w, x_k, x_v, x_a, x_g);

    // 2) w0 scan
    w0_kernel<<<1, C_>>>(w0_base, w0_delta);

    // 3) r/k/v projections (HMMA 256x128, 3-stage cp.async)
    {
        HJobs hj;
        hj.j[0] = { p_xrh, p_xrl, p_wh + 0*C_*C_, p_wl + 0*C_*C_,
                    p_r, nullptr, nullptr, nullptr, C_, C_, 0 };
        hj.j[1] = { p_xkh, p_xkl, p_wh + 1*C_*C_, p_wl + 1*C_*C_,
                    p_k, nullptr, nullptr, nullptr, C_, C_, 0 };
        hj.j[2] = { p_xvh, p_xvl, p_wh + 2*C_*C_, p_wl + 2*C_*C_,
                    p_v, nullptr, nullptr, nullptr, C_, C_, 0 };
        hg3_kernel<128><<<dim3(C_/128, BT_/AROWS, 3), 512, HS3_128>>>(hj);
    }

    // 4) LoRA stage 1 (NT=64, epilogue emits bf16 hi/lo)
    {
        HJobs hj;
        hj.j[0] = { p_xwh, p_xwl, p_wAh, p_wAl,
                    nullptr, p_w1h, p_w1l, nullptr, RW_, C_, 1 };   // tanh
        hj.j[1] = { p_xah, p_xal, p_aAh, p_aAl,
                    nullptr, p_a1h, p_a1l, nullptr, RA_, C_, 6 };   // none
        hj.j[2] = { p_xgh, p_xgl, p_gAh, p_gAl,
                    nullptr, p_g1h, p_g1l, nullptr, RG_, C_, 2 };   // sigmoid
        hg3_kernel<64><<<dim3((RG_+63)/64, BT_/AROWS, 3), 512, HS3_64>>>(hj);
    }

    // 5) LoRA stage 2 (NT=128, fused epilogues)
    {
        HJobs hj;
        hj.j[0] = { p_w1h, p_w1l, p_wBh, p_wBl,
                    p_dec, nullptr, nullptr, wBias, C_, RW_, 3 };   // decay
        hj.j[1] = { p_a1h, p_a1l, p_aBh, p_aBl,
                    p_a, nullptr, nullptr, aBias, C_, RA_, 5 };     // sigm+bias
        hj.j[2] = { p_g1h, p_g1l, p_gBh, p_gBl,
                    p_g, nullptr, nullptr, nullptr, C_, RG_, 0 };
        hg3_kernel<128><<<dim3(C_/128, BT_/AROWS, 3), 512, HS3_128>>>(hj);
    }

    // 6) kk normalize / a_in / b_in / k update
    kk_kernel<<<(BT_*H_*32 + 255)/256, 256>>>(k_k, k_a);

    // 7) sequential recurrence (row-split)
    rec_kernel<<<128, 128>>>();

    // 8) GroupNorm + bonus + gate (-> bf16 hi/lo)
    post_kernel<<<(BT_*H_*32 + 255)/256, 256>>>(r_k, gnw, gnb);

    // 9) output projection (HMMA)
    {
        HJobs hj;
        hj.j[0] = { p_preh, p_prel, p_wh + 3*C_*C_, p_wl + 3*C_*C_,
                    out, nullptr, nullptr, nullptr, C_, C_, 0 };
        hj.j[1] = hj.j[0];
        hj.j[2] = hj.j[0];
        hg3_kernel<128><<<dim3(C_/128, BT_/AROWS, 1), 512, HS3_128>>>(hj);
    }
}